// round 1
// baseline (speedup 1.0000x reference)
#include <cuda_runtime.h>
#include <cuda_bf16.h>
#include <math.h>
#include <stdint.h>

#define NR    8000
#define NPOS  4000
#define NF    128
#define NVOX  32768
#define NMSE  (128*32*32*32)

// ---- scratch (static device globals; no allocations) ----
__device__ float          g_P[NR*NF];     // normalized pixels fp32
__device__ __nv_bfloat16  g_Pb[NR*NF];    // normalized pixels bf16 (B operand)
__device__ __nv_bfloat16  g_Ab[NR*NF];    // row-scaled pixels bf16 (A operand)
__device__ float          g_M[NF*NF];     // P^T P
__device__ float          g_S[2*NF];      // class block column sums (0=pos,1=neg)
__device__ float          g_denom[NR];
__device__ float          g_acc[4];       // [0]=S_mask, [2]=mse sum

// ---------------- K0: zero accumulators ----------------
__global__ void k_init() {
    int i = blockIdx.x*256 + threadIdx.x, st = gridDim.x*256;
    for (int j = i; j < NF*NF; j += st) g_M[j] = 0.f;
    for (int j = i; j < NR;    j += st) g_denom[j] = 0.f;
    for (int j = i; j < 2*NF;  j += st) g_S[j] = 0.f;
    if (i < 4) g_acc[i] = 0.f;
}

// ---------------- K1: gather + L2-normalize rows ----------------
// one block (128 thr) per row
__global__ void k_gather(const float* __restrict__ Zs,
                         const int* __restrict__ pos,
                         const int* __restrict__ neg) {
    int r = blockIdx.x;
    int f = threadIdx.x;
    int v = (r < NPOS) ? pos[r] : neg[r - NPOS];
    float x = Zs[f*NVOX + v];
    float s = x*x;
    #pragma unroll
    for (int m = 16; m; m >>= 1) s += __shfl_xor_sync(0xffffffffu, s, m);
    __shared__ float ws[4];
    if ((f & 31) == 0) ws[f >> 5] = s;
    __syncthreads();
    float tot = ws[0] + ws[1] + ws[2] + ws[3];
    float inv = 1.0f / fmaxf(sqrtf(tot), 1e-12f);
    float p = x * inv;
    g_P [r*NF + f] = p;
    g_Pb[r*NF + f] = __float2bfloat16(p);
}

// ---------------- K2: class-block column sums ----------------
// grid 16 (8 pos chunks, 8 neg chunks), block 128
__global__ void k_colsum() {
    int b = blockIdx.x, f = threadIdx.x;
    int r0 = b * 500;
    float s = 0.f;
    for (int r = r0; r < r0 + 500; r++) s += g_P[r*NF + f];
    int lab = (r0 < NPOS) ? 0 : 1;
    atomicAdd(&g_S[lab*NF + f], s);
}

// ---------------- K3: M = P^T P ----------------
// grid 125 (64 rows each), block 256; each thread owns an 8x8 sub-block of M
__global__ void k_M() {
    __shared__ float sp[64][NF];
    int t = threadIdx.x;
    int r0 = blockIdx.x * 64;
    const float4* src = (const float4*)&g_P[r0*NF];
    float4* dst = (float4*)&sp[0][0];
    for (int i = t; i < 64*NF/4; i += 256) dst[i] = src[i];
    __syncthreads();
    int k0 = (t >> 4) * 8, l0 = (t & 15) * 8;
    float acc[8][8];
    #pragma unroll
    for (int i = 0; i < 8; i++)
        #pragma unroll
        for (int j = 0; j < 8; j++) acc[i][j] = 0.f;
    for (int r = 0; r < 64; r++) {
        float a[8], b[8];
        #pragma unroll
        for (int i = 0; i < 8; i++) { a[i] = sp[r][k0+i]; b[i] = sp[r][l0+i]; }
        #pragma unroll
        for (int i = 0; i < 8; i++)
            #pragma unroll
            for (int j = 0; j < 8; j++) acc[i][j] = fmaf(a[i], b[j], acc[i][j]);
    }
    #pragma unroll
    for (int i = 0; i < 8; i++)
        #pragma unroll
        for (int j = 0; j < 8; j++)
            atomicAdd(&g_M[(k0+i)*NF + (l0+j)], acc[i][j]);
}

// ---------------- K4: per-row qf, S_mask contribution, scaled A ----------------
// grid 1000 (8 rows each), block 128
__global__ void k_prep() {
    __shared__ float sp[8][NF];
    __shared__ float smQ[8][4], smS[8][4], smR[8], smC[8];
    int f = threadIdx.x;
    int r0 = blockIdx.x * 8;
    for (int r = 0; r < 8; r++) sp[r][f] = g_P[(r0+r)*NF + f];
    __syncthreads();
    float inner[8] = {0,0,0,0,0,0,0,0};
    for (int l = 0; l < NF; l++) {
        float m = g_M[f*NF + l];
        #pragma unroll
        for (int r = 0; r < 8; r++) inner[r] = fmaf(m, sp[r][l], inner[r]);
    }
    int sb = (r0 < NPOS) ? 0 : NF;
    float sf = g_S[sb + f];
    int lane = f & 31, w = f >> 5;
    #pragma unroll
    for (int r = 0; r < 8; r++) {
        float q = inner[r] * sp[r][f];
        float s = sf * sp[r][f];
        #pragma unroll
        for (int m = 16; m; m >>= 1) {
            q += __shfl_xor_sync(0xffffffffu, q, m);
            s += __shfl_xor_sync(0xffffffffu, s, m);
        }
        if (lane == 0) { smQ[r][w] = q; smS[r][w] = s; }
    }
    __syncthreads();
    if (f < 8) {
        int r = f;
        float qf = smQ[r][0] + smQ[r][1] + smQ[r][2] + smQ[r][3];
        float ps = smS[r][0] + smS[r][1] + smS[r][2] + smS[r][3];
        float rinv = rsqrtf(qf);
        rinv = rinv * (1.5f - 0.5f * qf * rinv * rinv);   // Newton refine
        smR[r] = rinv;
        smC[r] = (ps - 1.0f) * rinv;                      // sum of same-class dots for row
    }
    __syncthreads();
    if (f == 0) {
        float c = 0.f;
        #pragma unroll
        for (int r = 0; r < 8; r++) c += smC[r];
        atomicAdd(&g_acc[0], c);
    }
    for (int r = 0; r < 8; r++)
        g_Ab[(r0+r)*NF + f] = __float2bfloat16(sp[r][f] * smR[r]);
}

// ---------------- K5: fused bf16 GEMM + poly-exp + row reduce ----------------
__device__ __forceinline__ float expp(float x) {
    // degree-7 Taylor, valid for |x|<=1 (guaranteed by Cauchy-Schwarz; typical |x|<0.13)
    float r = 1.f/5040.f;
    r = fmaf(r, x, 1.f/720.f);
    r = fmaf(r, x, 1.f/120.f);
    r = fmaf(r, x, 1.f/24.f);
    r = fmaf(r, x, 1.f/6.f);
    r = fmaf(r, x, 0.5f);
    r = fmaf(r, x, 1.f);
    r = fmaf(r, x, 1.f);
    return r;
}

__device__ __forceinline__ void mma16816(float c[4], const unsigned a[4],
                                         unsigned b0, unsigned b1) {
    asm volatile(
        "mma.sync.aligned.m16n8k16.row.col.f32.bf16.bf16.f32 "
        "{%0,%1,%2,%3}, {%4,%5,%6,%7}, {%8,%9}, {%0,%1,%2,%3};"
        : "+f"(c[0]), "+f"(c[1]), "+f"(c[2]), "+f"(c[3])
        : "r"(a[0]), "r"(a[1]), "r"(a[2]), "r"(a[3]), "r"(b0), "r"(b1));
}

#define BSTR 136  // padded smem stride in bf16 (272B -> conflict-free frag loads)

// grid 500: 250 row-tiles (32 rows) x 2 column halves (2000 cols each)
__global__ void __launch_bounds__(256) k_denom() {
    __shared__ __nv_bfloat16 At[32*BSTR];
    __shared__ __nv_bfloat16 Bt[128*BSTR];
    int bid = blockIdx.x;
    int rowTile = bid >> 1, jh = bid & 1;
    int r0 = rowTile * 32;
    int j0 = ((r0 < NPOS) ? NPOS : 0) + jh * 2000;
    int jlim = j0 + 2000;
    int t = threadIdx.x;
    int wid = t >> 5, lane = t & 31;
    int g = lane >> 2, tt = lane & 3;
    int warp_m = wid & 1, warp_n = wid >> 1;

    // A tile: 32 rows x 128 bf16 = 512 uint4
    {
        const uint4* src = (const uint4*)&g_Ab[r0*NF];
        for (int i = t; i < 512; i += 256) {
            int row = i >> 4, seg = i & 15;
            *(uint4*)&At[row*BSTR + seg*8] = src[i];
        }
    }
    __syncthreads();

    // A fragments in registers: reused across all 16 B tiles
    unsigned af[8][4];
    int ar = warp_m * 16 + g;
    #pragma unroll
    for (int kk = 0; kk < 8; kk++) {
        af[kk][0] = *(const unsigned*)&At[ ar    *BSTR + kk*16     + 2*tt];
        af[kk][1] = *(const unsigned*)&At[(ar+8)*BSTR + kk*16     + 2*tt];
        af[kk][2] = *(const unsigned*)&At[ ar    *BSTR + kk*16 + 8 + 2*tt];
        af[kk][3] = *(const unsigned*)&At[(ar+8)*BSTR + kk*16 + 8 + 2*tt];
    }

    float sumA = 0.f, sumB = 0.f;
    for (int tile = 0; tile < 16; tile++) {
        int jt = j0 + tile * 128;
        __syncthreads();
        // B tile: 128 rows x 128 bf16; zero-fill past jlim (exp(0)=1, corrected below)
        for (int i = t; i < 2048; i += 256) {
            int row = i >> 4, seg = i & 15;
            int jj = jt + row;
            uint4 v = make_uint4(0u, 0u, 0u, 0u);
            if (jj < jlim) v = ((const uint4*)&g_Pb[(size_t)jj*NF])[seg];
            *(uint4*)&Bt[row*BSTR + seg*8] = v;
        }
        __syncthreads();

        float c[4][4];
        #pragma unroll
        for (int nn = 0; nn < 4; nn++)
            #pragma unroll
            for (int q = 0; q < 4; q++) c[nn][q] = 0.f;

        #pragma unroll
        for (int kk = 0; kk < 8; kk++) {
            #pragma unroll
            for (int nn = 0; nn < 4; nn++) {
                int jc = warp_n*32 + nn*8 + g;
                unsigned b0 = *(const unsigned*)&Bt[jc*BSTR + kk*16     + 2*tt];
                unsigned b1 = *(const unsigned*)&Bt[jc*BSTR + kk*16 + 8 + 2*tt];
                mma16816(c[nn], af[kk], b0, b1);
            }
        }
        #pragma unroll
        for (int nn = 0; nn < 4; nn++) {
            sumA += expp(c[nn][0]) + expp(c[nn][1]);   // row g
            sumB += expp(c[nn][2]) + expp(c[nn][3]);   // row g+8
        }
    }
    // reduce over the 4 tt-lanes of each row group
    #pragma unroll
    for (int m = 1; m <= 2; m <<= 1) {
        sumA += __shfl_xor_sync(0xffffffffu, sumA, m);
        sumB += __shfl_xor_sync(0xffffffffu, sumB, m);
    }
    if (tt == 0) {
        // last tile zero-filled cols: 2048-2000=48 -> per warp {0,0,16,32}
        float corr = (warp_n == 2) ? 16.f : ((warp_n == 3) ? 32.f : 0.f);
        int rowA = r0 + warp_m*16 + g;
        atomicAdd(&g_denom[rowA],     sumA - corr);
        atomicAdd(&g_denom[rowA + 8], sumB - corr);
    }
}

// ---------------- K6: MSE partial ----------------
__global__ void k_mse(const float* __restrict__ fd, const float* __restrict__ id) {
    int n4 = NMSE / 4;
    float s = 0.f;
    for (int i = blockIdx.x*blockDim.x + threadIdx.x; i < n4; i += gridDim.x*blockDim.x) {
        float4 a = ((const float4*)fd)[i];
        float4 b = ((const float4*)id)[i];
        float d0 = a.x-b.x, d1 = a.y-b.y, d2 = a.z-b.z, d3 = a.w-b.w;
        s += d0*d0 + d1*d1 + d2*d2 + d3*d3;
    }
    #pragma unroll
    for (int m = 16; m; m >>= 1) s += __shfl_xor_sync(0xffffffffu, s, m);
    __shared__ float ws[8];
    if ((threadIdx.x & 31) == 0) ws[threadIdx.x >> 5] = s;
    __syncthreads();
    if (threadIdx.x == 0) {
        float tot = 0.f;
        for (int w = 0; w < (int)(blockDim.x >> 5); w++) tot += ws[w];
        atomicAdd(&g_acc[2], tot);
    }
}

// ---------------- K7: final combine ----------------
__global__ void k_final(float* out) {
    float s = 0.f;
    for (int i = threadIdx.x; i < NR; i += 256) s += logf(g_denom[i]);
    #pragma unroll
    for (int m = 16; m; m >>= 1) s += __shfl_xor_sync(0xffffffffu, s, m);
    __shared__ float ws[8];
    if ((threadIdx.x & 31) == 0) ws[threadIdx.x >> 5] = s;
    __syncthreads();
    if (threadIdx.x == 0) {
        float lsum = 0.f;
        for (int w = 0; w < 8; w++) lsum += ws[w];
        float supcon = -g_acc[0] * (1.0f / NR) + lsum;
        float mse = g_acc[2] * (1.0f / NMSE);
        out[0] = supcon + 0.5f * mse;
    }
}

extern "C" void kernel_launch(void* const* d_in, const int* in_sizes, int n_in,
                              void* d_out, int out_size) {
    const float* Zs  = (const float*)d_in[0];
    const int*   pos = (const int*)d_in[1];
    const int*   neg = (const int*)d_in[2];
    const float* fd  = (const float*)d_in[3];
    const float* id  = (const float*)d_in[4];
    float* out = (float*)d_out;

    k_init  <<<64, 256>>>();
    k_gather<<<NR, 128>>>(Zs, pos, neg);
    k_colsum<<<16, 128>>>();
    k_M     <<<125, 256>>>();
    k_prep  <<<1000, 128>>>();
    k_denom <<<500, 256>>>();
    k_mse   <<<1024, 256>>>(fd, id);
    k_final <<<1, 256>>>(out);
}

// round 3
// speedup vs baseline: 1.8991x; 1.8991x over previous
#include <cuda_runtime.h>
#include <cuda_bf16.h>
#include <math.h>
#include <stdint.h>

#define NR    8000
#define NPOS  4000
#define NF    128
#define NVOX  32768
#define NMSE  (128*32*32*32)
#define NMP   250          // k_M split-K partial count

// ---- scratch (static device globals; no allocations) ----
__device__ float          g_P[NR*NF];        // normalized pixels fp32
__device__ __nv_bfloat16  g_Pb[NR*NF];       // normalized pixels bf16 (B operand)
__device__ __nv_bfloat16  g_Ab[NR*NF];       // row-scaled pixels bf16 (A operand)
__device__ float          g_Mp[NMP*NF*NF];   // split-K partials of P^T P (16 MB)
__device__ float          g_M[NF*NF];        // P^T P
__device__ float          g_S[2*NF];         // class block column sums
__device__ float          g_denom[NR];
__device__ float          g_acc[4];          // [0]=S_mask, [2]=mse sum

__device__ __forceinline__ unsigned smem_u32(const void* p) {
    return (unsigned)__cvta_generic_to_shared(p);
}
#define CP_ASYNC_COMMIT() asm volatile("cp.async.commit_group;\n" ::)
#define CP_ASYNC_WAIT(n)  asm volatile("cp.async.wait_group %0;\n" :: "n"(n))

// ---------------- K0: zero accumulators ----------------
__global__ void k_init() {
    int i = blockIdx.x*256 + threadIdx.x, st = gridDim.x*256;
    for (int j = i; j < NR;   j += st) g_denom[j] = 0.f;
    for (int j = i; j < 2*NF; j += st) g_S[j] = 0.f;
    if (i < 4) g_acc[i] = 0.f;
}

// ---------------- K1: gather + L2-normalize rows (warp per row) ----------------
__global__ void k_gather(const float* __restrict__ Zs,
                         const int* __restrict__ pos,
                         const int* __restrict__ neg) {
    int t = threadIdx.x, wid = t >> 5, lane = t & 31;
    int r = blockIdx.x * 8 + wid;
    int v = (r < NPOS) ? pos[r] : neg[r - NPOS];
    float x[4];
    #pragma unroll
    for (int k = 0; k < 4; k++) x[k] = Zs[(size_t)(lane + 32*k)*NVOX + v];
    float s = x[0]*x[0] + x[1]*x[1] + x[2]*x[2] + x[3]*x[3];
    #pragma unroll
    for (int m = 16; m; m >>= 1) s += __shfl_xor_sync(0xffffffffu, s, m);
    float inv = 1.0f / fmaxf(sqrtf(s), 1e-12f);
    #pragma unroll
    for (int k = 0; k < 4; k++) {
        float p = x[k] * inv;
        g_P [r*NF + lane + 32*k] = p;
        g_Pb[r*NF + lane + 32*k] = __float2bfloat16(p);
    }
}

// ---------------- K2a: split-K partials of M = P^T P  (+ class column sums) ----
// grid 250 (32 rows each), block 256; thread owns 8x8 sub-block
__global__ void __launch_bounds__(256) k_MA() {
    __shared__ float sp[32][NF];
    int t = threadIdx.x;
    int r0 = blockIdx.x * 32;
    {
        const float4* src = (const float4*)&g_P[r0*NF];
        float4* dst = (float4*)&sp[0][0];
        for (int i = t; i < 32*NF/4; i += 256) dst[i] = src[i];
    }
    __syncthreads();
    // column sums for this (class-aligned) row chunk
    if (t < NF) {
        float s = 0.f;
        #pragma unroll 8
        for (int r = 0; r < 32; r++) s += sp[r][t];
        atomicAdd(&g_S[((r0 < NPOS) ? 0 : NF) + t], s);
    }
    int k0 = (t >> 4) * 8, l0 = (t & 15) * 8;
    float acc[8][8];
    #pragma unroll
    for (int i = 0; i < 8; i++)
        #pragma unroll
        for (int j = 0; j < 8; j++) acc[i][j] = 0.f;
    for (int r = 0; r < 32; r++) {
        float4 a0 = *(const float4*)&sp[r][k0];
        float4 a1 = *(const float4*)&sp[r][k0+4];
        float4 b0 = *(const float4*)&sp[r][l0];
        float4 b1 = *(const float4*)&sp[r][l0+4];
        float a[8] = {a0.x,a0.y,a0.z,a0.w,a1.x,a1.y,a1.z,a1.w};
        float b[8] = {b0.x,b0.y,b0.z,b0.w,b1.x,b1.y,b1.z,b1.w};
        #pragma unroll
        for (int i = 0; i < 8; i++)
            #pragma unroll
            for (int j = 0; j < 8; j++) acc[i][j] = fmaf(a[i], b[j], acc[i][j]);
    }
    float* dst = &g_Mp[(size_t)blockIdx.x * NF * NF];
    #pragma unroll
    for (int i = 0; i < 8; i++) {
        *(float4*)&dst[(k0+i)*NF + l0    ] = make_float4(acc[i][0],acc[i][1],acc[i][2],acc[i][3]);
        *(float4*)&dst[(k0+i)*NF + l0 + 4] = make_float4(acc[i][4],acc[i][5],acc[i][6],acc[i][7]);
    }
}

// ---------------- K2b: reduce partials -> g_M ----------------
__global__ void k_Mred() {
    int e = blockIdx.x * 256 + threadIdx.x;   // 64 blocks x 256 = 16384
    float s = 0.f;
    #pragma unroll 5
    for (int p = 0; p < NMP; p++) s += g_Mp[(size_t)p*NF*NF + e];
    g_M[e] = s;
}

// ---------------- K4: per-row qf, S_mask contribution, scaled A ----------------
__global__ void k_prep() {
    __shared__ float sp[8][NF];
    __shared__ float smQ[8][4], smS[8][4], smR[8], smC[8];
    int f = threadIdx.x;
    int r0 = blockIdx.x * 8;
    for (int r = 0; r < 8; r++) sp[r][f] = g_P[(r0+r)*NF + f];
    __syncthreads();
    float inner[8] = {0,0,0,0,0,0,0,0};
    for (int l = 0; l < NF; l++) {
        float m = g_M[f*NF + l];
        #pragma unroll
        for (int r = 0; r < 8; r++) inner[r] = fmaf(m, sp[r][l], inner[r]);
    }
    int sb = (r0 < NPOS) ? 0 : NF;
    float sf = g_S[sb + f];
    int lane = f & 31, w = f >> 5;
    #pragma unroll
    for (int r = 0; r < 8; r++) {
        float q = inner[r] * sp[r][f];
        float s = sf * sp[r][f];
        #pragma unroll
        for (int m = 16; m; m >>= 1) {
            q += __shfl_xor_sync(0xffffffffu, q, m);
            s += __shfl_xor_sync(0xffffffffu, s, m);
        }
        if (lane == 0) { smQ[r][w] = q; smS[r][w] = s; }
    }
    __syncthreads();
    if (f < 8) {
        int r = f;
        float qf = smQ[r][0] + smQ[r][1] + smQ[r][2] + smQ[r][3];
        float ps = smS[r][0] + smS[r][1] + smS[r][2] + smS[r][3];
        float rinv = rsqrtf(qf);
        rinv = rinv * (1.5f - 0.5f * qf * rinv * rinv);
        smR[r] = rinv;
        smC[r] = (ps - 1.0f) * rinv;
    }
    __syncthreads();
    if (f == 0) {
        float c = 0.f;
        #pragma unroll
        for (int r = 0; r < 8; r++) c += smC[r];
        atomicAdd(&g_acc[0], c);
    }
    for (int r = 0; r < 8; r++)
        g_Ab[(r0+r)*NF + f] = __float2bfloat16(sp[r][f] * smR[r]);
}

// ---------------- K5: fused bf16 GEMM + poly-exp + row reduce ----------------
__device__ __forceinline__ float expp(float x) {
    float r = 1.f/5040.f;
    r = fmaf(r, x, 1.f/720.f);
    r = fmaf(r, x, 1.f/120.f);
    r = fmaf(r, x, 1.f/24.f);
    r = fmaf(r, x, 1.f/6.f);
    r = fmaf(r, x, 0.5f);
    r = fmaf(r, x, 1.f);
    r = fmaf(r, x, 1.f);
    return r;
}

__device__ __forceinline__ void mma16816(float c[4], const unsigned a[4],
                                         unsigned b0, unsigned b1) {
    asm volatile(
        "mma.sync.aligned.m16n8k16.row.col.f32.bf16.bf16.f32 "
        "{%0,%1,%2,%3}, {%4,%5,%6,%7}, {%8,%9}, {%0,%1,%2,%3};"
        : "+f"(c[0]), "+f"(c[1]), "+f"(c[2]), "+f"(c[3])
        : "r"(a[0]), "r"(a[1]), "r"(a[2]), "r"(a[3]), "r"(b0), "r"(b1));
}

#define BSTR 136           // padded smem stride in bf16 (272B; frag LDS conflict-free)
#define NTILES 16          // 16 x 128 = 2048 >= 2000 cols

// grid 252: 126 row tiles (64 rows, class-aligned w/ zero-pad) x 2 column halves
__global__ void __launch_bounds__(256) k_denom() {
    extern __shared__ __nv_bfloat16 sm[];
    __nv_bfloat16* At = sm;                  // 64 x BSTR
    __nv_bfloat16* Bt = sm + 64*BSTR;        // 2 x 128 x BSTR (double buffer)

    int bid = blockIdx.x;
    int tileR = bid >> 1, jh = bid & 1;
    int r0, class_end, j0;
    if (tileR < 63) { r0 = tileR * 64;              class_end = NPOS; j0 = NPOS; }
    else            { r0 = NPOS + (tileR - 63)*64;  class_end = NR;   j0 = 0;    }
    j0 += jh * 2000;
    int jlim = j0 + 2000;

    int t = threadIdx.x;
    int wid = t >> 5, lane = t & 31;
    int g = lane >> 2, tt = lane & 3;
    int warp_m = wid & 3, warp_n = wid >> 2;

    // prefetch B tile 0 (cp.async; src-size=0 past jlim -> zero-fill)
    {
        int jt = j0;
        for (int i = t; i < 2048; i += 256) {
            int row = i >> 4, seg = i & 15;
            int jj = jt + row;
            unsigned dst = smem_u32(&Bt[row*BSTR + seg*8]);
            const __nv_bfloat16* src = &g_Pb[(size_t)min(jj, jlim-1)*NF + seg*8];
            int sz = (jj < jlim) ? 16 : 0;
            asm volatile("cp.async.cg.shared.global [%0], [%1], 16, %2;\n"
                         :: "r"(dst), "l"(src), "r"(sz));
        }
        CP_ASYNC_COMMIT();
    }

    // A tile: 64 rows x 128 bf16, zero rows beyond class_end
    for (int i = t; i < 1024; i += 256) {
        int row = i >> 4, seg = i & 15;
        int jj = r0 + row;
        uint4 v = make_uint4(0u,0u,0u,0u);
        if (jj < class_end) v = ((const uint4*)&g_Ab[(size_t)jj*NF])[seg];
        *(uint4*)&At[row*BSTR + seg*8] = v;
    }
    __syncthreads();

    // A fragments (reused across all B tiles)
    unsigned af[8][4];
    int ar = warp_m * 16 + g;
    #pragma unroll
    for (int kk = 0; kk < 8; kk++) {
        af[kk][0] = *(const unsigned*)&At[ ar    *BSTR + kk*16     + 2*tt];
        af[kk][1] = *(const unsigned*)&At[(ar+8)*BSTR + kk*16     + 2*tt];
        af[kk][2] = *(const unsigned*)&At[ ar    *BSTR + kk*16 + 8 + 2*tt];
        af[kk][3] = *(const unsigned*)&At[(ar+8)*BSTR + kk*16 + 8 + 2*tt];
    }

    float sumA = 0.f, sumB = 0.f;
    for (int tile = 0; tile < NTILES; tile++) {
        if (tile + 1 < NTILES) {
            int jt = j0 + (tile + 1) * 128;
            __nv_bfloat16* dbuf = &Bt[((tile + 1) & 1) * 128 * BSTR];
            for (int i = t; i < 2048; i += 256) {
                int row = i >> 4, seg = i & 15;
                int jj = jt + row;
                unsigned dst = smem_u32(&dbuf[row*BSTR + seg*8]);
                const __nv_bfloat16* src = &g_Pb[(size_t)min(jj, jlim-1)*NF + seg*8];
                int sz = (jj < jlim) ? 16 : 0;
                asm volatile("cp.async.cg.shared.global [%0], [%1], 16, %2;\n"
                             :: "r"(dst), "l"(src), "r"(sz));
            }
            CP_ASYNC_COMMIT();
            CP_ASYNC_WAIT(1);
        } else {
            CP_ASYNC_WAIT(0);
        }
        __syncthreads();

        const __nv_bfloat16* B = &Bt[(tile & 1) * 128 * BSTR];
        float c[8][4];
        #pragma unroll
        for (int nn = 0; nn < 8; nn++)
            #pragma unroll
            for (int q = 0; q < 4; q++) c[nn][q] = 0.f;

        #pragma unroll
        for (int kk = 0; kk < 8; kk++) {
            #pragma unroll
            for (int nn = 0; nn < 8; nn++) {
                int jc = warp_n*64 + nn*8 + g;
                unsigned b0 = *(const unsigned*)&B[jc*BSTR + kk*16     + 2*tt];
                unsigned b1 = *(const unsigned*)&B[jc*BSTR + kk*16 + 8 + 2*tt];
                mma16816(c[nn], af[kk], b0, b1);
            }
        }
        #pragma unroll
        for (int nn = 0; nn < 8; nn++) {
            sumA += expp(c[nn][0]) + expp(c[nn][1]);   // row ar
            sumB += expp(c[nn][2]) + expp(c[nn][3]);   // row ar+8
        }
        __syncthreads();
    }

    #pragma unroll
    for (int m = 1; m <= 2; m <<= 1) {
        sumA += __shfl_xor_sync(0xffffffffu, sumA, m);
        sumB += __shfl_xor_sync(0xffffffffu, sumB, m);
    }
    if (tt == 0) {
        // 2048-2000=48 zero cols, all in warp_n==1's 64..127 range of last tile
        float corr = (warp_n == 1) ? 48.f : 0.f;
        int rowA = r0 + warp_m*16 + g;
        if (rowA     < class_end) atomicAdd(&g_denom[rowA],     sumA - corr);
        if (rowA + 8 < class_end) atomicAdd(&g_denom[rowA + 8], sumB - corr);
    }
}

// ---------------- K6: MSE partial ----------------
__global__ void k_mse(const float* __restrict__ fd, const float* __restrict__ id) {
    int n4 = NMSE / 4;
    float s = 0.f;
    for (int i = blockIdx.x*blockDim.x + threadIdx.x; i < n4; i += gridDim.x*blockDim.x) {
        float4 a = ((const float4*)fd)[i];
        float4 b = ((const float4*)id)[i];
        float d0 = a.x-b.x, d1 = a.y-b.y, d2 = a.z-b.z, d3 = a.w-b.w;
        s += d0*d0 + d1*d1 + d2*d2 + d3*d3;
    }
    #pragma unroll
    for (int m = 16; m; m >>= 1) s += __shfl_xor_sync(0xffffffffu, s, m);
    __shared__ float ws[8];
    if ((threadIdx.x & 31) == 0) ws[threadIdx.x >> 5] = s;
    __syncthreads();
    if (threadIdx.x == 0) {
        float tot = 0.f;
        for (int w = 0; w < (int)(blockDim.x >> 5); w++) tot += ws[w];
        atomicAdd(&g_acc[2], tot);
    }
}

// ---------------- K7: final combine ----------------
__global__ void k_final(float* out) {
    float s = 0.f;
    for (int i = threadIdx.x; i < NR; i += 256) s += logf(g_denom[i]);
    #pragma unroll
    for (int m = 16; m; m >>= 1) s += __shfl_xor_sync(0xffffffffu, s, m);
    __shared__ float ws[8];
    if ((threadIdx.x & 31) == 0) ws[threadIdx.x >> 5] = s;
    __syncthreads();
    if (threadIdx.x == 0) {
        float lsum = 0.f;
        for (int w = 0; w < 8; w++) lsum += ws[w];
        float supcon = -g_acc[0] * (1.0f / NR) + lsum;
        float mse = g_acc[2] * (1.0f / NMSE);
        out[0] = supcon + 0.5f * mse;
    }
}

extern "C" void kernel_launch(void* const* d_in, const int* in_sizes, int n_in,
                              void* d_out, int out_size) {
    const float* Zs  = (const float*)d_in[0];
    const int*   pos = (const int*)d_in[1];
    const int*   neg = (const int*)d_in[2];
    const float* fd  = (const float*)d_in[3];
    const float* id  = (const float*)d_in[4];
    float* out = (float*)d_out;

    static int smem_set = 0;
    int denom_smem = (64*BSTR + 2*128*BSTR) * (int)sizeof(__nv_bfloat16);
    if (!smem_set) {
        cudaFuncSetAttribute(k_denom, cudaFuncAttributeMaxDynamicSharedMemorySize, denom_smem);
        smem_set = 1;
    }

    k_init  <<<32, 256>>>();
    k_gather<<<NR/8, 256>>>(Zs, pos, neg);
    k_MA    <<<NMP, 256>>>();
    k_Mred  <<<64, 256>>>();
    k_prep  <<<1000, 128>>>();
    k_denom <<<252, 256, denom_smem>>>();
    k_mse   <<<1024, 256>>>(fd, id);
    k_final <<<1, 256>>>(out);
}

// round 7
// speedup vs baseline: 2.6462x; 1.3934x over previous
#include <cuda_runtime.h>
#include <cuda_bf16.h>
#include <math.h>
#include <stdint.h>

#define NR    8000
#define NPOS  4000
#define NF    128
#define NVOX  32768
#define NMSE  (128*32*32*32)
#define NMP   125          // k_M split-K partial count (64 rows each)

// ---- scratch (static device globals; no allocations) ----
__device__ float          g_P[NR*NF];        // normalized pixels fp32
__device__ __nv_bfloat16  g_Pb[NR*NF];       // normalized pixels bf16 (B operand)
__device__ __nv_bfloat16  g_Ab[NR*NF];       // row-scaled pixels bf16 (A operand)
__device__ float          g_Mp[NMP*NF*NF];   // split-K partials of P^T P (8 MB)
__device__ float          g_M[NF*NF];        // P^T P
__device__ float          g_S[2*NF];         // class block column sums
__device__ float          g_denom[NR];
__device__ float          g_acc[4];          // [0]=S_mask, [2]=mse sum

__device__ __forceinline__ unsigned smem_u32(const void* p) {
    return (unsigned)__cvta_generic_to_shared(p);
}
#define CP_ASYNC_COMMIT() asm volatile("cp.async.commit_group;\n" ::)
#define CP_ASYNC_WAIT(n)  asm volatile("cp.async.wait_group %0;\n" :: "n"(n))

// packed f32x2 helpers
__device__ __forceinline__ unsigned long long pk2(float lo, float hi) {
    unsigned long long v; asm("mov.b64 %0,{%1,%2};" : "=l"(v) : "f"(lo), "f"(hi)); return v;
}
__device__ __forceinline__ void unpk2(unsigned long long v, float& lo, float& hi) {
    asm("mov.b64 {%0,%1},%2;" : "=f"(lo), "=f"(hi) : "l"(v));
}
__device__ __forceinline__ unsigned long long fma2(unsigned long long a,
                                                   unsigned long long b,
                                                   unsigned long long c) {
    unsigned long long d;
    asm("fma.rn.f32x2 %0,%1,%2,%3;" : "=l"(d) : "l"(a), "l"(b), "l"(c));
    return d;
}
__device__ __forceinline__ unsigned long long add2(unsigned long long a,
                                                   unsigned long long b) {
    unsigned long long d;
    asm("add.rn.f32x2 %0,%1,%2;" : "=l"(d) : "l"(a), "l"(b));
    return d;
}

// ---------------- K0: zero accumulators ----------------
__global__ void k_init() {
    int i = blockIdx.x*256 + threadIdx.x, st = gridDim.x*256;
    for (int j = i; j < NR;    j += st) g_denom[j] = 0.f;
    for (int j = i; j < NF*NF; j += st) g_M[j] = 0.f;
    for (int j = i; j < 2*NF;  j += st) g_S[j] = 0.f;
    if (i < 4) g_acc[i] = 0.f;
}

// ---------------- K1: gather + L2-normalize rows (warp per row) ----------------
__global__ void k_gather(const float* __restrict__ Zs,
                         const int* __restrict__ pos,
                         const int* __restrict__ neg) {
    int t = threadIdx.x, wid = t >> 5, lane = t & 31;
    int r = blockIdx.x * 8 + wid;
    int v = (r < NPOS) ? pos[r] : neg[r - NPOS];
    float x[4];
    #pragma unroll
    for (int k = 0; k < 4; k++) x[k] = Zs[(size_t)(lane + 32*k)*NVOX + v];
    float s = x[0]*x[0] + x[1]*x[1] + x[2]*x[2] + x[3]*x[3];
    #pragma unroll
    for (int m = 16; m; m >>= 1) s += __shfl_xor_sync(0xffffffffu, s, m);
    float inv = 1.0f / fmaxf(sqrtf(s), 1e-12f);
    #pragma unroll
    for (int k = 0; k < 4; k++) {
        float p = x[k] * inv;
        g_P [r*NF + lane + 32*k] = p;
        g_Pb[r*NF + lane + 32*k] = __float2bfloat16(p);
    }
}

// ---------------- K2a: split-K partials of M = P^T P  (+ class column sums) ----
// grid 125 (64 rows each), block 256; thread owns 8x8 sub-block
__global__ void __launch_bounds__(256) k_MA() {
    __shared__ float sp[64][NF];
    int t = threadIdx.x;
    int r0 = blockIdx.x * 64;
    {
        const float4* src = (const float4*)&g_P[r0*NF];
        float4* dst = (float4*)&sp[0][0];
        for (int i = t; i < 64*NF/4; i += 256) dst[i] = src[i];
    }
    __syncthreads();
    // class column sums (block 62 straddles the pos/neg boundary)
    if (t < NF) {
        float s0 = 0.f, s1 = 0.f;
        for (int r = 0; r < 64; r++) {
            float v = sp[r][t];
            if (r0 + r < NPOS) s0 += v; else s1 += v;
        }
        atomicAdd(&g_S[t], s0);
        atomicAdd(&g_S[NF + t], s1);
    }
    int k0 = (t >> 4) * 8, l0 = (t & 15) * 8;
    float acc[8][8];
    #pragma unroll
    for (int i = 0; i < 8; i++)
        #pragma unroll
        for (int j = 0; j < 8; j++) acc[i][j] = 0.f;
    for (int r = 0; r < 64; r++) {
        float4 a0 = *(const float4*)&sp[r][k0];
        float4 a1 = *(const float4*)&sp[r][k0+4];
        float4 b0 = *(const float4*)&sp[r][l0];
        float4 b1 = *(const float4*)&sp[r][l0+4];
        float a[8] = {a0.x,a0.y,a0.z,a0.w,a1.x,a1.y,a1.z,a1.w};
        float b[8] = {b0.x,b0.y,b0.z,b0.w,b1.x,b1.y,b1.z,b1.w};
        #pragma unroll
        for (int i = 0; i < 8; i++)
            #pragma unroll
            for (int j = 0; j < 8; j++) acc[i][j] = fmaf(a[i], b[j], acc[i][j]);
    }
    float* dst = &g_Mp[(size_t)blockIdx.x * NF * NF];
    #pragma unroll
    for (int i = 0; i < 8; i++) {
        *(float4*)&dst[(k0+i)*NF + l0    ] = make_float4(acc[i][0],acc[i][1],acc[i][2],acc[i][3]);
        *(float4*)&dst[(k0+i)*NF + l0 + 4] = make_float4(acc[i][4],acc[i][5],acc[i][6],acc[i][7]);
    }
}

// ---------------- K2b: reduce partials -> g_M (split over partials, atomics) ----
// grid 320 = 64 element-chunks x 5 partial-chunks (25 partials each)
__global__ void k_Mred() {
    int e = (blockIdx.x & 63) * 256 + threadIdx.x;
    int c = blockIdx.x >> 6;
    float s = 0.f;
    int p0 = c * 25;
    #pragma unroll 25
    for (int p = p0; p < p0 + 25; p++) s += g_Mp[(size_t)p*NF*NF + e];
    atomicAdd(&g_M[e], s);
}

// ---------------- K4: per-row qf, S_mask contribution, scaled A ----------------
// grid 500 (16 rows each), block 128
__global__ void k_prep() {
    __shared__ float sp[16][NF];
    __shared__ float smQ[16][4], smS[16][4], smR[16], smC[16];
    int f = threadIdx.x;
    int r0 = blockIdx.x * 16;
    for (int r = 0; r < 16; r++) sp[r][f] = g_P[(r0+r)*NF + f];
    __syncthreads();
    float inner[16];
    #pragma unroll
    for (int r = 0; r < 16; r++) inner[r] = 0.f;
    for (int l = 0; l < NF; l++) {
        float m = g_M[f*NF + l];
        #pragma unroll
        for (int r = 0; r < 16; r++) inner[r] = fmaf(m, sp[r][l], inner[r]);
    }
    int sb = (r0 < NPOS) ? 0 : NF;
    float sf = g_S[sb + f];
    int lane = f & 31, w = f >> 5;
    #pragma unroll
    for (int r = 0; r < 16; r++) {
        float q = inner[r] * sp[r][f];
        float s = sf * sp[r][f];
        #pragma unroll
        for (int m = 16; m; m >>= 1) {
            q += __shfl_xor_sync(0xffffffffu, q, m);
            s += __shfl_xor_sync(0xffffffffu, s, m);
        }
        if (lane == 0) { smQ[r][w] = q; smS[r][w] = s; }
    }
    __syncthreads();
    if (f < 16) {
        int r = f;
        float qf = smQ[r][0] + smQ[r][1] + smQ[r][2] + smQ[r][3];
        float ps = smS[r][0] + smS[r][1] + smS[r][2] + smS[r][3];
        float rinv = rsqrtf(qf);
        rinv = rinv * (1.5f - 0.5f * qf * rinv * rinv);
        smR[r] = rinv;
        smC[r] = (ps - 1.0f) * rinv;
    }
    __syncthreads();
    if (f == 0) {
        float c = 0.f;
        #pragma unroll
        for (int r = 0; r < 16; r++) c += smC[r];
        atomicAdd(&g_acc[0], c);
    }
    for (int r = 0; r < 16; r++)
        g_Ab[(r0+r)*NF + f] = __float2bfloat16(sp[r][f] * smR[r]);
}

// ---------------- K5: fused bf16 GEMM + packed poly-exp + row reduce ----------------
__device__ __forceinline__ void mma16816(float c[4], const unsigned a[4],
                                         unsigned b0, unsigned b1) {
    asm volatile(
        "mma.sync.aligned.m16n8k16.row.col.f32.bf16.bf16.f32 "
        "{%0,%1,%2,%3}, {%4,%5,%6,%7}, {%8,%9}, {%0,%1,%2,%3};"
        : "+f"(c[0]), "+f"(c[1]), "+f"(c[2]), "+f"(c[3])
        : "r"(a[0]), "r"(a[1]), "r"(a[2]), "r"(a[3]), "r"(b0), "r"(b1));
}

#define BSTR 136           // padded smem stride in bf16 (272B; conflict-free)
#define NTILES 16          // 16 x 128 = 2048 >= 2000 cols

// grid 252: 126 row tiles (64 rows, class-aligned w/ zero-pad) x 2 column halves
__global__ void __launch_bounds__(256) k_denom() {
    extern __shared__ __nv_bfloat16 sm[];
    __nv_bfloat16* At = sm;                  // 64 x BSTR
    __nv_bfloat16* Bt = sm + 64*BSTR;        // 2 x 128 x BSTR (double buffer)

    int bid = blockIdx.x;
    int tileR = bid >> 1, jh = bid & 1;
    int r0, class_end, j0;
    if (tileR < 63) { r0 = tileR * 64;              class_end = NPOS; j0 = NPOS; }
    else            { r0 = NPOS + (tileR - 63)*64;  class_end = NR;   j0 = 0;    }
    j0 += jh * 2000;
    int jlim = j0 + 2000;

    int t = threadIdx.x;
    int wid = t >> 5, lane = t & 31;
    int g = lane >> 2, tt = lane & 3;
    int warp_m = wid & 3, warp_n = wid >> 2;

    // prefetch B tile 0 (cp.async; src-size=0 past jlim -> zero-fill)
    {
        for (int i = t; i < 2048; i += 256) {
            int row = i >> 4, seg = i & 15;
            int jj = j0 + row;
            unsigned dst = smem_u32(&Bt[row*BSTR + seg*8]);
            const __nv_bfloat16* src = &g_Pb[(size_t)min(jj, jlim-1)*NF + seg*8];
            int sz = (jj < jlim) ? 16 : 0;
            asm volatile("cp.async.cg.shared.global [%0], [%1], 16, %2;\n"
                         :: "r"(dst), "l"(src), "r"(sz));
        }
        CP_ASYNC_COMMIT();
    }

    // A tile: 64 rows x 128 bf16, zero rows beyond class_end
    for (int i = t; i < 1024; i += 256) {
        int row = i >> 4, seg = i & 15;
        int jj = r0 + row;
        uint4 v = make_uint4(0u,0u,0u,0u);
        if (jj < class_end) v = ((const uint4*)&g_Ab[(size_t)jj*NF])[seg];
        *(uint4*)&At[row*BSTR + seg*8] = v;
    }
    __syncthreads();

    // A fragments (reused across all B tiles)
    unsigned af[8][4];
    int ar = warp_m * 16 + g;
    #pragma unroll
    for (int kk = 0; kk < 8; kk++) {
        af[kk][0] = *(const unsigned*)&At[ ar    *BSTR + kk*16     + 2*tt];
        af[kk][1] = *(const unsigned*)&At[(ar+8)*BSTR + kk*16     + 2*tt];
        af[kk][2] = *(const unsigned*)&At[ ar    *BSTR + kk*16 + 8 + 2*tt];
        af[kk][3] = *(const unsigned*)&At[(ar+8)*BSTR + kk*16 + 8 + 2*tt];
    }

    // ldmatrix per-thread row base: lane l -> matrix m=l>>3, row r=l&7
    // col(q,m,r) = warp_n*64 + q*16 + (m>>1)*8 + r ; half = m&1
    int lm = lane >> 3, lr = lane & 7;
    unsigned lmbase;   // bf16-element offset (without q,kk terms)
    lmbase = (unsigned)((warp_n*64 + (lm>>1)*8 + lr) * BSTR + (lm&1)*8);

    // packed exp(x) deg-5 constants
    const unsigned long long K5 = pk2(1.f/120.f, 1.f/120.f);
    const unsigned long long K4 = pk2(1.f/24.f,  1.f/24.f);
    const unsigned long long K3 = pk2(1.f/6.f,   1.f/6.f);
    const unsigned long long K2 = pk2(0.5f,      0.5f);
    const unsigned long long K1 = pk2(1.f,       1.f);

    unsigned long long sA2 = pk2(0.f, 0.f), sB2 = pk2(0.f, 0.f);

    for (int tile = 0; tile < NTILES; tile++) {
        if (tile + 1 < NTILES) {
            int jt = j0 + (tile + 1) * 128;
            __nv_bfloat16* dbuf = &Bt[((tile + 1) & 1) * 128 * BSTR];
            for (int i = t; i < 2048; i += 256) {
                int row = i >> 4, seg = i & 15;
                int jj = jt + row;
                unsigned dst = smem_u32(&dbuf[row*BSTR + seg*8]);
                const __nv_bfloat16* src = &g_Pb[(size_t)min(jj, jlim-1)*NF + seg*8];
                int sz = (jj < jlim) ? 16 : 0;
                asm volatile("cp.async.cg.shared.global [%0], [%1], 16, %2;\n"
                             :: "r"(dst), "l"(src), "r"(sz));
            }
            CP_ASYNC_COMMIT();
            CP_ASYNC_WAIT(1);
        } else {
            CP_ASYNC_WAIT(0);
        }
        __syncthreads();

        const __nv_bfloat16* B = &Bt[(tile & 1) * 128 * BSTR];
        unsigned bbase = smem_u32(B) + 2u * lmbase;

        float c[8][4];
        #pragma unroll
        for (int nn = 0; nn < 8; nn++)
            #pragma unroll
            for (int q = 0; q < 4; q++) c[nn][q] = 0.f;

        #pragma unroll
        for (int kk = 0; kk < 8; kk++) {
            #pragma unroll
            for (int q = 0; q < 4; q++) {
                unsigned addr = bbase + 2u*(q*16*BSTR + kk*16);
                unsigned x0, x1, x2, x3;
                asm volatile(
                    "ldmatrix.sync.aligned.m8n8.x4.shared.b16 {%0,%1,%2,%3}, [%4];"
                    : "=r"(x0), "=r"(x1), "=r"(x2), "=r"(x3) : "r"(addr));
                mma16816(c[2*q],     af[kk], x0, x1);
                mma16816(c[2*q + 1], af[kk], x2, x3);
            }
        }
        #pragma unroll
        for (int nn = 0; nn < 8; nn++) {
            unsigned long long XA = pk2(c[nn][0], c[nn][1]);
            unsigned long long XB = pk2(c[nn][2], c[nn][3]);
            unsigned long long rA = fma2(K5, XA, K4);
            unsigned long long rB = fma2(K5, XB, K4);
            rA = fma2(rA, XA, K3);  rB = fma2(rB, XB, K3);
            rA = fma2(rA, XA, K2);  rB = fma2(rB, XB, K2);
            rA = fma2(rA, XA, K1);  rB = fma2(rB, XB, K1);
            rA = fma2(rA, XA, K1);  rB = fma2(rB, XB, K1);
            sA2 = add2(sA2, rA);
            sB2 = add2(sB2, rB);
        }
        __syncthreads();
    }

    float aLo, aHi, bLo, bHi;
    unpk2(sA2, aLo, aHi);
    unpk2(sB2, bLo, bHi);
    float sumA = aLo + aHi, sumB = bLo + bHi;
    #pragma unroll
    for (int m = 1; m <= 2; m <<= 1) {
        sumA += __shfl_xor_sync(0xffffffffu, sumA, m);
        sumB += __shfl_xor_sync(0xffffffffu, sumB, m);
    }
    if (tt == 0) {
        // 2048-2000=48 zero cols -> exp(0)=1 each, all within warp_n==1's range
        float corr = (warp_n == 1) ? 48.f : 0.f;
        int rowA = r0 + warp_m*16 + g;
        if (rowA     < class_end) atomicAdd(&g_denom[rowA],     sumA - corr);
        if (rowA + 8 < class_end) atomicAdd(&g_denom[rowA + 8], sumB - corr);
    }
}

// ---------------- K6: MSE partial ----------------
__global__ void k_mse(const float* __restrict__ fd, const float* __restrict__ id) {
    int n4 = NMSE / 4;
    float s = 0.f;
    for (int i = blockIdx.x*blockDim.x + threadIdx.x; i < n4; i += gridDim.x*blockDim.x) {
        float4 a = ((const float4*)fd)[i];
        float4 b = ((const float4*)id)[i];
        float d0 = a.x-b.x, d1 = a.y-b.y, d2 = a.z-b.z, d3 = a.w-b.w;
        s += d0*d0 + d1*d1 + d2*d2 + d3*d3;
    }
    #pragma unroll
    for (int m = 16; m; m >>= 1) s += __shfl_xor_sync(0xffffffffu, s, m);
    __shared__ float ws[8];
    if ((threadIdx.x & 31) == 0) ws[threadIdx.x >> 5] = s;
    __syncthreads();
    if (threadIdx.x == 0) {
        float tot = 0.f;
        for (int w = 0; w < (int)(blockDim.x >> 5); w++) tot += ws[w];
        atomicAdd(&g_acc[2], tot);
    }
}

// ---------------- K7: final combine ----------------
__global__ void k_final(float* out) {
    float s = 0.f;
    for (int i = threadIdx.x; i < NR; i += 256) s += logf(g_denom[i]);
    #pragma unroll
    for (int m = 16; m; m >>= 1) s += __shfl_xor_sync(0xffffffffu, s, m);
    __shared__ float ws[8];
    if ((threadIdx.x & 31) == 0) ws[threadIdx.x >> 5] = s;
    __syncthreads();
    if (threadIdx.x == 0) {
        float lsum = 0.f;
        for (int w = 0; w < 8; w++) lsum += ws[w];
        float supcon = -g_acc[0] * (1.0f / NR) + lsum;
        float mse = g_acc[2] * (1.0f / NMSE);
        out[0] = supcon + 0.5f * mse;
    }
}

extern "C" void kernel_launch(void* const* d_in, const int* in_sizes, int n_in,
                              void* d_out, int out_size) {
    const float* Zs  = (const float*)d_in[0];
    const int*   pos = (const int*)d_in[1];
    const int*   neg = (const int*)d_in[2];
    const float* fd  = (const float*)d_in[3];
    const float* id  = (const float*)d_in[4];
    float* out = (float*)d_out;

    static int smem_set = 0;
    int denom_smem = (64*BSTR + 2*128*BSTR) * (int)sizeof(__nv_bfloat16);
    if (!smem_set) {
        cudaFuncSetAttribute(k_denom, cudaFuncAttributeMaxDynamicSharedMemorySize, denom_smem);
        smem_set = 1;
    }

    k_init  <<<32, 256>>>();
    k_gather<<<NR/8, 256>>>(Zs, pos, neg);
    k_MA    <<<NMP, 256>>>();
    k_Mred  <<<320, 256>>>();
    k_prep  <<<500, 128>>>();
    k_denom <<<252, 256, denom_smem>>>();
    k_mse   <<<1024, 256>>>(fd, id);
    k_final <<<1, 256>>>(out);
}

// round 9
// speedup vs baseline: 2.7853x; 1.0526x over previous
#include <cuda_runtime.h>
#include <cuda_bf16.h>
#include <math.h>
#include <stdint.h>

#define NR    8000
#define NPOS  4000
#define NF    128
#define NVOX  32768
#define NMSE  (128*32*32*32)
#define NMP   125          // k_MA split-K partial count (64 rows each)

// ---- scratch (static device globals; no allocations) ----
__device__ float          g_P[NR*NF];        // normalized pixels fp32
__device__ __nv_bfloat16  g_Pb[NR*NF];       // normalized pixels bf16 (B operand)
__device__ __nv_bfloat16  g_Ab[NR*NF];       // row-scaled pixels bf16 (A operand)
__device__ float          g_Mp[NMP*NF*NF];   // split-K partials of P^T P (8 MB)
__device__ float          g_M[NF*NF];        // P^T P      (atomic, zeroed in k_front)
__device__ float          g_S[2*NF];         // class col sums (atomic, zeroed in k_front)
__device__ float          g_Sp[1000*NF];     // per-gather-block column-sum partials
__device__ float          g_mseP[512];       // per-block mse partials (plain store)
__device__ float          g_smaskP[500];     // per-block S_mask partials (plain store)
__device__ float          g_denomH[2*NR];    // per-column-half denom sums (plain store)

__device__ __forceinline__ unsigned smem_u32(const void* p) {
    return (unsigned)__cvta_generic_to_shared(p);
}
#define CP_ASYNC_COMMIT() asm volatile("cp.async.commit_group;\n" ::)
#define CP_ASYNC_WAIT(n)  asm volatile("cp.async.wait_group %0;\n" :: "n"(n))

// packed f32x2 helpers
__device__ __forceinline__ unsigned long long pk2(float lo, float hi) {
    unsigned long long v; asm("mov.b64 %0,{%1,%2};" : "=l"(v) : "f"(lo), "f"(hi)); return v;
}
__device__ __forceinline__ void unpk2(unsigned long long v, float& lo, float& hi) {
    asm("mov.b64 {%0,%1},%2;" : "=f"(lo), "=f"(hi) : "l"(v));
}
__device__ __forceinline__ unsigned long long fma2(unsigned long long a,
                                                   unsigned long long b,
                                                   unsigned long long c) {
    unsigned long long d;
    asm("fma.rn.f32x2 %0,%1,%2,%3;" : "=l"(d) : "l"(a), "l"(b), "l"(c));
    return d;
}
__device__ __forceinline__ unsigned long long add2(unsigned long long a,
                                                   unsigned long long b) {
    unsigned long long d;
    asm("add.rn.f32x2 %0,%1,%2;" : "=l"(d) : "l"(a), "l"(b));
    return d;
}

__device__ __forceinline__ void mma16816(float c[4], const unsigned a[4],
                                         unsigned b0, unsigned b1) {
    asm volatile(
        "mma.sync.aligned.m16n8k16.row.col.f32.bf16.bf16.f32 "
        "{%0,%1,%2,%3}, {%4,%5,%6,%7}, {%8,%9}, {%0,%1,%2,%3};"
        : "+f"(c[0]), "+f"(c[1]), "+f"(c[2]), "+f"(c[3])
        : "r"(a[0]), "r"(a[1]), "r"(a[2]), "r"(a[3]), "r"(b0), "r"(b1));
}
__device__ __forceinline__ void ldsm4(unsigned& x0, unsigned& x1,
                                      unsigned& x2, unsigned& x3, unsigned addr) {
    asm volatile("ldmatrix.sync.aligned.m8n8.x4.shared.b16 {%0,%1,%2,%3}, [%4];"
                 : "=r"(x0), "=r"(x1), "=r"(x2), "=r"(x3) : "r"(addr));
}

// ---------------- K1: fused front kernel ----------------
// blocks [0,1000): gather + L2-normalize 8 rows + column-sum partial
// blocks [1000,1512): MSE partials
// blocks 1512,1513: zero g_M / g_S for the atomic consumers downstream
__global__ void k_front(const float* __restrict__ Zs,
                        const int* __restrict__ pos,
                        const int* __restrict__ neg,
                        const float* __restrict__ fd,
                        const float* __restrict__ id) {
    __shared__ float smP[8][NF];
    int b = blockIdx.x, t = threadIdx.x;
    if (b < 1000) {
        int wid = t >> 5, lane = t & 31;
        int r = b * 8 + wid;
        int v = (r < NPOS) ? pos[r] : neg[r - NPOS];
        float x[4];
        #pragma unroll
        for (int k = 0; k < 4; k++) x[k] = Zs[(size_t)(lane + 32*k)*NVOX + v];
        float s = x[0]*x[0] + x[1]*x[1] + x[2]*x[2] + x[3]*x[3];
        #pragma unroll
        for (int m = 16; m; m >>= 1) s += __shfl_xor_sync(0xffffffffu, s, m);
        float inv = 1.0f / fmaxf(sqrtf(s), 1e-12f);
        #pragma unroll
        for (int k = 0; k < 4; k++) {
            float p = x[k] * inv;
            g_P [r*NF + lane + 32*k] = p;
            g_Pb[r*NF + lane + 32*k] = __float2bfloat16(p);
            smP[wid][lane + 32*k] = p;
        }
        __syncthreads();
        if (t < NF) {
            float cs = 0.f;
            #pragma unroll
            for (int w = 0; w < 8; w++) cs += smP[w][t];
            g_Sp[b*NF + t] = cs;
        }
    } else if (b < 1512) {
        int mb = b - 1000;
        int n4 = NMSE / 4;
        float s = 0.f;
        for (int i = mb*256 + t; i < n4; i += 512*256) {
            float4 a = ((const float4*)fd)[i];
            float4 c = ((const float4*)id)[i];
            float d0 = a.x-c.x, d1 = a.y-c.y, d2 = a.z-c.z, d3 = a.w-c.w;
            s += d0*d0 + d1*d1 + d2*d2 + d3*d3;
        }
        #pragma unroll
        for (int m = 16; m; m >>= 1) s += __shfl_xor_sync(0xffffffffu, s, m);
        __shared__ float ws[8];
        if ((t & 31) == 0) ws[t >> 5] = s;
        __syncthreads();
        if (t == 0) {
            float tot = 0.f;
            #pragma unroll
            for (int w = 0; w < 8; w++) tot += ws[w];
            g_mseP[mb] = tot;
        }
    } else {
        int half = b - 1512;                       // 0 or 1
        for (int i = t; i < 8192; i += 256) g_M[half*8192 + i] = 0.f;
        if (half == 1 && t < 2*NF) g_S[t] = 0.f;
    }
}

// ---------------- K2a: M = P^T P split-K partials via bf16 HMMA ----------------
// grid 125 (64 samples each), block 256 = 8 warps; warp w -> M rows 16w..16w+15
__global__ void __launch_bounds__(256) k_MA() {
    __shared__ unsigned short spT[128][72];  // transposed tile: [feat][sample]
    int t = threadIdx.x, wid = t >> 5, lane = t & 31;
    int r0 = blockIdx.x * 64;

    // load 64x128 bf16, transpose into spT
    for (int i = t; i < 1024; i += 256) {
        int r = i >> 4, seg = i & 15;
        uint4 v = ((const uint4*)&g_Pb[(size_t)(r0+r)*NF])[seg];
        unsigned w0 = v.x, w1 = v.y, w2 = v.z, w3 = v.w;
        int f = seg * 8;
        spT[f+0][r] = (unsigned short)(w0 & 0xffffu);
        spT[f+1][r] = (unsigned short)(w0 >> 16);
        spT[f+2][r] = (unsigned short)(w1 & 0xffffu);
        spT[f+3][r] = (unsigned short)(w1 >> 16);
        spT[f+4][r] = (unsigned short)(w2 & 0xffffu);
        spT[f+5][r] = (unsigned short)(w2 >> 16);
        spT[f+6][r] = (unsigned short)(w3 & 0xffffu);
        spT[f+7][r] = (unsigned short)(w3 >> 16);
    }
    __syncthreads();

    int i0 = wid * 16;
    int lm = lane >> 3, lr = lane & 7;
    unsigned base = smem_u32(&spT[0][0]);
    // A frags: a0=(rows0-7,k0-7) a1=(rows8-15,k0-7) a2=(rows0-7,k8-15) a3=(rows8-15,k8-15)
    unsigned aAddr0 = base + (unsigned)(((i0 + (lm & 1)*8 + lr) * 72 + (lm >> 1)*8) << 1);
    // B frags: x0/x1 = n-rows0-7 two k-halves; x2/x3 = n-rows8-15
    unsigned bRowOff = (unsigned)((((lm >> 1)*8 + lr) * 72 + (lm & 1)*8) << 1);

    float c[16][4];
    #pragma unroll
    for (int nn = 0; nn < 16; nn++)
        #pragma unroll
        for (int q = 0; q < 4; q++) c[nn][q] = 0.f;

    #pragma unroll
    for (int kk = 0; kk < 4; kk++) {
        unsigned af[4];
        ldsm4(af[0], af[1], af[2], af[3], aAddr0 + kk*32);
        #pragma unroll
        for (int q = 0; q < 8; q++) {
            unsigned x0, x1, x2, x3;
            unsigned addr = base + (unsigned)((q*16*72) << 1) + bRowOff + kk*32;
            ldsm4(x0, x1, x2, x3, addr);
            mma16816(c[2*q],     af, x0, x1);
            mma16816(c[2*q + 1], af, x2, x3);
        }
    }

    float* dst = &g_Mp[(size_t)blockIdx.x * NF * NF];
    int g = lane >> 2, tt = lane & 3;
    #pragma unroll
    for (int nn = 0; nn < 16; nn++) {
        int col = nn*8 + 2*tt;
        *(float2*)&dst[(i0+g  )*NF + col] = make_float2(c[nn][0], c[nn][1]);
        *(float2*)&dst[(i0+g+8)*NF + col] = make_float2(c[nn][2], c[nn][3]);
    }
}

// ---------------- K2b: reduce M partials + S partials ----------------
// grid 340: [0,320) = 64 element-chunks x 5 partial-chunks (25 each) -> atomic g_M
//           [320,340) = 2 classes x 10 chunks (50 gather-blocks each) -> atomic g_S
__global__ void k_Mred() {
    int b = blockIdx.x, t = threadIdx.x;
    if (b < 320) {
        int e = (b & 63) * 256 + t;
        int p0 = (b >> 6) * 25;
        float s = 0.f;
        #pragma unroll 25
        for (int p = p0; p < p0 + 25; p++) s += g_Mp[(size_t)p*NF*NF + e];
        atomicAdd(&g_M[e], s);
    } else if (t < NF) {
        int idx = b - 320;
        int cls = idx & 1, chunk = idx >> 1;
        int b0 = cls * 500 + chunk * 50;
        float s = 0.f;
        #pragma unroll 10
        for (int k = 0; k < 50; k++) s += g_Sp[(b0 + k)*NF + t];
        atomicAdd(&g_S[cls*NF + t], s);
    }
}

// ---------------- K4: per-row qf, S_mask partial, scaled A ----------------
// grid 500 (16 rows each), block 128
__global__ void k_prep() {
    __shared__ float sp[16][NF];
    __shared__ float smQ[16][4], smS[16][4], smR[16], smC[16];
    int f = threadIdx.x;
    int r0 = blockIdx.x * 16;
    for (int r = 0; r < 16; r++) sp[r][f] = g_P[(r0+r)*NF + f];
    __syncthreads();
    float inner[16];
    #pragma unroll
    for (int r = 0; r < 16; r++) inner[r] = 0.f;
    for (int l = 0; l < NF; l++) {
        float m = g_M[f*NF + l];
        #pragma unroll
        for (int r = 0; r < 16; r++) inner[r] = fmaf(m, sp[r][l], inner[r]);
    }
    int sb = (r0 < NPOS) ? 0 : NF;
    float sf = g_S[sb + f];
    int lane = f & 31, w = f >> 5;
    #pragma unroll
    for (int r = 0; r < 16; r++) {
        float q = inner[r] * sp[r][f];
        float s = sf * sp[r][f];
        #pragma unroll
        for (int m = 16; m; m >>= 1) {
            q += __shfl_xor_sync(0xffffffffu, q, m);
            s += __shfl_xor_sync(0xffffffffu, s, m);
        }
        if (lane == 0) { smQ[r][w] = q; smS[r][w] = s; }
    }
    __syncthreads();
    if (f < 16) {
        int r = f;
        float qf = smQ[r][0] + smQ[r][1] + smQ[r][2] + smQ[r][3];
        float ps = smS[r][0] + smS[r][1] + smS[r][2] + smS[r][3];
        float rinv = rsqrtf(qf);
        rinv = rinv * (1.5f - 0.5f * qf * rinv * rinv);
        smR[r] = rinv;
        smC[r] = (ps - 1.0f) * rinv;
    }
    __syncthreads();
    if (f == 0) {
        float c = 0.f;
        #pragma unroll
        for (int r = 0; r < 16; r++) c += smC[r];
        g_smaskP[blockIdx.x] = c;
    }
    for (int r = 0; r < 16; r++)
        g_Ab[(r0+r)*NF + f] = __float2bfloat16(sp[r][f] * smR[r]);
}

// ---------------- K5: fused bf16 GEMM + packed poly-exp + row reduce ----------------
#define CSTR   136         // padded smem stride in bf16
#define NCHUNK 32          // 32 x 64 = 2048 >= 2000 cols

// grid 252: 126 row tiles (64 rows, class-aligned w/ zero-pad) x 2 column halves
// 2 blocks/SM -> single wave
__global__ void __launch_bounds__(256, 2) k_denom() {
    extern __shared__ __nv_bfloat16 sm[];
    __nv_bfloat16* At = sm;                  // 64 x CSTR
    __nv_bfloat16* Bt = sm + 64*CSTR;        // 3 x 64 x CSTR (triple buffer)

    int bid = blockIdx.x;
    int tileR = bid >> 1, jh = bid & 1;
    int r0, class_end, j0;
    if (tileR < 63) { r0 = tileR * 64;              class_end = NPOS; j0 = NPOS; }
    else            { r0 = NPOS + (tileR - 63)*64;  class_end = NR;   j0 = 0;    }
    j0 += jh * 2000;
    int jlim = j0 + 2000;

    int t = threadIdx.x;
    int wid = t >> 5, lane = t & 31;
    int g = lane >> 2, tt = lane & 3;
    int warp_m = wid & 3, warp_n = wid >> 2;

    // prologue: prefetch chunks 0,1,2 (64 rows each)
    #pragma unroll
    for (int ch = 0; ch < 3; ch++) {
        __nv_bfloat16* dbuf = &Bt[ch * 64 * CSTR];
        for (int i = t; i < 1024; i += 256) {
            int row = i >> 4, seg = i & 15;
            int jj = j0 + ch*64 + row;
            unsigned dst = smem_u32(&dbuf[row*CSTR + seg*8]);
            const __nv_bfloat16* src = &g_Pb[(size_t)min(jj, jlim-1)*NF + seg*8];
            int sz = (jj < jlim) ? 16 : 0;
            asm volatile("cp.async.cg.shared.global [%0], [%1], 16, %2;\n"
                         :: "r"(dst), "l"(src), "r"(sz));
        }
        CP_ASYNC_COMMIT();
    }

    // A tile: 64 rows x 128 bf16, zero rows beyond class_end
    for (int i = t; i < 1024; i += 256) {
        int row = i >> 4, seg = i & 15;
        int jj = r0 + row;
        uint4 v = make_uint4(0u,0u,0u,0u);
        if (jj < class_end) v = ((const uint4*)&g_Ab[(size_t)jj*NF])[seg];
        *(uint4*)&At[row*CSTR + seg*8] = v;
    }
    __syncthreads();

    // A fragments (reused across all chunks)
    unsigned af[8][4];
    int ar = warp_m * 16 + g;
    #pragma unroll
    for (int kk = 0; kk < 8; kk++) {
        af[kk][0] = *(const unsigned*)&At[ ar    *CSTR + kk*16     + 2*tt];
        af[kk][1] = *(const unsigned*)&At[(ar+8)*CSTR + kk*16     + 2*tt];
        af[kk][2] = *(const unsigned*)&At[ ar    *CSTR + kk*16 + 8 + 2*tt];
        af[kk][3] = *(const unsigned*)&At[(ar+8)*CSTR + kk*16 + 8 + 2*tt];
    }

    // ldmatrix B row base within a 64-col chunk (warp_n owns 32 cols)
    int lm = lane >> 3, lr = lane & 7;
    unsigned lmbase = (unsigned)((warp_n*32 + (lm>>1)*8 + lr) * CSTR + (lm&1)*8);

    const unsigned long long K5 = pk2(1.f/120.f, 1.f/120.f);
    const unsigned long long K4 = pk2(1.f/24.f,  1.f/24.f);
    const unsigned long long K3 = pk2(1.f/6.f,   1.f/6.f);
    const unsigned long long K2 = pk2(0.5f,      0.5f);
    const unsigned long long K1 = pk2(1.f,       1.f);

    unsigned long long sA2 = pk2(0.f, 0.f), sB2 = pk2(0.f, 0.f);

    for (int ch = 0; ch < NCHUNK; ch++) {
        if (ch <= NCHUNK-3)      { CP_ASYNC_WAIT(2); }
        else if (ch == NCHUNK-2) { CP_ASYNC_WAIT(1); }
        else                     { CP_ASYNC_WAIT(0); }
        __syncthreads();

        const __nv_bfloat16* B = &Bt[(ch % 3) * 64 * CSTR];
        unsigned bbase = smem_u32(B) + 2u * lmbase;

        float c[4][4];
        #pragma unroll
        for (int nn = 0; nn < 4; nn++)
            #pragma unroll
            for (int q = 0; q < 4; q++) c[nn][q] = 0.f;

        #pragma unroll
        for (int kk = 0; kk < 8; kk++) {
            #pragma unroll
            for (int q = 0; q < 2; q++) {
                unsigned x0, x1, x2, x3;
                ldsm4(x0, x1, x2, x3, bbase + 2u*(unsigned)(q*16*CSTR + kk*16));
                mma16816(c[2*q],     af[kk], x0, x1);
                mma16816(c[2*q + 1], af[kk], x2, x3);
            }
        }
        #pragma unroll
        for (int nn = 0; nn < 4; nn++) {
            unsigned long long XA = pk2(c[nn][0], c[nn][1]);
            unsigned long long XB = pk2(c[nn][2], c[nn][3]);
            unsigned long long rA = fma2(K5, XA, K4);
            unsigned long long rB = fma2(K5, XB, K4);
            rA = fma2(rA, XA, K3);  rB = fma2(rB, XB, K3);
            rA = fma2(rA, XA, K2);  rB = fma2(rB, XB, K2);
            rA = fma2(rA, XA, K1);  rB = fma2(rB, XB, K1);
            rA = fma2(rA, XA, K1);  rB = fma2(rB, XB, K1);
            sA2 = add2(sA2, rA);
            sB2 = add2(sB2, rB);
        }
        __syncthreads();

        // issue chunk ch+3 into the buffer just freed
        if (ch + 3 < NCHUNK) {
            int jt = j0 + (ch + 3) * 64;
            __nv_bfloat16* dbuf = &Bt[(ch % 3) * 64 * CSTR];
            for (int i = t; i < 1024; i += 256) {
                int row = i >> 4, seg = i & 15;
                int jj = jt + row;
                unsigned dst = smem_u32(&dbuf[row*CSTR + seg*8]);
                const __nv_bfloat16* src = &g_Pb[(size_t)min(jj, jlim-1)*NF + seg*8];
                int sz = (jj < jlim) ? 16 : 0;
                asm volatile("cp.async.cg.shared.global [%0], [%1], 16, %2;\n"
                             :: "r"(dst), "l"(src), "r"(sz));
            }
            CP_ASYNC_COMMIT();
        }
    }

    float aLo, aHi, bLo, bHi;
    unpk2(sA2, aLo, aHi);
    unpk2(sB2, bLo, bHi);
    float sumA = aLo + aHi, sumB = bLo + bHi;
    #pragma unroll
    for (int m = 1; m <= 2; m <<= 1) {
        sumA += __shfl_xor_sync(0xffffffffu, sumA, m);
        sumB += __shfl_xor_sync(0xffffffffu, sumB, m);
    }
    // cross-warp_n reduce + plain per-half store (no atomics, no init)
    __syncthreads();
    float* sred = (float*)sm;
    if (tt == 0) {
        sred[warp_n*64 + warp_m*16 + g]     = sumA;
        sred[warp_n*64 + warp_m*16 + g + 8] = sumB;
    }
    __syncthreads();
    if (t < 64) {
        int row = r0 + t;
        if (row < class_end)
            g_denomH[jh*NR + row] = sred[t] + sred[64 + t] - 48.0f;  // 48 zero-pad cols
    }
}

// ---------------- K7: final combine ----------------
__global__ void k_final(float* out) {
    int t = threadIdx.x;
    float s = 0.f;
    for (int i = t; i < NR; i += 256)
        s += logf(g_denomH[i] + g_denomH[NR + i]);
    float sm_ = 0.f;
    for (int i = t; i < 512; i += 256) sm_ += g_mseP[i];
    float sk = 0.f;
    for (int i = t; i < 500; i += 256) sk += g_smaskP[i];
    #pragma unroll
    for (int m = 16; m; m >>= 1) {
        s   += __shfl_xor_sync(0xffffffffu, s, m);
        sm_ += __shfl_xor_sync(0xffffffffu, sm_, m);
        sk  += __shfl_xor_sync(0xffffffffu, sk, m);
    }
    __shared__ float ws[8][3];
    if ((t & 31) == 0) { ws[t>>5][0] = s; ws[t>>5][1] = sm_; ws[t>>5][2] = sk; }
    __syncthreads();
    if (t == 0) {
        float lsum = 0.f, msum = 0.f, ksum = 0.f;
        #pragma unroll
        for (int w = 0; w < 8; w++) { lsum += ws[w][0]; msum += ws[w][1]; ksum += ws[w][2]; }
        float supcon = -ksum * (1.0f / NR) + lsum;
        float mse = msum * (1.0f / NMSE);
        out[0] = supcon + 0.5f * mse;
    }
}

extern "C" void kernel_launch(void* const* d_in, const int* in_sizes, int n_in,
                              void* d_out, int out_size) {
    const float* Zs  = (const float*)d_in[0];
    const int*   pos = (const int*)d_in[1];
    const int*   neg = (const int*)d_in[2];
    const float* fd  = (const float*)d_in[3];
    const float* id  = (const float*)d_in[4];
    float* out = (float*)d_out;

    static int smem_set = 0;
    int denom_smem = (64*CSTR + 3*64*CSTR) * (int)sizeof(__nv_bfloat16);
    if (!smem_set) {
        cudaFuncSetAttribute(k_denom, cudaFuncAttributeMaxDynamicSharedMemorySize, denom_smem);
        smem_set = 1;
    }

    k_front <<<1514, 256>>>(Zs, pos, neg, fd, id);
    k_MA    <<<NMP, 256>>>();
    k_Mred  <<<340, 256>>>();
    k_prep  <<<500, 128>>>();
    k_denom <<<252, 256, denom_smem>>>();
    k_final <<<1, 256>>>(out);
}

// round 10
// speedup vs baseline: 3.8726x; 1.3904x over previous
#include <cuda_runtime.h>
#include <cuda_bf16.h>
#include <math.h>
#include <stdint.h>

#define NR    8000
#define NPOS  4000
#define NF    128
#define NVOX  32768
#define NMSE  (128*32*32*32)
#define NMP   125          // k_MA split-K partial count (64 rows each)

// ---- scratch (static device globals; no allocations) ----
__device__ float          g_P[NR*NF];        // normalized pixels fp32
__device__ __nv_bfloat16  g_Pb[NR*NF];       // normalized pixels bf16 (B operand)
__device__ __nv_bfloat16  g_Ab[NR*NF];       // row-scaled pixels bf16 (A operand)
__device__ float          g_Mp[NMP*NF*NF];   // split-K partials of P^T P (8 MB)
__device__ float          g_M[NF*NF];        // P^T P      (atomic, zeroed in k_front)
__device__ float          g_S[2*NF];         // class col sums (atomic, zeroed in k_front)
__device__ float          g_Sp[1000*NF];     // per-gather-block column-sum partials
__device__ float          g_mseP[512];       // per-block mse partials (plain store)
__device__ float          g_smaskP[500];     // per-block S_mask partials (plain store)
__device__ float          g_denomH[2*NR];    // per-column-half denom sums (plain store)

__device__ __forceinline__ unsigned smem_u32(const void* p) {
    return (unsigned)__cvta_generic_to_shared(p);
}
#define CP_ASYNC_COMMIT() asm volatile("cp.async.commit_group;\n" ::)
#define CP_ASYNC_WAIT(n)  asm volatile("cp.async.wait_group %0;\n" :: "n"(n))

// packed f32x2 helpers
__device__ __forceinline__ unsigned long long pk2(float lo, float hi) {
    unsigned long long v; asm("mov.b64 %0,{%1,%2};" : "=l"(v) : "f"(lo), "f"(hi)); return v;
}
__device__ __forceinline__ void unpk2(unsigned long long v, float& lo, float& hi) {
    asm("mov.b64 {%0,%1},%2;" : "=f"(lo), "=f"(hi) : "l"(v));
}
__device__ __forceinline__ unsigned long long fma2(unsigned long long a,
                                                   unsigned long long b,
                                                   unsigned long long c) {
    unsigned long long d;
    asm("fma.rn.f32x2 %0,%1,%2,%3;" : "=l"(d) : "l"(a), "l"(b), "l"(c));
    return d;
}
__device__ __forceinline__ unsigned long long add2(unsigned long long a,
                                                   unsigned long long b) {
    unsigned long long d;
    asm("add.rn.f32x2 %0,%1,%2;" : "=l"(d) : "l"(a), "l"(b));
    return d;
}

__device__ __forceinline__ void mma16816(float c[4], const unsigned a[4],
                                         unsigned b0, unsigned b1) {
    asm volatile(
        "mma.sync.aligned.m16n8k16.row.col.f32.bf16.bf16.f32 "
        "{%0,%1,%2,%3}, {%4,%5,%6,%7}, {%8,%9}, {%0,%1,%2,%3};"
        : "+f"(c[0]), "+f"(c[1]), "+f"(c[2]), "+f"(c[3])
        : "r"(a[0]), "r"(a[1]), "r"(a[2]), "r"(a[3]), "r"(b0), "r"(b1));
}
__device__ __forceinline__ void ldsm4(unsigned& x0, unsigned& x1,
                                      unsigned& x2, unsigned& x3, unsigned addr) {
    asm volatile("ldmatrix.sync.aligned.m8n8.x4.shared.b16 {%0,%1,%2,%3}, [%4];"
                 : "=r"(x0), "=r"(x1), "=r"(x2), "=r"(x3) : "r"(addr));
}

// ---------------- K1: fused front kernel ----------------
// blocks [0,1000): gather + L2-normalize 8 rows + column-sum partial
// blocks [1000,1512): MSE partials
// blocks 1512,1513: zero g_M / g_S for the atomic consumers downstream
__global__ void k_front(const float* __restrict__ Zs,
                        const int* __restrict__ pos,
                        const int* __restrict__ neg,
                        const float* __restrict__ fd,
                        const float* __restrict__ id) {
    __shared__ float smP[8][NF];
    int b = blockIdx.x, t = threadIdx.x;
    if (b < 1000) {
        int wid = t >> 5, lane = t & 31;
        int r = b * 8 + wid;
        int v = (r < NPOS) ? pos[r] : neg[r - NPOS];
        float x[4];
        #pragma unroll
        for (int k = 0; k < 4; k++) x[k] = Zs[(size_t)(lane + 32*k)*NVOX + v];
        float s = x[0]*x[0] + x[1]*x[1] + x[2]*x[2] + x[3]*x[3];
        #pragma unroll
        for (int m = 16; m; m >>= 1) s += __shfl_xor_sync(0xffffffffu, s, m);
        float inv = 1.0f / fmaxf(sqrtf(s), 1e-12f);
        #pragma unroll
        for (int k = 0; k < 4; k++) {
            float p = x[k] * inv;
            g_P [r*NF + lane + 32*k] = p;
            g_Pb[r*NF + lane + 32*k] = __float2bfloat16(p);
            smP[wid][lane + 32*k] = p;
        }
        __syncthreads();
        if (t < NF) {
            float cs = 0.f;
            #pragma unroll
            for (int w = 0; w < 8; w++) cs += smP[w][t];
            g_Sp[b*NF + t] = cs;
        }
    } else if (b < 1512) {
        int mb = b - 1000;
        int n4 = NMSE / 4;
        float s = 0.f;
        for (int i = mb*256 + t; i < n4; i += 512*256) {
            float4 a = ((const float4*)fd)[i];
            float4 c = ((const float4*)id)[i];
            float d0 = a.x-c.x, d1 = a.y-c.y, d2 = a.z-c.z, d3 = a.w-c.w;
            s += d0*d0 + d1*d1 + d2*d2 + d3*d3;
        }
        #pragma unroll
        for (int m = 16; m; m >>= 1) s += __shfl_xor_sync(0xffffffffu, s, m);
        __shared__ float ws[8];
        if ((t & 31) == 0) ws[t >> 5] = s;
        __syncthreads();
        if (t == 0) {
            float tot = 0.f;
            #pragma unroll
            for (int w = 0; w < 8; w++) tot += ws[w];
            g_mseP[mb] = tot;
        }
    } else {
        int half = b - 1512;                       // 0 or 1
        for (int i = t; i < 8192; i += 256) g_M[half*8192 + i] = 0.f;
        if (half == 1 && t < 2*NF) g_S[t] = 0.f;
    }
}

// ---------------- K2a: M = P^T P split-K partials via bf16 HMMA ----------------
// grid 125 (64 samples each), block 256 = 8 warps; warp w -> M rows 16w..16w+15
__global__ void __launch_bounds__(256) k_MA() {
    __shared__ unsigned short spT[128][72];  // transposed tile: [feat][sample]
    int t = threadIdx.x, wid = t >> 5, lane = t & 31;
    int r0 = blockIdx.x * 64;

    // load 64x128 bf16, transpose into spT
    for (int i = t; i < 1024; i += 256) {
        int r = i >> 4, seg = i & 15;
        uint4 v = ((const uint4*)&g_Pb[(size_t)(r0+r)*NF])[seg];
        unsigned w0 = v.x, w1 = v.y, w2 = v.z, w3 = v.w;
        int f = seg * 8;
        spT[f+0][r] = (unsigned short)(w0 & 0xffffu);
        spT[f+1][r] = (unsigned short)(w0 >> 16);
        spT[f+2][r] = (unsigned short)(w1 & 0xffffu);
        spT[f+3][r] = (unsigned short)(w1 >> 16);
        spT[f+4][r] = (unsigned short)(w2 & 0xffffu);
        spT[f+5][r] = (unsigned short)(w2 >> 16);
        spT[f+6][r] = (unsigned short)(w3 & 0xffffu);
        spT[f+7][r] = (unsigned short)(w3 >> 16);
    }
    __syncthreads();

    int i0 = wid * 16;
    int lm = lane >> 3, lr = lane & 7;
    unsigned base = smem_u32(&spT[0][0]);
    // A frags: a0=(rows0-7,k0-7) a1=(rows8-15,k0-7) a2=(rows0-7,k8-15) a3=(rows8-15,k8-15)
    unsigned aAddr0 = base + (unsigned)(((i0 + (lm & 1)*8 + lr) * 72 + (lm >> 1)*8) << 1);
    // B frags: x0/x1 = n-rows0-7 two k-halves; x2/x3 = n-rows8-15
    unsigned bRowOff = (unsigned)((((lm >> 1)*8 + lr) * 72 + (lm & 1)*8) << 1);

    float c[16][4];
    #pragma unroll
    for (int nn = 0; nn < 16; nn++)
        #pragma unroll
        for (int q = 0; q < 4; q++) c[nn][q] = 0.f;

    #pragma unroll
    for (int kk = 0; kk < 4; kk++) {
        unsigned af[4];
        ldsm4(af[0], af[1], af[2], af[3], aAddr0 + kk*32);
        #pragma unroll
        for (int q = 0; q < 8; q++) {
            unsigned x0, x1, x2, x3;
            unsigned addr = base + (unsigned)((q*16*72) << 1) + bRowOff + kk*32;
            ldsm4(x0, x1, x2, x3, addr);
            mma16816(c[2*q],     af, x0, x1);
            mma16816(c[2*q + 1], af, x2, x3);
        }
    }

    float* dst = &g_Mp[(size_t)blockIdx.x * NF * NF];
    int g = lane >> 2, tt = lane & 3;
    #pragma unroll
    for (int nn = 0; nn < 16; nn++) {
        int col = nn*8 + 2*tt;
        *(float2*)&dst[(i0+g  )*NF + col] = make_float2(c[nn][0], c[nn][1]);
        *(float2*)&dst[(i0+g+8)*NF + col] = make_float2(c[nn][2], c[nn][3]);
    }
}

// ---------------- K2b: reduce M partials + S partials ----------------
// grid 340: [0,320) = 64 element-chunks x 5 partial-chunks (25 each) -> atomic g_M
//           [320,340) = 2 classes x 10 chunks (50 gather-blocks each) -> atomic g_S
__global__ void k_Mred() {
    int b = blockIdx.x, t = threadIdx.x;
    if (b < 320) {
        int e = (b & 63) * 256 + t;
        int p0 = (b >> 6) * 25;
        float s = 0.f;
        #pragma unroll 25
        for (int p = p0; p < p0 + 25; p++) s += g_Mp[(size_t)p*NF*NF + e];
        atomicAdd(&g_M[e], s);
    } else if (t < NF) {
        int idx = b - 320;
        int cls = idx & 1, chunk = idx >> 1;
        int b0 = cls * 500 + chunk * 50;
        float s = 0.f;
        #pragma unroll 10
        for (int k = 0; k < 50; k++) s += g_Sp[(b0 + k)*NF + t];
        atomicAdd(&g_S[cls*NF + t], s);
    }
}

// ---------------- K4: per-row qf, S_mask partial, scaled A ----------------
// grid 500 (16 rows each), block 128
// M is symmetric: read M[l][f] (coalesced across f) instead of M[f][l].
__global__ void k_prep() {
    __shared__ float sp[16][NF];
    __shared__ float smQ[16][4], smS[16][4], smR[16], smC[16];
    int f = threadIdx.x;
    int r0 = blockIdx.x * 16;
    for (int r = 0; r < 16; r++) sp[r][f] = g_P[(r0+r)*NF + f];
    __syncthreads();
    float inner[16];
    #pragma unroll
    for (int r = 0; r < 16; r++) inner[r] = 0.f;
    #pragma unroll 4
    for (int l = 0; l < NF; l += 4) {
        // coalesced: at fixed l, lanes read consecutive f
        float m0 = g_M[(l+0)*NF + f];
        float m1 = g_M[(l+1)*NF + f];
        float m2 = g_M[(l+2)*NF + f];
        float m3 = g_M[(l+3)*NF + f];
        #pragma unroll
        for (int r = 0; r < 16; r++) {
            float4 s4 = *(const float4*)&sp[r][l];   // one LDS.128 broadcast
            float acc = inner[r];
            acc = fmaf(m0, s4.x, acc);
            acc = fmaf(m1, s4.y, acc);
            acc = fmaf(m2, s4.z, acc);
            acc = fmaf(m3, s4.w, acc);
            inner[r] = acc;
        }
    }
    int sb = (r0 < NPOS) ? 0 : NF;
    float sf = g_S[sb + f];
    int lane = f & 31, w = f >> 5;
    #pragma unroll
    for (int r = 0; r < 16; r++) {
        float q = inner[r] * sp[r][f];
        float s = sf * sp[r][f];
        #pragma unroll
        for (int m = 16; m; m >>= 1) {
            q += __shfl_xor_sync(0xffffffffu, q, m);
            s += __shfl_xor_sync(0xffffffffu, s, m);
        }
        if (lane == 0) { smQ[r][w] = q; smS[r][w] = s; }
    }
    __syncthreads();
    if (f < 16) {
        int r = f;
        float qf = smQ[r][0] + smQ[r][1] + smQ[r][2] + smQ[r][3];
        float ps = smS[r][0] + smS[r][1] + smS[r][2] + smS[r][3];
        float rinv = rsqrtf(qf);
        rinv = rinv * (1.5f - 0.5f * qf * rinv * rinv);
        smR[r] = rinv;
        smC[r] = (ps - 1.0f) * rinv;
    }
    __syncthreads();
    if (f == 0) {
        float c = 0.f;
        #pragma unroll
        for (int r = 0; r < 16; r++) c += smC[r];
        g_smaskP[blockIdx.x] = c;
    }
    for (int r = 0; r < 16; r++)
        g_Ab[(r0+r)*NF + f] = __float2bfloat16(sp[r][f] * smR[r]);
}

// ---------------- K5: fused bf16 GEMM + packed poly-exp + row reduce ----------------
#define CSTR   136         // padded smem stride in bf16
#define NCHUNK 32          // 32 x 64 = 2048 >= 2000 cols

// grid 252: 126 row tiles (64 rows, class-aligned w/ zero-pad) x 2 column halves
// 2 blocks/SM -> single wave
__global__ void __launch_bounds__(256, 2) k_denom() {
    extern __shared__ __nv_bfloat16 sm[];
    __nv_bfloat16* At = sm;                  // 64 x CSTR
    __nv_bfloat16* Bt = sm + 64*CSTR;        // 3 x 64 x CSTR (triple buffer)

    int bid = blockIdx.x;
    int tileR = bid >> 1, jh = bid & 1;
    int r0, class_end, j0;
    if (tileR < 63) { r0 = tileR * 64;              class_end = NPOS; j0 = NPOS; }
    else            { r0 = NPOS + (tileR - 63)*64;  class_end = NR;   j0 = 0;    }
    j0 += jh * 2000;
    int jlim = j0 + 2000;

    int t = threadIdx.x;
    int wid = t >> 5, lane = t & 31;
    int g = lane >> 2, tt = lane & 3;
    int warp_m = wid & 3, warp_n = wid >> 2;

    // prologue: prefetch chunks 0,1,2 (64 rows each)
    #pragma unroll
    for (int ch = 0; ch < 3; ch++) {
        __nv_bfloat16* dbuf = &Bt[ch * 64 * CSTR];
        for (int i = t; i < 1024; i += 256) {
            int row = i >> 4, seg = i & 15;
            int jj = j0 + ch*64 + row;
            unsigned dst = smem_u32(&dbuf[row*CSTR + seg*8]);
            const __nv_bfloat16* src = &g_Pb[(size_t)min(jj, jlim-1)*NF + seg*8];
            int sz = (jj < jlim) ? 16 : 0;
            asm volatile("cp.async.cg.shared.global [%0], [%1], 16, %2;\n"
                         :: "r"(dst), "l"(src), "r"(sz));
        }
        CP_ASYNC_COMMIT();
    }

    // A tile: 64 rows x 128 bf16, zero rows beyond class_end
    for (int i = t; i < 1024; i += 256) {
        int row = i >> 4, seg = i & 15;
        int jj = r0 + row;
        uint4 v = make_uint4(0u,0u,0u,0u);
        if (jj < class_end) v = ((const uint4*)&g_Ab[(size_t)jj*NF])[seg];
        *(uint4*)&At[row*CSTR + seg*8] = v;
    }
    __syncthreads();

    // A fragments (reused across all chunks)
    unsigned af[8][4];
    int ar = warp_m * 16 + g;
    #pragma unroll
    for (int kk = 0; kk < 8; kk++) {
        af[kk][0] = *(const unsigned*)&At[ ar    *CSTR + kk*16     + 2*tt];
        af[kk][1] = *(const unsigned*)&At[(ar+8)*CSTR + kk*16     + 2*tt];
        af[kk][2] = *(const unsigned*)&At[ ar    *CSTR + kk*16 + 8 + 2*tt];
        af[kk][3] = *(const unsigned*)&At[(ar+8)*CSTR + kk*16 + 8 + 2*tt];
    }

    // ldmatrix B row base within a 64-col chunk (warp_n owns 32 cols)
    int lm = lane >> 3, lr = lane & 7;
    unsigned lmbase = (unsigned)((warp_n*32 + (lm>>1)*8 + lr) * CSTR + (lm&1)*8);

    const unsigned long long K5 = pk2(1.f/120.f, 1.f/120.f);
    const unsigned long long K4 = pk2(1.f/24.f,  1.f/24.f);
    const unsigned long long K3 = pk2(1.f/6.f,   1.f/6.f);
    const unsigned long long K2 = pk2(0.5f,      0.5f);
    const unsigned long long K1 = pk2(1.f,       1.f);

    unsigned long long sA2 = pk2(0.f, 0.f), sB2 = pk2(0.f, 0.f);

    for (int ch = 0; ch < NCHUNK; ch++) {
        if (ch <= NCHUNK-3)      { CP_ASYNC_WAIT(2); }
        else if (ch == NCHUNK-2) { CP_ASYNC_WAIT(1); }
        else                     { CP_ASYNC_WAIT(0); }
        __syncthreads();

        const __nv_bfloat16* B = &Bt[(ch % 3) * 64 * CSTR];
        unsigned bbase = smem_u32(B) + 2u * lmbase;

        float c[4][4];
        #pragma unroll
        for (int nn = 0; nn < 4; nn++)
            #pragma unroll
            for (int q = 0; q < 4; q++) c[nn][q] = 0.f;

        #pragma unroll
        for (int kk = 0; kk < 8; kk++) {
            #pragma unroll
            for (int q = 0; q < 2; q++) {
                unsigned x0, x1, x2, x3;
                ldsm4(x0, x1, x2, x3, bbase + 2u*(unsigned)(q*16*CSTR + kk*16));
                mma16816(c[2*q],     af[kk], x0, x1);
                mma16816(c[2*q + 1], af[kk], x2, x3);
            }
        }
        #pragma unroll
        for (int nn = 0; nn < 4; nn++) {
            unsigned long long XA = pk2(c[nn][0], c[nn][1]);
            unsigned long long XB = pk2(c[nn][2], c[nn][3]);
            unsigned long long rA = fma2(K5, XA, K4);
            unsigned long long rB = fma2(K5, XB, K4);
            rA = fma2(rA, XA, K3);  rB = fma2(rB, XB, K3);
            rA = fma2(rA, XA, K2);  rB = fma2(rB, XB, K2);
            rA = fma2(rA, XA, K1);  rB = fma2(rB, XB, K1);
            rA = fma2(rA, XA, K1);  rB = fma2(rB, XB, K1);
            sA2 = add2(sA2, rA);
            sB2 = add2(sB2, rB);
        }
        __syncthreads();

        // issue chunk ch+3 into the buffer just freed
        if (ch + 3 < NCHUNK) {
            int jt = j0 + (ch + 3) * 64;
            __nv_bfloat16* dbuf = &Bt[(ch % 3) * 64 * CSTR];
            for (int i = t; i < 1024; i += 256) {
                int row = i >> 4, seg = i & 15;
                int jj = jt + row;
                unsigned dst = smem_u32(&dbuf[row*CSTR + seg*8]);
                const __nv_bfloat16* src = &g_Pb[(size_t)min(jj, jlim-1)*NF + seg*8];
                int sz = (jj < jlim) ? 16 : 0;
                asm volatile("cp.async.cg.shared.global [%0], [%1], 16, %2;\n"
                             :: "r"(dst), "l"(src), "r"(sz));
            }
            CP_ASYNC_COMMIT();
        }
    }

    float aLo, aHi, bLo, bHi;
    unpk2(sA2, aLo, aHi);
    unpk2(sB2, bLo, bHi);
    float sumA = aLo + aHi, sumB = bLo + bHi;
    #pragma unroll
    for (int m = 1; m <= 2; m <<= 1) {
        sumA += __shfl_xor_sync(0xffffffffu, sumA, m);
        sumB += __shfl_xor_sync(0xffffffffu, sumB, m);
    }
    // cross-warp_n reduce + plain per-half store (no atomics, no init)
    __syncthreads();
    float* sred = (float*)sm;
    if (tt == 0) {
        sred[warp_n*64 + warp_m*16 + g]     = sumA;
        sred[warp_n*64 + warp_m*16 + g + 8] = sumB;
    }
    __syncthreads();
    if (t < 64) {
        int row = r0 + t;
        if (row < class_end)
            g_denomH[jh*NR + row] = sred[t] + sred[64 + t] - 48.0f;  // 48 zero-pad cols
    }
}

// ---------------- K7: final combine ----------------
__global__ void k_final(float* out) {
    int t = threadIdx.x;
    float s = 0.f;
    for (int i = t; i < NR; i += 256)
        s += logf(g_denomH[i] + g_denomH[NR + i]);
    float sm_ = 0.f;
    for (int i = t; i < 512; i += 256) sm_ += g_mseP[i];
    float sk = 0.f;
    for (int i = t; i < 500; i += 256) sk += g_smaskP[i];
    #pragma unroll
    for (int m = 16; m; m >>= 1) {
        s   += __shfl_xor_sync(0xffffffffu, s, m);
        sm_ += __shfl_xor_sync(0xffffffffu, sm_, m);
        sk  += __shfl_xor_sync(0xffffffffu, sk, m);
    }
    __shared__ float ws[8][3];
    if ((t & 31) == 0) { ws[t>>5][0] = s; ws[t>>5][1] = sm_; ws[t>>5][2] = sk; }
    __syncthreads();
    if (t == 0) {
        float lsum = 0.f, msum = 0.f, ksum = 0.f;
        #pragma unroll
        for (int w = 0; w < 8; w++) { lsum += ws[w][0]; msum += ws[w][1]; ksum += ws[w][2]; }
        float supcon = -ksum * (1.0f / NR) + lsum;
        float mse = msum * (1.0f / NMSE);
        out[0] = supcon + 0.5f * mse;
    }
}

extern "C" void kernel_launch(void* const* d_in, const int* in_sizes, int n_in,
                              void* d_out, int out_size) {
    const float* Zs  = (const float*)d_in[0];
    const int*   pos = (const int*)d_in[1];
    const int*   neg = (const int*)d_in[2];
    const float* fd  = (const float*)d_in[3];
    const float* id  = (const float*)d_in[4];
    float* out = (float*)d_out;

    static int smem_set = 0;
    int denom_smem = (64*CSTR + 3*64*CSTR) * (int)sizeof(__nv_bfloat16);
    if (!smem_set) {
        cudaFuncSetAttribute(k_denom, cudaFuncAttributeMaxDynamicSharedMemorySize, denom_smem);
        smem_set = 1;
    }

    k_front <<<1514, 256>>>(Zs, pos, neg, fd, id);
    k_MA    <<<NMP, 256>>>();
    k_Mred  <<<340, 256>>>();
    k_prep  <<<500, 128>>>();
    k_denom <<<252, 256, denom_smem>>>();
    k_final <<<1, 256>>>(out);
}

// round 11
// speedup vs baseline: 3.8917x; 1.0049x over previous
#include <cuda_runtime.h>
#include <cuda_bf16.h>
#include <math.h>
#include <stdint.h>

#define NR    8000
#define NPOS  4000
#define NF    128
#define NVOX  32768
#define NMSE  (128*32*32*32)
#define NMP   125          // k_MA split-K partial count (64 rows each)

// ---- scratch (static device globals; no allocations) ----
__device__ float          g_P[NR*NF];        // normalized pixels fp32
__device__ __nv_bfloat16  g_Pb[NR*NF];       // normalized pixels bf16 (B operand)
__device__ __nv_bfloat16  g_Ab[NR*NF];       // row-scaled pixels bf16 (A operand)
__device__ float          g_Mp[NMP*NF*NF];   // split-K partials of P^T P (8 MB)
__device__ float          g_M[NF*NF];        // P^T P      (atomic, zeroed in k_front)
__device__ float          g_S[2*NF];         // class col sums (atomic, zeroed in k_front)
__device__ float          g_Sp[1000*NF];     // per-gather-block column-sum partials
__device__ float          g_mseP[512];       // per-block mse partials (plain store)
__device__ float          g_smaskP[1000];    // per-block S_mask partials (plain store)
__device__ float          g_denomH[2*NR];    // per-column-half denom sums (plain store)

__device__ __forceinline__ unsigned smem_u32(const void* p) {
    return (unsigned)__cvta_generic_to_shared(p);
}
#define CP_ASYNC_COMMIT() asm volatile("cp.async.commit_group;\n" ::)
#define CP_ASYNC_WAIT(n)  asm volatile("cp.async.wait_group %0;\n" :: "n"(n))

// packed f32x2 helpers
__device__ __forceinline__ unsigned long long pk2(float lo, float hi) {
    unsigned long long v; asm("mov.b64 %0,{%1,%2};" : "=l"(v) : "f"(lo), "f"(hi)); return v;
}
__device__ __forceinline__ void unpk2(unsigned long long v, float& lo, float& hi) {
    asm("mov.b64 {%0,%1},%2;" : "=f"(lo), "=f"(hi) : "l"(v));
}
__device__ __forceinline__ unsigned long long fma2(unsigned long long a,
                                                   unsigned long long b,
                                                   unsigned long long c) {
    unsigned long long d;
    asm("fma.rn.f32x2 %0,%1,%2,%3;" : "=l"(d) : "l"(a), "l"(b), "l"(c));
    return d;
}
__device__ __forceinline__ unsigned long long add2(unsigned long long a,
                                                   unsigned long long b) {
    unsigned long long d;
    asm("add.rn.f32x2 %0,%1,%2;" : "=l"(d) : "l"(a), "l"(b));
    return d;
}

__device__ __forceinline__ void mma16816(float c[4], const unsigned a[4],
                                         unsigned b0, unsigned b1) {
    asm volatile(
        "mma.sync.aligned.m16n8k16.row.col.f32.bf16.bf16.f32 "
        "{%0,%1,%2,%3}, {%4,%5,%6,%7}, {%8,%9}, {%0,%1,%2,%3};"
        : "+f"(c[0]), "+f"(c[1]), "+f"(c[2]), "+f"(c[3])
        : "r"(a[0]), "r"(a[1]), "r"(a[2]), "r"(a[3]), "r"(b0), "r"(b1));
}
__device__ __forceinline__ void ldsm4(unsigned& x0, unsigned& x1,
                                      unsigned& x2, unsigned& x3, unsigned addr) {
    asm volatile("ldmatrix.sync.aligned.m8n8.x4.shared.b16 {%0,%1,%2,%3}, [%4];"
                 : "=r"(x0), "=r"(x1), "=r"(x2), "=r"(x3) : "r"(addr));
}

// ---------------- K1: fused front kernel ----------------
// blocks [0,1000): gather + L2-normalize 8 rows + column-sum partial
// blocks [1000,1512): MSE partials
// blocks 1512,1513: zero g_M / g_S for the atomic consumers downstream
__global__ void k_front(const float* __restrict__ Zs,
                        const int* __restrict__ pos,
                        const int* __restrict__ neg,
                        const float* __restrict__ fd,
                        const float* __restrict__ id) {
    __shared__ float smP[8][NF];
    int b = blockIdx.x, t = threadIdx.x;
    if (b < 1000) {
        int wid = t >> 5, lane = t & 31;
        int r = b * 8 + wid;
        int v = (r < NPOS) ? pos[r] : neg[r - NPOS];
        float x[4];
        #pragma unroll
        for (int k = 0; k < 4; k++) x[k] = Zs[(size_t)(lane + 32*k)*NVOX + v];
        float s = x[0]*x[0] + x[1]*x[1] + x[2]*x[2] + x[3]*x[3];
        #pragma unroll
        for (int m = 16; m; m >>= 1) s += __shfl_xor_sync(0xffffffffu, s, m);
        float inv = 1.0f / fmaxf(sqrtf(s), 1e-12f);
        #pragma unroll
        for (int k = 0; k < 4; k++) {
            float p = x[k] * inv;
            g_P [r*NF + lane + 32*k] = p;
            g_Pb[r*NF + lane + 32*k] = __float2bfloat16(p);
            smP[wid][lane + 32*k] = p;
        }
        __syncthreads();
        if (t < NF) {
            float cs = 0.f;
            #pragma unroll
            for (int w = 0; w < 8; w++) cs += smP[w][t];
            g_Sp[b*NF + t] = cs;
        }
    } else if (b < 1512) {
        int mb = b - 1000;
        int n4 = NMSE / 4;
        float s = 0.f;
        for (int i = mb*256 + t; i < n4; i += 512*256) {
            float4 a = ((const float4*)fd)[i];
            float4 c = ((const float4*)id)[i];
            float d0 = a.x-c.x, d1 = a.y-c.y, d2 = a.z-c.z, d3 = a.w-c.w;
            s += d0*d0 + d1*d1 + d2*d2 + d3*d3;
        }
        #pragma unroll
        for (int m = 16; m; m >>= 1) s += __shfl_xor_sync(0xffffffffu, s, m);
        __shared__ float ws[8];
        if ((t & 31) == 0) ws[t >> 5] = s;
        __syncthreads();
        if (t == 0) {
            float tot = 0.f;
            #pragma unroll
            for (int w = 0; w < 8; w++) tot += ws[w];
            g_mseP[mb] = tot;
        }
    } else {
        int half = b - 1512;                       // 0 or 1
        for (int i = t; i < 8192; i += 256) g_M[half*8192 + i] = 0.f;
        if (half == 1 && t < 2*NF) g_S[t] = 0.f;
    }
}

// ---------------- K2a: M = P^T P split-K partials via bf16 HMMA ----------------
// grid 125 (64 samples each), block 256 = 8 warps; warp w -> M rows 16w..16w+15
__global__ void __launch_bounds__(256) k_MA() {
    __shared__ unsigned short spT[128][72];  // transposed tile: [feat][sample]
    int t = threadIdx.x, wid = t >> 5, lane = t & 31;
    int r0 = blockIdx.x * 64;

    // load 64x128 bf16, transpose into spT
    for (int i = t; i < 1024; i += 256) {
        int r = i >> 4, seg = i & 15;
        uint4 v = ((const uint4*)&g_Pb[(size_t)(r0+r)*NF])[seg];
        unsigned w0 = v.x, w1 = v.y, w2 = v.z, w3 = v.w;
        int f = seg * 8;
        spT[f+0][r] = (unsigned short)(w0 & 0xffffu);
        spT[f+1][r] = (unsigned short)(w0 >> 16);
        spT[f+2][r] = (unsigned short)(w1 & 0xffffu);
        spT[f+3][r] = (unsigned short)(w1 >> 16);
        spT[f+4][r] = (unsigned short)(w2 & 0xffffu);
        spT[f+5][r] = (unsigned short)(w2 >> 16);
        spT[f+6][r] = (unsigned short)(w3 & 0xffffu);
        spT[f+7][r] = (unsigned short)(w3 >> 16);
    }
    __syncthreads();

    int i0 = wid * 16;
    int lm = lane >> 3, lr = lane & 7;
    unsigned base = smem_u32(&spT[0][0]);
    // A frags: a0=(rows0-7,k0-7) a1=(rows8-15,k0-7) a2=(rows0-7,k8-15) a3=(rows8-15,k8-15)
    unsigned aAddr0 = base + (unsigned)(((i0 + (lm & 1)*8 + lr) * 72 + (lm >> 1)*8) << 1);
    // B frags: x0/x1 = n-rows0-7 two k-halves; x2/x3 = n-rows8-15
    unsigned bRowOff = (unsigned)((((lm >> 1)*8 + lr) * 72 + (lm & 1)*8) << 1);

    float c[16][4];
    #pragma unroll
    for (int nn = 0; nn < 16; nn++)
        #pragma unroll
        for (int q = 0; q < 4; q++) c[nn][q] = 0.f;

    #pragma unroll
    for (int kk = 0; kk < 4; kk++) {
        unsigned af[4];
        ldsm4(af[0], af[1], af[2], af[3], aAddr0 + kk*32);
        #pragma unroll
        for (int q = 0; q < 8; q++) {
            unsigned x0, x1, x2, x3;
            unsigned addr = base + (unsigned)((q*16*72) << 1) + bRowOff + kk*32;
            ldsm4(x0, x1, x2, x3, addr);
            mma16816(c[2*q],     af, x0, x1);
            mma16816(c[2*q + 1], af, x2, x3);
        }
    }

    float* dst = &g_Mp[(size_t)blockIdx.x * NF * NF];
    int g = lane >> 2, tt = lane & 3;
    #pragma unroll
    for (int nn = 0; nn < 16; nn++) {
        int col = nn*8 + 2*tt;
        *(float2*)&dst[(i0+g  )*NF + col] = make_float2(c[nn][0], c[nn][1]);
        *(float2*)&dst[(i0+g+8)*NF + col] = make_float2(c[nn][2], c[nn][3]);
    }
}

// ---------------- K2b: reduce M partials + S partials ----------------
// grid 340: [0,320) = 64 element-chunks x 5 partial-chunks (25 each) -> atomic g_M
//           [320,340) = 2 classes x 10 chunks (50 gather-blocks each) -> atomic g_S
__global__ void k_Mred() {
    int b = blockIdx.x, t = threadIdx.x;
    if (b < 320) {
        int e = (b & 63) * 256 + t;
        int p0 = (b >> 6) * 25;
        float s = 0.f;
        #pragma unroll 25
        for (int p = p0; p < p0 + 25; p++) s += g_Mp[(size_t)p*NF*NF + e];
        atomicAdd(&g_M[e], s);
    } else if (t < NF) {
        int idx = b - 320;
        int cls = idx & 1, chunk = idx >> 1;
        int b0 = cls * 500 + chunk * 50;
        float s = 0.f;
        #pragma unroll 10
        for (int k = 0; k < 50; k++) s += g_Sp[(b0 + k)*NF + t];
        atomicAdd(&g_S[cls*NF + t], s);
    }
}

// ---------------- K4: per-row qf, S_mask partial, scaled A ----------------
// grid 1000 (8 rows each), block 128; packed f32x2 inner products
__global__ void k_prep() {
    __shared__ float sp[8][NF];
    __shared__ float smQ[8][4], smS[8][4], smR[8], smC[8];
    int f = threadIdx.x;
    int r0 = blockIdx.x * 8;
    for (int r = 0; r < 8; r++) sp[r][f] = g_P[(r0+r)*NF + f];
    __syncthreads();
    unsigned long long in2[8];
    #pragma unroll
    for (int r = 0; r < 8; r++) in2[r] = 0ull;
    #pragma unroll 4
    for (int l = 0; l < NF; l += 4) {
        // coalesced: at fixed l, lanes read consecutive f (M symmetric)
        float m0 = g_M[(l+0)*NF + f];
        float m1 = g_M[(l+1)*NF + f];
        float m2 = g_M[(l+2)*NF + f];
        float m3 = g_M[(l+3)*NF + f];
        unsigned long long m01 = pk2(m0, m1);
        unsigned long long m23 = pk2(m2, m3);
        #pragma unroll
        for (int r = 0; r < 8; r++) {
            float4 s4 = *(const float4*)&sp[r][l];   // one LDS.128 broadcast
            in2[r] = fma2(m01, pk2(s4.x, s4.y), in2[r]);
            in2[r] = fma2(m23, pk2(s4.z, s4.w), in2[r]);
        }
    }
    int sb = (r0 < NPOS) ? 0 : NF;
    float sf = g_S[sb + f];
    int lane = f & 31, w = f >> 5;
    #pragma unroll
    for (int r = 0; r < 8; r++) {
        float lo, hi;
        unpk2(in2[r], lo, hi);
        float q = (lo + hi) * sp[r][f];
        float s = sf * sp[r][f];
        #pragma unroll
        for (int m = 16; m; m >>= 1) {
            q += __shfl_xor_sync(0xffffffffu, q, m);
            s += __shfl_xor_sync(0xffffffffu, s, m);
        }
        if (lane == 0) { smQ[r][w] = q; smS[r][w] = s; }
    }
    __syncthreads();
    if (f < 8) {
        int r = f;
        float qf = smQ[r][0] + smQ[r][1] + smQ[r][2] + smQ[r][3];
        float ps = smS[r][0] + smS[r][1] + smS[r][2] + smS[r][3];
        float rinv = rsqrtf(qf);
        rinv = rinv * (1.5f - 0.5f * qf * rinv * rinv);
        smR[r] = rinv;
        smC[r] = (ps - 1.0f) * rinv;
    }
    __syncthreads();
    if (f == 0) {
        float c = 0.f;
        #pragma unroll
        for (int r = 0; r < 8; r++) c += smC[r];
        g_smaskP[blockIdx.x] = c;
    }
    for (int r = 0; r < 8; r++)
        g_Ab[(r0+r)*NF + f] = __float2bfloat16(sp[r][f] * smR[r]);
}

// ---------------- K5: fused bf16 GEMM + packed poly-exp + row reduce ----------------
#define CSTR   136         // padded smem stride in bf16
#define NCHUNK 32          // 32 x 64 = 2048 >= 2000 cols

// grid 252: 126 row tiles (64 rows, class-aligned w/ zero-pad) x 2 column halves
// 2 blocks/SM -> single wave
__global__ void __launch_bounds__(256, 2) k_denom() {
    extern __shared__ __nv_bfloat16 sm[];
    __nv_bfloat16* At = sm;                  // 64 x CSTR
    __nv_bfloat16* Bt = sm + 64*CSTR;        // 3 x 64 x CSTR (triple buffer)

    int bid = blockIdx.x;
    int tileR = bid >> 1, jh = bid & 1;
    int r0, class_end, j0;
    if (tileR < 63) { r0 = tileR * 64;              class_end = NPOS; j0 = NPOS; }
    else            { r0 = NPOS + (tileR - 63)*64;  class_end = NR;   j0 = 0;    }
    j0 += jh * 2000;
    int jlim = j0 + 2000;

    int t = threadIdx.x;
    int wid = t >> 5, lane = t & 31;
    int g = lane >> 2, tt = lane & 3;
    int warp_m = wid & 3, warp_n = wid >> 2;

    // prologue: prefetch chunks 0,1,2 (64 rows each)
    #pragma unroll
    for (int ch = 0; ch < 3; ch++) {
        __nv_bfloat16* dbuf = &Bt[ch * 64 * CSTR];
        for (int i = t; i < 1024; i += 256) {
            int row = i >> 4, seg = i & 15;
            int jj = j0 + ch*64 + row;
            unsigned dst = smem_u32(&dbuf[row*CSTR + seg*8]);
            const __nv_bfloat16* src = &g_Pb[(size_t)min(jj, jlim-1)*NF + seg*8];
            int sz = (jj < jlim) ? 16 : 0;
            asm volatile("cp.async.cg.shared.global [%0], [%1], 16, %2;\n"
                         :: "r"(dst), "l"(src), "r"(sz));
        }
        CP_ASYNC_COMMIT();
    }

    // A tile: 64 rows x 128 bf16, zero rows beyond class_end
    for (int i = t; i < 1024; i += 256) {
        int row = i >> 4, seg = i & 15;
        int jj = r0 + row;
        uint4 v = make_uint4(0u,0u,0u,0u);
        if (jj < class_end) v = ((const uint4*)&g_Ab[(size_t)jj*NF])[seg];
        *(uint4*)&At[row*CSTR + seg*8] = v;
    }
    __syncthreads();

    // A fragments (reused across all chunks)
    unsigned af[8][4];
    int ar = warp_m * 16 + g;
    #pragma unroll
    for (int kk = 0; kk < 8; kk++) {
        af[kk][0] = *(const unsigned*)&At[ ar    *CSTR + kk*16     + 2*tt];
        af[kk][1] = *(const unsigned*)&At[(ar+8)*CSTR + kk*16     + 2*tt];
        af[kk][2] = *(const unsigned*)&At[ ar    *CSTR + kk*16 + 8 + 2*tt];
        af[kk][3] = *(const unsigned*)&At[(ar+8)*CSTR + kk*16 + 8 + 2*tt];
    }

    // ldmatrix B row base within a 64-col chunk (warp_n owns 32 cols)
    int lm = lane >> 3, lr = lane & 7;
    unsigned lmbase = (unsigned)((warp_n*32 + (lm>>1)*8 + lr) * CSTR + (lm&1)*8);

    const unsigned long long K5 = pk2(1.f/120.f, 1.f/120.f);
    const unsigned long long K4 = pk2(1.f/24.f,  1.f/24.f);
    const unsigned long long K3 = pk2(1.f/6.f,   1.f/6.f);
    const unsigned long long K2 = pk2(0.5f,      0.5f);
    const unsigned long long K1 = pk2(1.f,       1.f);

    unsigned long long sA2 = pk2(0.f, 0.f), sB2 = pk2(0.f, 0.f);

    for (int ch = 0; ch < NCHUNK; ch++) {
        if (ch <= NCHUNK-3)      { CP_ASYNC_WAIT(2); }
        else if (ch == NCHUNK-2) { CP_ASYNC_WAIT(1); }
        else                     { CP_ASYNC_WAIT(0); }
        __syncthreads();

        const __nv_bfloat16* B = &Bt[(ch % 3) * 64 * CSTR];
        unsigned bbase = smem_u32(B) + 2u * lmbase;

        float c[4][4];
        #pragma unroll
        for (int nn = 0; nn < 4; nn++)
            #pragma unroll
            for (int q = 0; q < 4; q++) c[nn][q] = 0.f;

        #pragma unroll
        for (int kk = 0; kk < 8; kk++) {
            #pragma unroll
            for (int q = 0; q < 2; q++) {
                unsigned x0, x1, x2, x3;
                ldsm4(x0, x1, x2, x3, bbase + 2u*(unsigned)(q*16*CSTR + kk*16));
                mma16816(c[2*q],     af[kk], x0, x1);
                mma16816(c[2*q + 1], af[kk], x2, x3);
            }
        }
        #pragma unroll
        for (int nn = 0; nn < 4; nn++) {
            unsigned long long XA = pk2(c[nn][0], c[nn][1]);
            unsigned long long XB = pk2(c[nn][2], c[nn][3]);
            unsigned long long rA = fma2(K5, XA, K4);
            unsigned long long rB = fma2(K5, XB, K4);
            rA = fma2(rA, XA, K3);  rB = fma2(rB, XB, K3);
            rA = fma2(rA, XA, K2);  rB = fma2(rB, XB, K2);
            rA = fma2(rA, XA, K1);  rB = fma2(rB, XB, K1);
            rA = fma2(rA, XA, K1);  rB = fma2(rB, XB, K1);
            sA2 = add2(sA2, rA);
            sB2 = add2(sB2, rB);
        }
        __syncthreads();

        // issue chunk ch+3 into the buffer just freed
        if (ch + 3 < NCHUNK) {
            int jt = j0 + (ch + 3) * 64;
            __nv_bfloat16* dbuf = &Bt[(ch % 3) * 64 * CSTR];
            for (int i = t; i < 1024; i += 256) {
                int row = i >> 4, seg = i & 15;
                int jj = jt + row;
                unsigned dst = smem_u32(&dbuf[row*CSTR + seg*8]);
                const __nv_bfloat16* src = &g_Pb[(size_t)min(jj, jlim-1)*NF + seg*8];
                int sz = (jj < jlim) ? 16 : 0;
                asm volatile("cp.async.cg.shared.global [%0], [%1], 16, %2;\n"
                             :: "r"(dst), "l"(src), "r"(sz));
            }
            CP_ASYNC_COMMIT();
        }
    }

    float aLo, aHi, bLo, bHi;
    unpk2(sA2, aLo, aHi);
    unpk2(sB2, bLo, bHi);
    float sumA = aLo + aHi, sumB = bLo + bHi;
    #pragma unroll
    for (int m = 1; m <= 2; m <<= 1) {
        sumA += __shfl_xor_sync(0xffffffffu, sumA, m);
        sumB += __shfl_xor_sync(0xffffffffu, sumB, m);
    }
    // cross-warp_n reduce + plain per-half store (no atomics, no init)
    __syncthreads();
    float* sred = (float*)sm;
    if (tt == 0) {
        sred[warp_n*64 + warp_m*16 + g]     = sumA;
        sred[warp_n*64 + warp_m*16 + g + 8] = sumB;
    }
    __syncthreads();
    if (t < 64) {
        int row = r0 + t;
        if (row < class_end)
            g_denomH[jh*NR + row] = sred[t] + sred[64 + t] - 48.0f;  // 48 zero-pad cols
    }
}

// ---------------- K7: final combine ----------------
__global__ void k_final(float* out) {
    int t = threadIdx.x;
    float s = 0.f;
    for (int i = t; i < NR; i += 256)
        s += logf(g_denomH[i] + g_denomH[NR + i]);
    float sm_ = 0.f;
    for (int i = t; i < 512; i += 256) sm_ += g_mseP[i];
    float sk = 0.f;
    for (int i = t; i < 1000; i += 256) sk += g_smaskP[i];
    #pragma unroll
    for (int m = 16; m; m >>= 1) {
        s   += __shfl_xor_sync(0xffffffffu, s, m);
        sm_ += __shfl_xor_sync(0xffffffffu, sm_, m);
        sk  += __shfl_xor_sync(0xffffffffu, sk, m);
    }
    __shared__ float ws[8][3];
    if ((t & 31) == 0) { ws[t>>5][0] = s; ws[t>>5][1] = sm_; ws[t>>5][2] = sk; }
    __syncthreads();
    if (t == 0) {
        float lsum = 0.f, msum = 0.f, ksum = 0.f;
        #pragma unroll
        for (int w = 0; w < 8; w++) { lsum += ws[w][0]; msum += ws[w][1]; ksum += ws[w][2]; }
        float supcon = -ksum * (1.0f / NR) + lsum;
        float mse = msum * (1.0f / NMSE);
        out[0] = supcon + 0.5f * mse;
    }
}

extern "C" void kernel_launch(void* const* d_in, const int* in_sizes, int n_in,
                              void* d_out, int out_size) {
    const float* Zs  = (const float*)d_in[0];
    const int*   pos = (const int*)d_in[1];
    const int*   neg = (const int*)d_in[2];
    const float* fd  = (const float*)d_in[3];
    const float* id  = (const float*)d_in[4];
    float* out = (float*)d_out;

    static int smem_set = 0;
    int denom_smem = (64*CSTR + 3*64*CSTR) * (int)sizeof(__nv_bfloat16);
    if (!smem_set) {
        cudaFuncSetAttribute(k_denom, cudaFuncAttributeMaxDynamicSharedMemorySize, denom_smem);
        smem_set = 1;
    }

    k_front <<<1514, 256>>>(Zs, pos, neg, fd, id);
    k_MA    <<<NMP, 256>>>();
    k_Mred  <<<340, 256>>>();
    k_prep  <<<1000, 128>>>();
    k_denom <<<252, 256, denom_smem>>>();
    k_final <<<1, 256>>>(out);
}

// round 12
// speedup vs baseline: 4.3565x; 1.1194x over previous
#include <cuda_runtime.h>
#include <cuda_bf16.h>
#include <math.h>
#include <stdint.h>

#define NR    8000
#define NPOS  4000
#define NF    128
#define NVOX  32768
#define NMSE  (128*32*32*32)
#define NMP   125          // k_MA split-K partial count (64 rows each)

// ---- scratch (static device globals; no allocations) ----
__device__ __nv_bfloat16  g_Pb[NR*NF];       // normalized pixels bf16
__device__ __nv_bfloat16  g_Ab[NR*NF];       // row-scaled pixels bf16 (A operand)
__device__ float          g_Mp[NMP*NF*NF];   // split-K partials of P^T P (8 MB)
__device__ __nv_bfloat16  g_Mb[NF*NF];       // P^T P in bf16 (plain store from k_Mred)
__device__ float          g_S[2*NF];         // class col sums (atomic, zeroed in k_front)
__device__ float          g_Sp[1000*NF];     // per-gather-block column-sum partials
__device__ float          g_mseP[512];       // per-block mse partials (plain store)
__device__ float          g_smaskP[128];     // per-block S_mask partials (plain store)
__device__ float          g_denomH[2*NR];    // per-column-half denom sums (plain store)

__device__ __forceinline__ unsigned smem_u32(const void* p) {
    return (unsigned)__cvta_generic_to_shared(p);
}
#define CP_ASYNC_COMMIT() asm volatile("cp.async.commit_group;\n" ::)
#define CP_ASYNC_WAIT(n)  asm volatile("cp.async.wait_group %0;\n" :: "n"(n))

// packed f32x2 helpers
__device__ __forceinline__ unsigned long long pk2(float lo, float hi) {
    unsigned long long v; asm("mov.b64 %0,{%1,%2};" : "=l"(v) : "f"(lo), "f"(hi)); return v;
}
__device__ __forceinline__ void unpk2(unsigned long long v, float& lo, float& hi) {
    asm("mov.b64 {%0,%1},%2;" : "=f"(lo), "=f"(hi) : "l"(v));
}
__device__ __forceinline__ unsigned long long fma2(unsigned long long a,
                                                   unsigned long long b,
                                                   unsigned long long c) {
    unsigned long long d;
    asm("fma.rn.f32x2 %0,%1,%2,%3;" : "=l"(d) : "l"(a), "l"(b), "l"(c));
    return d;
}
__device__ __forceinline__ unsigned long long add2(unsigned long long a,
                                                   unsigned long long b) {
    unsigned long long d;
    asm("add.rn.f32x2 %0,%1,%2;" : "=l"(d) : "l"(a), "l"(b));
    return d;
}

__device__ __forceinline__ void mma16816(float c[4], const unsigned a[4],
                                         unsigned b0, unsigned b1) {
    asm volatile(
        "mma.sync.aligned.m16n8k16.row.col.f32.bf16.bf16.f32 "
        "{%0,%1,%2,%3}, {%4,%5,%6,%7}, {%8,%9}, {%0,%1,%2,%3};"
        : "+f"(c[0]), "+f"(c[1]), "+f"(c[2]), "+f"(c[3])
        : "r"(a[0]), "r"(a[1]), "r"(a[2]), "r"(a[3]), "r"(b0), "r"(b1));
}
__device__ __forceinline__ void ldsm4(unsigned& x0, unsigned& x1,
                                      unsigned& x2, unsigned& x3, unsigned addr) {
    asm volatile("ldmatrix.sync.aligned.m8n8.x4.shared.b16 {%0,%1,%2,%3}, [%4];"
                 : "=r"(x0), "=r"(x1), "=r"(x2), "=r"(x3) : "r"(addr));
}

// ---------------- K1: fused front kernel ----------------
// blocks [0,1000): gather + L2-normalize 8 rows + column-sum partial
// blocks [1000,1512): MSE partials;  block 1512: zero g_S
__global__ void k_front(const float* __restrict__ Zs,
                        const int* __restrict__ pos,
                        const int* __restrict__ neg,
                        const float* __restrict__ fd,
                        const float* __restrict__ id) {
    __shared__ float smP[8][NF];
    int b = blockIdx.x, t = threadIdx.x;
    if (b < 1000) {
        int wid = t >> 5, lane = t & 31;
        int r = b * 8 + wid;
        int v = (r < NPOS) ? pos[r] : neg[r - NPOS];
        float x[4];
        #pragma unroll
        for (int k = 0; k < 4; k++) x[k] = Zs[(size_t)(lane + 32*k)*NVOX + v];
        float s = x[0]*x[0] + x[1]*x[1] + x[2]*x[2] + x[3]*x[3];
        #pragma unroll
        for (int m = 16; m; m >>= 1) s += __shfl_xor_sync(0xffffffffu, s, m);
        float inv = 1.0f / fmaxf(sqrtf(s), 1e-12f);
        #pragma unroll
        for (int k = 0; k < 4; k++) {
            float p = x[k] * inv;
            g_Pb[r*NF + lane + 32*k] = __float2bfloat16(p);
            smP[wid][lane + 32*k] = p;
        }
        __syncthreads();
        if (t < NF) {
            float cs = 0.f;
            #pragma unroll
            for (int w = 0; w < 8; w++) cs += smP[w][t];
            g_Sp[b*NF + t] = cs;
        }
    } else if (b < 1512) {
        int mb = b - 1000;
        int n4 = NMSE / 4;
        float s = 0.f;
        for (int i = mb*256 + t; i < n4; i += 512*256) {
            float4 a = ((const float4*)fd)[i];
            float4 c = ((const float4*)id)[i];
            float d0 = a.x-c.x, d1 = a.y-c.y, d2 = a.z-c.z, d3 = a.w-c.w;
            s += d0*d0 + d1*d1 + d2*d2 + d3*d3;
        }
        #pragma unroll
        for (int m = 16; m; m >>= 1) s += __shfl_xor_sync(0xffffffffu, s, m);
        __shared__ float ws[8];
        if ((t & 31) == 0) ws[t >> 5] = s;
        __syncthreads();
        if (t == 0) {
            float tot = 0.f;
            #pragma unroll
            for (int w = 0; w < 8; w++) tot += ws[w];
            g_mseP[mb] = tot;
        }
    } else {
        if (t < 2*NF) g_S[t] = 0.f;
    }
}

// ---------------- K2a: M = P^T P split-K partials via bf16 HMMA ----------------
// grid 125 (64 samples each), block 256 = 8 warps; warp w -> M rows 16w..16w+15
__global__ void __launch_bounds__(256) k_MA() {
    __shared__ unsigned short spT[128][72];  // transposed tile: [feat][sample]
    int t = threadIdx.x, wid = t >> 5, lane = t & 31;
    int r0 = blockIdx.x * 64;

    // load 64x128 bf16, transpose into spT
    for (int i = t; i < 1024; i += 256) {
        int r = i >> 4, seg = i & 15;
        uint4 v = ((const uint4*)&g_Pb[(size_t)(r0+r)*NF])[seg];
        unsigned w0 = v.x, w1 = v.y, w2 = v.z, w3 = v.w;
        int f = seg * 8;
        spT[f+0][r] = (unsigned short)(w0 & 0xffffu);
        spT[f+1][r] = (unsigned short)(w0 >> 16);
        spT[f+2][r] = (unsigned short)(w1 & 0xffffu);
        spT[f+3][r] = (unsigned short)(w1 >> 16);
        spT[f+4][r] = (unsigned short)(w2 & 0xffffu);
        spT[f+5][r] = (unsigned short)(w2 >> 16);
        spT[f+6][r] = (unsigned short)(w3 & 0xffffu);
        spT[f+7][r] = (unsigned short)(w3 >> 16);
    }
    __syncthreads();

    int i0 = wid * 16;
    int lm = lane >> 3, lr = lane & 7;
    unsigned base = smem_u32(&spT[0][0]);
    unsigned aAddr0 = base + (unsigned)(((i0 + (lm & 1)*8 + lr) * 72 + (lm >> 1)*8) << 1);
    unsigned bRowOff = (unsigned)((((lm >> 1)*8 + lr) * 72 + (lm & 1)*8) << 1);

    float c[16][4];
    #pragma unroll
    for (int nn = 0; nn < 16; nn++)
        #pragma unroll
        for (int q = 0; q < 4; q++) c[nn][q] = 0.f;

    #pragma unroll
    for (int kk = 0; kk < 4; kk++) {
        unsigned af[4];
        ldsm4(af[0], af[1], af[2], af[3], aAddr0 + kk*32);
        #pragma unroll
        for (int q = 0; q < 8; q++) {
            unsigned x0, x1, x2, x3;
            unsigned addr = base + (unsigned)((q*16*72) << 1) + bRowOff + kk*32;
            ldsm4(x0, x1, x2, x3, addr);
            mma16816(c[2*q],     af, x0, x1);
            mma16816(c[2*q + 1], af, x2, x3);
        }
    }

    float* dst = &g_Mp[(size_t)blockIdx.x * NF * NF];
    int g = lane >> 2, tt = lane & 3;
    #pragma unroll
    for (int nn = 0; nn < 16; nn++) {
        int col = nn*8 + 2*tt;
        *(float2*)&dst[(i0+g  )*NF + col] = make_float2(c[nn][0], c[nn][1]);
        *(float2*)&dst[(i0+g+8)*NF + col] = make_float2(c[nn][2], c[nn][3]);
    }
}

// ---------------- K2b: reduce M partials (-> bf16 M) + S partials ----------------
// grid 276: [0,256) = 64-element chunks, 4 partial-groups per block -> g_Mb
//           [256,276) = 2 classes x 10 chunks (50 gather-blocks each) -> atomic g_S
__global__ void k_Mred() {
    int b = blockIdx.x, t = threadIdx.x;
    if (b < 256) {
        __shared__ float red[4][64];
        int gp = t >> 6, e = t & 63;
        int base = b * 64;
        int p0 = gp * 32, pc = (gp == 3) ? 29 : 32;
        float s = 0.f;
        for (int p = p0; p < p0 + pc; p++) s += g_Mp[(size_t)p*NF*NF + base + e];
        red[gp][e] = s;
        __syncthreads();
        if (t < 64)
            g_Mb[base + t] = __float2bfloat16(red[0][t] + red[1][t] + red[2][t] + red[3][t]);
    } else if (t < NF) {
        int idx = b - 256;
        int cls = idx & 1, chunk = idx >> 1;
        int b0 = cls * 500 + chunk * 50;
        float s = 0.f;
        #pragma unroll 10
        for (int k = 0; k < 50; k++) s += g_Sp[(b0 + k)*NF + t];
        atomicAdd(&g_S[cls*NF + t], s);
    }
}

// ---------------- K4: HMMA prep: Y = P*M, qf/ps epilogue, scaled A ----------------
// grid 125 (64 rows each), block 256 = 8 warps (warp_m 0..3, warp_n 0..1)
// M symmetric: B[n][k] = M[n][k] (row-major M tile, K-major frags -- same as k_denom B)
#define PSTR 136
#define MSTR 136
__global__ void __launch_bounds__(256) k_prep() {
    extern __shared__ __nv_bfloat16 dsm[];
    __nv_bfloat16* Pt = dsm;                          // 64 x PSTR
    __nv_bfloat16* Mt = dsm + 64*PSTR;                // 128 x MSTR
    float* fb   = (float*)(dsm + 64*PSTR + 128*MSTR);
    float* Ssm0 = fb;                                  // [128]
    float* Ssm1 = fb + 128;                            // [128]
    float* qsm  = fb + 256;                            // [2][64]
    float* psm  = fb + 384;                            // [2][64]
    float* rsm  = fb + 512;                            // [64]
    float* wsum = fb + 576;                            // [2]

    int t = threadIdx.x, wid = t >> 5, lane = t & 31;
    int g = lane >> 2, tt = lane & 3;
    int warp_m = wid & 3, warp_n = wid >> 2;
    int r0 = blockIdx.x * 64;

    {
        const uint4* srcP = (const uint4*)&g_Pb[(size_t)r0*NF];
        for (int i = t; i < 1024; i += 256) {
            int row = i >> 4, seg = i & 15;
            *(uint4*)&Pt[row*PSTR + seg*8] = srcP[i];
        }
        const uint4* srcM = (const uint4*)g_Mb;
        for (int i = t; i < 2048; i += 256) {
            int row = i >> 4, seg = i & 15;
            *(uint4*)&Mt[row*MSTR + seg*8] = srcM[i];
        }
        if (t < NF) { Ssm0[t] = g_S[t]; Ssm1[t] = g_S[NF + t]; }
    }
    __syncthreads();

    // A fragments (rows of P) -- same pattern as k_denom A-tile
    unsigned af[8][4];
    int ar = warp_m * 16 + g;
    #pragma unroll
    for (int kk = 0; kk < 8; kk++) {
        af[kk][0] = *(const unsigned*)&Pt[ ar    *PSTR + kk*16     + 2*tt];
        af[kk][1] = *(const unsigned*)&Pt[(ar+8)*PSTR + kk*16     + 2*tt];
        af[kk][2] = *(const unsigned*)&Pt[ ar    *PSTR + kk*16 + 8 + 2*tt];
        af[kk][3] = *(const unsigned*)&Pt[(ar+8)*PSTR + kk*16 + 8 + 2*tt];
    }

    int lm = lane >> 3, lr = lane & 7;
    unsigned bbase = smem_u32(Mt)
                   + 2u*(unsigned)((warp_n*64 + (lm>>1)*8 + lr)*MSTR + (lm&1)*8);

    float c[8][4];
    #pragma unroll
    for (int nn = 0; nn < 8; nn++)
        #pragma unroll
        for (int q = 0; q < 4; q++) c[nn][q] = 0.f;

    #pragma unroll
    for (int kk = 0; kk < 8; kk++) {
        #pragma unroll
        for (int q = 0; q < 4; q++) {
            unsigned x0, x1, x2, x3;
            ldsm4(x0, x1, x2, x3, bbase + 2u*(unsigned)(q*16*MSTR + kk*16));
            mma16816(c[2*q],     af[kk], x0, x1);
            mma16816(c[2*q + 1], af[kk], x2, x3);
        }
    }

    // epilogue: qf and ps partials
    int RA = r0 + ar;
    const float* SA = (RA     < NPOS) ? Ssm0 : Ssm1;
    const float* SB = (RA + 8 < NPOS) ? Ssm0 : Ssm1;
    float qA = 0.f, qB = 0.f, pA = 0.f, pB = 0.f;
    #pragma unroll
    for (int nn = 0; nn < 8; nn++) {
        int col = warp_n*64 + nn*8 + 2*tt;
        float2 pa = __bfloat1622float2(*(__nv_bfloat162*)&Pt[ ar    *PSTR + col]);
        float2 pb = __bfloat1622float2(*(__nv_bfloat162*)&Pt[(ar+8)*PSTR + col]);
        qA += c[nn][0]*pa.x + c[nn][1]*pa.y;
        qB += c[nn][2]*pb.x + c[nn][3]*pb.y;
        float2 sa = *(const float2*)&SA[col];
        float2 sb = *(const float2*)&SB[col];
        pA += sa.x*pa.x + sa.y*pa.y;
        pB += sb.x*pb.x + sb.y*pb.y;
    }
    #pragma unroll
    for (int m = 1; m <= 2; m <<= 1) {
        qA += __shfl_xor_sync(0xffffffffu, qA, m);
        qB += __shfl_xor_sync(0xffffffffu, qB, m);
        pA += __shfl_xor_sync(0xffffffffu, pA, m);
        pB += __shfl_xor_sync(0xffffffffu, pB, m);
    }
    if (tt == 0) {
        qsm[warp_n*64 + ar]     = qA;
        qsm[warp_n*64 + ar + 8] = qB;
        psm[warp_n*64 + ar]     = pA;
        psm[warp_n*64 + ar + 8] = pB;
    }
    __syncthreads();

    if (t < 64) {
        float qf = qsm[t] + qsm[64 + t];
        float ps = psm[t] + psm[64 + t];
        float rinv = rsqrtf(qf);
        rinv = rinv * (1.5f - 0.5f * qf * rinv * rinv);
        rsm[t] = rinv;
        float cval = (ps - 1.0f) * rinv;
        #pragma unroll
        for (int m = 16; m; m >>= 1) cval += __shfl_xor_sync(0xffffffffu, cval, m);
        if (lane == 0) wsum[wid] = cval;
    }
    __syncthreads();
    if (t == 0) g_smaskP[blockIdx.x] = wsum[0] + wsum[1];

    // Ab = bf16(P * rinv)
    #pragma unroll
    for (int i = 0; i < 8; i++) {
        int idx4 = t + 256*i;            // 2048 groups of 4 bf16
        int row = idx4 >> 5, c4 = (idx4 & 31) * 4;
        float rv = rsm[row];
        float2 f0 = __bfloat1622float2(*(__nv_bfloat162*)&Pt[row*PSTR + c4]);
        float2 f1 = __bfloat1622float2(*(__nv_bfloat162*)&Pt[row*PSTR + c4 + 2]);
        __nv_bfloat162 y0 = __floats2bfloat162_rn(f0.x*rv, f0.y*rv);
        __nv_bfloat162 y1 = __floats2bfloat162_rn(f1.x*rv, f1.y*rv);
        *(uint2*)&g_Ab[(size_t)(r0+row)*NF + c4] =
            make_uint2(*(unsigned*)&y0, *(unsigned*)&y1);
    }
}

// ---------------- K5: fused bf16 GEMM + packed poly-exp + row reduce ----------------
#define CSTR   136         // padded smem stride in bf16
#define NCHUNK 32          // 32 x 64 = 2048 >= 2000 cols

// grid 252: 126 row tiles (64 rows, class-aligned w/ zero-pad) x 2 column halves
__global__ void __launch_bounds__(256, 2) k_denom() {
    extern __shared__ __nv_bfloat16 sm[];
    __nv_bfloat16* At = sm;                  // 64 x CSTR
    __nv_bfloat16* Bt = sm + 64*CSTR;        // 3 x 64 x CSTR (triple buffer)

    int bid = blockIdx.x;
    int tileR = bid >> 1, jh = bid & 1;
    int r0, class_end, j0;
    if (tileR < 63) { r0 = tileR * 64;              class_end = NPOS; j0 = NPOS; }
    else            { r0 = NPOS + (tileR - 63)*64;  class_end = NR;   j0 = 0;    }
    j0 += jh * 2000;
    int jlim = j0 + 2000;

    int t = threadIdx.x;
    int wid = t >> 5, lane = t & 31;
    int g = lane >> 2, tt = lane & 3;
    int warp_m = wid & 3, warp_n = wid >> 2;

    #pragma unroll
    for (int ch = 0; ch < 3; ch++) {
        __nv_bfloat16* dbuf = &Bt[ch * 64 * CSTR];
        for (int i = t; i < 1024; i += 256) {
            int row = i >> 4, seg = i & 15;
            int jj = j0 + ch*64 + row;
            unsigned dst = smem_u32(&dbuf[row*CSTR + seg*8]);
            const __nv_bfloat16* src = &g_Pb[(size_t)min(jj, jlim-1)*NF + seg*8];
            int sz = (jj < jlim) ? 16 : 0;
            asm volatile("cp.async.cg.shared.global [%0], [%1], 16, %2;\n"
                         :: "r"(dst), "l"(src), "r"(sz));
        }
        CP_ASYNC_COMMIT();
    }

    for (int i = t; i < 1024; i += 256) {
        int row = i >> 4, seg = i & 15;
        int jj = r0 + row;
        uint4 v = make_uint4(0u,0u,0u,0u);
        if (jj < class_end) v = ((const uint4*)&g_Ab[(size_t)jj*NF])[seg];
        *(uint4*)&At[row*CSTR + seg*8] = v;
    }
    __syncthreads();

    unsigned af[8][4];
    int ar = warp_m * 16 + g;
    #pragma unroll
    for (int kk = 0; kk < 8; kk++) {
        af[kk][0] = *(const unsigned*)&At[ ar    *CSTR + kk*16     + 2*tt];
        af[kk][1] = *(const unsigned*)&At[(ar+8)*CSTR + kk*16     + 2*tt];
        af[kk][2] = *(const unsigned*)&At[ ar    *CSTR + kk*16 + 8 + 2*tt];
        af[kk][3] = *(const unsigned*)&At[(ar+8)*CSTR + kk*16 + 8 + 2*tt];
    }

    int lm = lane >> 3, lr = lane & 7;
    unsigned lmbase = (unsigned)((warp_n*32 + (lm>>1)*8 + lr) * CSTR + (lm&1)*8);

    const unsigned long long K5 = pk2(1.f/120.f, 1.f/120.f);
    const unsigned long long K4 = pk2(1.f/24.f,  1.f/24.f);
    const unsigned long long K3 = pk2(1.f/6.f,   1.f/6.f);
    const unsigned long long K2 = pk2(0.5f,      0.5f);
    const unsigned long long K1 = pk2(1.f,       1.f);

    unsigned long long sA2 = pk2(0.f, 0.f), sB2 = pk2(0.f, 0.f);

    for (int ch = 0; ch < NCHUNK; ch++) {
        if (ch <= NCHUNK-3)      { CP_ASYNC_WAIT(2); }
        else if (ch == NCHUNK-2) { CP_ASYNC_WAIT(1); }
        else                     { CP_ASYNC_WAIT(0); }
        __syncthreads();

        const __nv_bfloat16* B = &Bt[(ch % 3) * 64 * CSTR];
        unsigned bbase = smem_u32(B) + 2u * lmbase;

        float c[4][4];
        #pragma unroll
        for (int nn = 0; nn < 4; nn++)
            #pragma unroll
            for (int q = 0; q < 4; q++) c[nn][q] = 0.f;

        #pragma unroll
        for (int kk = 0; kk < 8; kk++) {
            #pragma unroll
            for (int q = 0; q < 2; q++) {
                unsigned x0, x1, x2, x3;
                ldsm4(x0, x1, x2, x3, bbase + 2u*(unsigned)(q*16*CSTR + kk*16));
                mma16816(c[2*q],     af[kk], x0, x1);
                mma16816(c[2*q + 1], af[kk], x2, x3);
            }
        }
        #pragma unroll
        for (int nn = 0; nn < 4; nn++) {
            unsigned long long XA = pk2(c[nn][0], c[nn][1]);
            unsigned long long XB = pk2(c[nn][2], c[nn][3]);
            unsigned long long rA = fma2(K5, XA, K4);
            unsigned long long rB = fma2(K5, XB, K4);
            rA = fma2(rA, XA, K3);  rB = fma2(rB, XB, K3);
            rA = fma2(rA, XA, K2);  rB = fma2(rB, XB, K2);
            rA = fma2(rA, XA, K1);  rB = fma2(rB, XB, K1);
            rA = fma2(rA, XA, K1);  rB = fma2(rB, XB, K1);
            sA2 = add2(sA2, rA);
            sB2 = add2(sB2, rB);
        }
        __syncthreads();

        if (ch + 3 < NCHUNK) {
            int jt = j0 + (ch + 3) * 64;
            __nv_bfloat16* dbuf = &Bt[(ch % 3) * 64 * CSTR];
            for (int i = t; i < 1024; i += 256) {
                int row = i >> 4, seg = i & 15;
                int jj = jt + row;
                unsigned dst = smem_u32(&dbuf[row*CSTR + seg*8]);
                const __nv_bfloat16* src = &g_Pb[(size_t)min(jj, jlim-1)*NF + seg*8];
                int sz = (jj < jlim) ? 16 : 0;
                asm volatile("cp.async.cg.shared.global [%0], [%1], 16, %2;\n"
                             :: "r"(dst), "l"(src), "r"(sz));
            }
            CP_ASYNC_COMMIT();
        }
    }

    float aLo, aHi, bLo, bHi;
    unpk2(sA2, aLo, aHi);
    unpk2(sB2, bLo, bHi);
    float sumA = aLo + aHi, sumB = bLo + bHi;
    #pragma unroll
    for (int m = 1; m <= 2; m <<= 1) {
        sumA += __shfl_xor_sync(0xffffffffu, sumA, m);
        sumB += __shfl_xor_sync(0xffffffffu, sumB, m);
    }
    __syncthreads();
    float* sred = (float*)sm;
    if (tt == 0) {
        sred[warp_n*64 + warp_m*16 + g]     = sumA;
        sred[warp_n*64 + warp_m*16 + g + 8] = sumB;
    }
    __syncthreads();
    if (t < 64) {
        int row = r0 + t;
        if (row < class_end)
            g_denomH[jh*NR + row] = sred[t] + sred[64 + t] - 48.0f;  // 48 zero-pad cols
    }
}

// ---------------- K7: final combine ----------------
__global__ void k_final(float* out) {
    int t = threadIdx.x;
    float s = 0.f;
    for (int i = t; i < NR; i += 256)
        s += logf(g_denomH[i] + g_denomH[NR + i]);
    float sm_ = 0.f;
    for (int i = t; i < 512; i += 256) sm_ += g_mseP[i];
    float sk = 0.f;
    if (t < 125) sk = g_smaskP[t];
    #pragma unroll
    for (int m = 16; m; m >>= 1) {
        s   += __shfl_xor_sync(0xffffffffu, s, m);
        sm_ += __shfl_xor_sync(0xffffffffu, sm_, m);
        sk  += __shfl_xor_sync(0xffffffffu, sk, m);
    }
    __shared__ float ws[8][3];
    if ((t & 31) == 0) { ws[t>>5][0] = s; ws[t>>5][1] = sm_; ws[t>>5][2] = sk; }
    __syncthreads();
    if (t == 0) {
        float lsum = 0.f, msum = 0.f, ksum = 0.f;
        #pragma unroll
        for (int w = 0; w < 8; w++) { lsum += ws[w][0]; msum += ws[w][1]; ksum += ws[w][2]; }
        float supcon = -ksum * (1.0f / NR) + lsum;
        float mse = msum * (1.0f / NMSE);
        out[0] = supcon + 0.5f * mse;
    }
}

extern "C" void kernel_launch(void* const* d_in, const int* in_sizes, int n_in,
                              void* d_out, int out_size) {
    const float* Zs  = (const float*)d_in[0];
    const int*   pos = (const int*)d_in[1];
    const int*   neg = (const int*)d_in[2];
    const float* fd  = (const float*)d_in[3];
    const float* id  = (const float*)d_in[4];
    float* out = (float*)d_out;

    static int smem_set = 0;
    int denom_smem = (64*CSTR + 3*64*CSTR) * (int)sizeof(__nv_bfloat16);
    int prep_smem  = (64*PSTR + 128*MSTR) * (int)sizeof(__nv_bfloat16) + 600*4;
    if (!smem_set) {
        cudaFuncSetAttribute(k_denom, cudaFuncAttributeMaxDynamicSharedMemorySize, denom_smem);
        cudaFuncSetAttribute(k_prep,  cudaFuncAttributeMaxDynamicSharedMemorySize, prep_smem);
        smem_set = 1;
    }

    k_front <<<1513, 256>>>(Zs, pos, neg, fd, id);
    k_MA    <<<NMP, 256>>>();
    k_Mred  <<<276, 256>>>();
    k_prep  <<<125, 256, prep_smem>>>();
    k_denom <<<252, 256, denom_smem>>>();
    k_final <<<1, 256>>>(out);
}

// round 13
// speedup vs baseline: 4.5950x; 1.0547x over previous
#include <cuda_runtime.h>
#include <cuda_bf16.h>
#include <math.h>
#include <stdint.h>

#define NR    8000
#define NPOS  4000
#define NF    128
#define NVOX  32768
#define NMSE  (128*32*32*32)
#define NMP   125          // k_MA split-K partial count (64 rows each)

// ---- scratch (static device globals; no allocations) ----
__device__ __nv_bfloat16  g_Pb[NR*NF];       // normalized pixels bf16
__device__ __nv_bfloat16  g_Mp[NMP*NF*NF];   // split-K partials of P^T P (bf16, 4 MB)
__device__ __nv_bfloat16  g_Mb[NF*NF];       // P^T P in bf16
__device__ float          g_S[2*NF];         // class col sums (atomic, zeroed in k_front)
__device__ float          g_Sp[1000*NF];     // per-gather-block column-sum partials
__device__ float          g_mseP[512];       // per-block mse partials
__device__ float          g_smaskP[128];     // per-row-tile S_mask partials (126 used)
__device__ float          g_denomH[2*NR];    // per-column-half denom sums

__device__ __forceinline__ unsigned smem_u32(const void* p) {
    return (unsigned)__cvta_generic_to_shared(p);
}
#define CP_ASYNC_COMMIT() asm volatile("cp.async.commit_group;\n" ::)
#define CP_ASYNC_WAIT(n)  asm volatile("cp.async.wait_group %0;\n" :: "n"(n))

// packed f32x2 helpers
__device__ __forceinline__ unsigned long long pk2(float lo, float hi) {
    unsigned long long v; asm("mov.b64 %0,{%1,%2};" : "=l"(v) : "f"(lo), "f"(hi)); return v;
}
__device__ __forceinline__ void unpk2(unsigned long long v, float& lo, float& hi) {
    asm("mov.b64 {%0,%1},%2;" : "=f"(lo), "=f"(hi) : "l"(v));
}
__device__ __forceinline__ unsigned long long fma2(unsigned long long a,
                                                   unsigned long long b,
                                                   unsigned long long c) {
    unsigned long long d;
    asm("fma.rn.f32x2 %0,%1,%2,%3;" : "=l"(d) : "l"(a), "l"(b), "l"(c));
    return d;
}
__device__ __forceinline__ unsigned long long add2(unsigned long long a,
                                                   unsigned long long b) {
    unsigned long long d;
    asm("add.rn.f32x2 %0,%1,%2;" : "=l"(d) : "l"(a), "l"(b));
    return d;
}

__device__ __forceinline__ void mma16816(float c[4], const unsigned a[4],
                                         unsigned b0, unsigned b1) {
    asm volatile(
        "mma.sync.aligned.m16n8k16.row.col.f32.bf16.bf16.f32 "
        "{%0,%1,%2,%3}, {%4,%5,%6,%7}, {%8,%9}, {%0,%1,%2,%3};"
        : "+f"(c[0]), "+f"(c[1]), "+f"(c[2]), "+f"(c[3])
        : "r"(a[0]), "r"(a[1]), "r"(a[2]), "r"(a[3]), "r"(b0), "r"(b1));
}
__device__ __forceinline__ void ldsm4(unsigned& x0, unsigned& x1,
                                      unsigned& x2, unsigned& x3, unsigned addr) {
    asm volatile("ldmatrix.sync.aligned.m8n8.x4.shared.b16 {%0,%1,%2,%3}, [%4];"
                 : "=r"(x0), "=r"(x1), "=r"(x2), "=r"(x3) : "r"(addr));
}
__device__ __forceinline__ unsigned scale_bf162(unsigned v, float s) {
    float2 f = __bfloat1622float2(*(__nv_bfloat162*)&v);
    __nv_bfloat162 y = __floats2bfloat162_rn(f.x*s, f.y*s);
    return *(unsigned*)&y;
}

// ---------------- K1: fused front kernel ----------------
__global__ void k_front(const float* __restrict__ Zs,
                        const int* __restrict__ pos,
                        const int* __restrict__ neg,
                        const float* __restrict__ fd,
                        const float* __restrict__ id) {
    __shared__ float smP[8][NF];
    int b = blockIdx.x, t = threadIdx.x;
    if (b < 1000) {
        int wid = t >> 5, lane = t & 31;
        int r = b * 8 + wid;
        int v = (r < NPOS) ? pos[r] : neg[r - NPOS];
        float x[4];
        #pragma unroll
        for (int k = 0; k < 4; k++) x[k] = Zs[(size_t)(lane + 32*k)*NVOX + v];
        float s = x[0]*x[0] + x[1]*x[1] + x[2]*x[2] + x[3]*x[3];
        #pragma unroll
        for (int m = 16; m; m >>= 1) s += __shfl_xor_sync(0xffffffffu, s, m);
        float inv = 1.0f / fmaxf(sqrtf(s), 1e-12f);
        #pragma unroll
        for (int k = 0; k < 4; k++) {
            float p = x[k] * inv;
            g_Pb[r*NF + lane + 32*k] = __float2bfloat16(p);
            smP[wid][lane + 32*k] = p;
        }
        __syncthreads();
        if (t < NF) {
            float cs = 0.f;
            #pragma unroll
            for (int w = 0; w < 8; w++) cs += smP[w][t];
            g_Sp[b*NF + t] = cs;
        }
    } else if (b < 1512) {
        int mb = b - 1000;
        int n4 = NMSE / 4;
        float s = 0.f;
        for (int i = mb*256 + t; i < n4; i += 512*256) {
            float4 a = ((const float4*)fd)[i];
            float4 c = ((const float4*)id)[i];
            float d0 = a.x-c.x, d1 = a.y-c.y, d2 = a.z-c.z, d3 = a.w-c.w;
            s += d0*d0 + d1*d1 + d2*d2 + d3*d3;
        }
        #pragma unroll
        for (int m = 16; m; m >>= 1) s += __shfl_xor_sync(0xffffffffu, s, m);
        __shared__ float ws[8];
        if ((t & 31) == 0) ws[t >> 5] = s;
        __syncthreads();
        if (t == 0) {
            float tot = 0.f;
            #pragma unroll
            for (int w = 0; w < 8; w++) tot += ws[w];
            g_mseP[mb] = tot;
        }
    } else {
        if (t < 2*NF) g_S[t] = 0.f;
    }
}

// ---------------- K2a: M = P^T P split-K partials via bf16 HMMA ----------------
__global__ void __launch_bounds__(256) k_MA() {
    __shared__ unsigned short spT[128][72];  // transposed tile: [feat][sample]
    int t = threadIdx.x, wid = t >> 5, lane = t & 31;
    int r0 = blockIdx.x * 64;

    for (int i = t; i < 1024; i += 256) {
        int r = i >> 4, seg = i & 15;
        uint4 v = ((const uint4*)&g_Pb[(size_t)(r0+r)*NF])[seg];
        unsigned w0 = v.x, w1 = v.y, w2 = v.z, w3 = v.w;
        int f = seg * 8;
        spT[f+0][r] = (unsigned short)(w0 & 0xffffu);
        spT[f+1][r] = (unsigned short)(w0 >> 16);
        spT[f+2][r] = (unsigned short)(w1 & 0xffffu);
        spT[f+3][r] = (unsigned short)(w1 >> 16);
        spT[f+4][r] = (unsigned short)(w2 & 0xffffu);
        spT[f+5][r] = (unsigned short)(w2 >> 16);
        spT[f+6][r] = (unsigned short)(w3 & 0xffffu);
        spT[f+7][r] = (unsigned short)(w3 >> 16);
    }
    __syncthreads();

    int i0 = wid * 16;
    int lm = lane >> 3, lr = lane & 7;
    unsigned base = smem_u32(&spT[0][0]);
    unsigned aAddr0 = base + (unsigned)(((i0 + (lm & 1)*8 + lr) * 72 + (lm >> 1)*8) << 1);
    unsigned bRowOff = (unsigned)((((lm >> 1)*8 + lr) * 72 + (lm & 1)*8) << 1);

    float c[16][4];
    #pragma unroll
    for (int nn = 0; nn < 16; nn++)
        #pragma unroll
        for (int q = 0; q < 4; q++) c[nn][q] = 0.f;

    #pragma unroll
    for (int kk = 0; kk < 4; kk++) {
        unsigned af[4];
        ldsm4(af[0], af[1], af[2], af[3], aAddr0 + kk*32);
        #pragma unroll
        for (int q = 0; q < 8; q++) {
            unsigned x0, x1, x2, x3;
            unsigned addr = base + (unsigned)((q*16*72) << 1) + bRowOff + kk*32;
            ldsm4(x0, x1, x2, x3, addr);
            mma16816(c[2*q],     af, x0, x1);
            mma16816(c[2*q + 1], af, x2, x3);
        }
    }

    __nv_bfloat16* dst = &g_Mp[(size_t)blockIdx.x * NF * NF];
    int g = lane >> 2, tt = lane & 3;
    #pragma unroll
    for (int nn = 0; nn < 16; nn++) {
        int col = nn*8 + 2*tt;
        __nv_bfloat162 v0 = __floats2bfloat162_rn(c[nn][0], c[nn][1]);
        __nv_bfloat162 v1 = __floats2bfloat162_rn(c[nn][2], c[nn][3]);
        *(unsigned*)&dst[(i0+g  )*NF + col] = *(unsigned*)&v0;
        *(unsigned*)&dst[(i0+g+8)*NF + col] = *(unsigned*)&v1;
    }
}

// ---------------- K2b: reduce M partials (-> bf16 M) + S partials ----------------
// grid 276: [0,256) = 64-element chunks -> g_Mb ; [256,276) = S chunks -> atomic g_S
__global__ void k_Mred() {
    int b = blockIdx.x, t = threadIdx.x;
    if (b < 256) {
        __shared__ float red[4][64];
        int gp = t >> 6, e = t & 63;
        int base = b * 64;
        int p0 = gp * 32, pc = (gp == 3) ? 29 : 32;
        float s = 0.f;
        for (int p = p0; p < p0 + pc; p++)
            s += __bfloat162float(g_Mp[(size_t)p*NF*NF + base + e]);
        red[gp][e] = s;
        __syncthreads();
        if (t < 64)
            g_Mb[base + t] = __float2bfloat16(red[0][t] + red[1][t] + red[2][t] + red[3][t]);
    } else if (t < NF) {
        int idx = b - 256;
        int cls = idx & 1, chunk = idx >> 1;
        int b0 = cls * 500 + chunk * 50;
        float s = 0.f;
        #pragma unroll 10
        for (int k = 0; k < 50; k++) s += g_Sp[(b0 + k)*NF + t];
        atomicAdd(&g_S[cls*NF + t], s);
    }
}

// ---------------- K5: fused prep + bf16 GEMM + packed poly-exp + row reduce ------
#define CSTR   136         // padded smem stride in bf16
#define NCHUNK 32          // 32 x 64 = 2048 >= 2000 cols

// grid 252: 126 row tiles (64 rows, class-aligned w/ zero-pad) x 2 column halves
__global__ void __launch_bounds__(256, 2) k_denom() {
    extern __shared__ __nv_bfloat16 sm[];
    __nv_bfloat16* At = sm;                  // 64 x CSTR (raw P tile)
    __nv_bfloat16* Bt = sm + 64*CSTR;        // 3 x 64 x CSTR (triple buffer)
    float* fb   = (float*)(sm + 64*CSTR + 3*64*CSTR);
    float* Ssm  = fb;        // [128]
    float* qsm  = fb + 128;  // [128]
    float* psm  = fb + 256;  // [128]
    float* rsm  = fb + 384;  // [64]
    float* wsum = fb + 448;  // [2]

    int bid = blockIdx.x;
    int tileR = bid >> 1, jh = bid & 1;
    int r0, class_end, j0;
    if (tileR < 63) { r0 = tileR * 64;              class_end = NPOS; j0 = NPOS; }
    else            { r0 = NPOS + (tileR - 63)*64;  class_end = NR;   j0 = 0;    }
    j0 += jh * 2000;
    int jlim = j0 + 2000;

    int t = threadIdx.x;
    int wid = t >> 5, lane = t & 31;
    int g = lane >> 2, tt = lane & 3;
    int warp_m = wid & 3, warp_n = wid >> 2;

    // 1. prefetch B chunk 0 into Bt[0] (async; not needed until mainloop)
    for (int i = t; i < 1024; i += 256) {
        int row = i >> 4, seg = i & 15;
        int jj = j0 + row;
        unsigned dst = smem_u32(&Bt[row*CSTR + seg*8]);
        const __nv_bfloat16* src = &g_Pb[(size_t)min(jj, jlim-1)*NF + seg*8];
        int sz = (jj < jlim) ? 16 : 0;
        asm volatile("cp.async.cg.shared.global [%0], [%1], 16, %2;\n"
                     :: "r"(dst), "l"(src), "r"(sz));
    }
    CP_ASYNC_COMMIT();

    // 2. load raw P tile into At (zero rows beyond class_end); M into Bt[1..2]; S
    for (int i = t; i < 1024; i += 256) {
        int row = i >> 4, seg = i & 15;
        int jj = r0 + row;
        uint4 v = make_uint4(0u,0u,0u,0u);
        if (jj < class_end) v = ((const uint4*)&g_Pb[(size_t)jj*NF])[seg];
        *(uint4*)&At[row*CSTR + seg*8] = v;
    }
    __nv_bfloat16* Mt = Bt + 64*CSTR;        // occupies chunk buffers 1 and 2
    {
        const uint4* srcM = (const uint4*)g_Mb;
        for (int i = t; i < 2048; i += 256) {
            int row = i >> 4, seg = i & 15;
            *(uint4*)&Mt[row*CSTR + seg*8] = srcM[i];
        }
    }
    if (t < NF) Ssm[t] = g_S[((r0 < NPOS) ? 0 : NF) + t];
    __syncthreads();

    // 3. A fragments from raw P tile
    unsigned af[8][4];
    int ar = warp_m * 16 + g;
    #pragma unroll
    for (int kk = 0; kk < 8; kk++) {
        af[kk][0] = *(const unsigned*)&At[ ar    *CSTR + kk*16     + 2*tt];
        af[kk][1] = *(const unsigned*)&At[(ar+8)*CSTR + kk*16     + 2*tt];
        af[kk][2] = *(const unsigned*)&At[ ar    *CSTR + kk*16 + 8 + 2*tt];
        af[kk][3] = *(const unsigned*)&At[(ar+8)*CSTR + kk*16 + 8 + 2*tt];
    }

    int lm = lane >> 3, lr = lane & 7;

    // 4. prep GEMM: Y = P * M  (M symmetric -> row-major M tile, K-major frags)
    {
        unsigned mbase = smem_u32(Mt)
                       + 2u*(unsigned)((warp_n*64 + (lm>>1)*8 + lr)*CSTR + (lm&1)*8);
        float c[8][4];
        #pragma unroll
        for (int nn = 0; nn < 8; nn++)
            #pragma unroll
            for (int q = 0; q < 4; q++) c[nn][q] = 0.f;
        #pragma unroll
        for (int kk = 0; kk < 8; kk++) {
            #pragma unroll
            for (int q = 0; q < 4; q++) {
                unsigned x0, x1, x2, x3;
                ldsm4(x0, x1, x2, x3, mbase + 2u*(unsigned)(q*16*CSTR + kk*16));
                mma16816(c[2*q],     af[kk], x0, x1);
                mma16816(c[2*q + 1], af[kk], x2, x3);
            }
        }
        // epilogue: qf = <Y_r, P_r>, ps = <S, P_r>
        float qA = 0.f, qB = 0.f, pA = 0.f, pB = 0.f;
        #pragma unroll
        for (int nn = 0; nn < 8; nn++) {
            int col = warp_n*64 + nn*8 + 2*tt;
            float2 pa = __bfloat1622float2(*(__nv_bfloat162*)&At[ ar    *CSTR + col]);
            float2 pb = __bfloat1622float2(*(__nv_bfloat162*)&At[(ar+8)*CSTR + col]);
            qA += c[nn][0]*pa.x + c[nn][1]*pa.y;
            qB += c[nn][2]*pb.x + c[nn][3]*pb.y;
            float2 sv = *(const float2*)&Ssm[col];
            pA += sv.x*pa.x + sv.y*pa.y;
            pB += sv.x*pb.x + sv.y*pb.y;
        }
        #pragma unroll
        for (int m = 1; m <= 2; m <<= 1) {
            qA += __shfl_xor_sync(0xffffffffu, qA, m);
            qB += __shfl_xor_sync(0xffffffffu, qB, m);
            pA += __shfl_xor_sync(0xffffffffu, pA, m);
            pB += __shfl_xor_sync(0xffffffffu, pB, m);
        }
        if (tt == 0) {
            qsm[warp_n*64 + ar]     = qA;
            qsm[warp_n*64 + ar + 8] = qB;
            psm[warp_n*64 + ar]     = pA;
            psm[warp_n*64 + ar + 8] = pB;
        }
    }
    __syncthreads();   // GEMM done in all warps -> Mt region free; qsm/psm ready

    if (t < 64) {
        float qf = qsm[t] + qsm[64 + t];
        float ps = psm[t] + psm[64 + t];
        float rinv = rsqrtf(qf);
        rinv = rinv * (1.5f - 0.5f * qf * rinv * rinv);
        bool valid = (r0 + t) < class_end;
        rsm[t] = valid ? rinv : 0.f;
        float cv = valid ? (ps - 1.0f) * rinv : 0.f;
        #pragma unroll
        for (int m = 16; m; m >>= 1) cv += __shfl_xor_sync(0xffffffffu, cv, m);
        if (lane == 0) wsum[wid] = cv;
    }
    __syncthreads();
    if (jh == 0 && t == 0) g_smaskP[tileR] = wsum[0] + wsum[1];

    // 5. prefetch B chunks 1,2 (overwrites Mt region -- safe after sync above)
    #pragma unroll
    for (int ch = 1; ch < 3; ch++) {
        __nv_bfloat16* dbuf = &Bt[ch * 64 * CSTR];
        for (int i = t; i < 1024; i += 256) {
            int row = i >> 4, seg = i & 15;
            int jj = j0 + ch*64 + row;
            unsigned dst = smem_u32(&dbuf[row*CSTR + seg*8]);
            const __nv_bfloat16* src = &g_Pb[(size_t)min(jj, jlim-1)*NF + seg*8];
            int sz = (jj < jlim) ? 16 : 0;
            asm volatile("cp.async.cg.shared.global [%0], [%1], 16, %2;\n"
                         :: "r"(dst), "l"(src), "r"(sz));
        }
        CP_ASYNC_COMMIT();
    }

    // 6. scale A fragments in registers: A = P * rinv (rowwise)
    {
        float rvA = rsm[ar], rvB = rsm[ar + 8];
        #pragma unroll
        for (int kk = 0; kk < 8; kk++) {
            af[kk][0] = scale_bf162(af[kk][0], rvA);
            af[kk][2] = scale_bf162(af[kk][2], rvA);
            af[kk][1] = scale_bf162(af[kk][1], rvB);
            af[kk][3] = scale_bf162(af[kk][3], rvB);
        }
    }

    unsigned lmbase = (unsigned)((warp_n*32 + (lm>>1)*8 + lr) * CSTR + (lm&1)*8);

    const unsigned long long K5 = pk2(1.f/120.f, 1.f/120.f);
    const unsigned long long K4 = pk2(1.f/24.f,  1.f/24.f);
    const unsigned long long K3 = pk2(1.f/6.f,   1.f/6.f);
    const unsigned long long K2 = pk2(0.5f,      0.5f);
    const unsigned long long K1 = pk2(1.f,       1.f);

    unsigned long long sA2 = pk2(0.f, 0.f), sB2 = pk2(0.f, 0.f);

    for (int ch = 0; ch < NCHUNK; ch++) {
        if (ch <= NCHUNK-3)      { CP_ASYNC_WAIT(2); }
        else if (ch == NCHUNK-2) { CP_ASYNC_WAIT(1); }
        else                     { CP_ASYNC_WAIT(0); }
        __syncthreads();

        const __nv_bfloat16* B = &Bt[(ch % 3) * 64 * CSTR];
        unsigned bbase = smem_u32(B) + 2u * lmbase;

        float c[4][4];
        #pragma unroll
        for (int nn = 0; nn < 4; nn++)
            #pragma unroll
            for (int q = 0; q < 4; q++) c[nn][q] = 0.f;

        #pragma unroll
        for (int kk = 0; kk < 8; kk++) {
            #pragma unroll
            for (int q = 0; q < 2; q++) {
                unsigned x0, x1, x2, x3;
                ldsm4(x0, x1, x2, x3, bbase + 2u*(unsigned)(q*16*CSTR + kk*16));
                mma16816(c[2*q],     af[kk], x0, x1);
                mma16816(c[2*q + 1], af[kk], x2, x3);
            }
        }
        #pragma unroll
        for (int nn = 0; nn < 4; nn++) {
            unsigned long long XA = pk2(c[nn][0], c[nn][1]);
            unsigned long long XB = pk2(c[nn][2], c[nn][3]);
            unsigned long long rA = fma2(K5, XA, K4);
            unsigned long long rB = fma2(K5, XB, K4);
            rA = fma2(rA, XA, K3);  rB = fma2(rB, XB, K3);
            rA = fma2(rA, XA, K2);  rB = fma2(rB, XB, K2);
            rA = fma2(rA, XA, K1);  rB = fma2(rB, XB, K1);
            rA = fma2(rA, XA, K1);  rB = fma2(rB, XB, K1);
            sA2 = add2(sA2, rA);
            sB2 = add2(sB2, rB);
        }
        __syncthreads();

        if (ch + 3 < NCHUNK) {
            int jt = j0 + (ch + 3) * 64;
            __nv_bfloat16* dbuf = &Bt[(ch % 3) * 64 * CSTR];
            for (int i = t; i < 1024; i += 256) {
                int row = i >> 4, seg = i & 15;
                int jj = jt + row;
                unsigned dst = smem_u32(&dbuf[row*CSTR + seg*8]);
                const __nv_bfloat16* src = &g_Pb[(size_t)min(jj, jlim-1)*NF + seg*8];
                int sz = (jj < jlim) ? 16 : 0;
                asm volatile("cp.async.cg.shared.global [%0], [%1], 16, %2;\n"
                             :: "r"(dst), "l"(src), "r"(sz));
            }
            CP_ASYNC_COMMIT();
        }
    }

    float aLo, aHi, bLo, bHi;
    unpk2(sA2, aLo, aHi);
    unpk2(sB2, bLo, bHi);
    float sumA = aLo + aHi, sumB = bLo + bHi;
    #pragma unroll
    for (int m = 1; m <= 2; m <<= 1) {
        sumA += __shfl_xor_sync(0xffffffffu, sumA, m);
        sumB += __shfl_xor_sync(0xffffffffu, sumB, m);
    }
    __syncthreads();
    float* sred = (float*)sm;
    if (tt == 0) {
        sred[warp_n*64 + warp_m*16 + g]     = sumA;
        sred[warp_n*64 + warp_m*16 + g + 8] = sumB;
    }
    __syncthreads();
    if (t < 64) {
        int row = r0 + t;
        if (row < class_end)
            g_denomH[jh*NR + row] = sred[t] + sred[64 + t] - 48.0f;  // 48 zero-pad cols
    }
}

// ---------------- K7: final combine ----------------
__global__ void k_final(float* out) {
    int t = threadIdx.x;
    float s = 0.f;
    for (int i = t; i < NR; i += 256)
        s += logf(g_denomH[i] + g_denomH[NR + i]);
    float sm_ = 0.f;
    for (int i = t; i < 512; i += 256) sm_ += g_mseP[i];
    float sk = 0.f;
    if (t < 126) sk = g_smaskP[t];
    #pragma unroll
    for (int m = 16; m; m >>= 1) {
        s   += __shfl_xor_sync(0xffffffffu, s, m);
        sm_ += __shfl_xor_sync(0xffffffffu, sm_, m);
        sk  += __shfl_xor_sync(0xffffffffu, sk, m);
    }
    __shared__ float ws[8][3];
    if ((t & 31) == 0) { ws[t>>5][0] = s; ws[t>>5][1] = sm_; ws[t>>5][2] = sk; }
    __syncthreads();
    if (t == 0) {
        float lsum = 0.f, msum = 0.f, ksum = 0.f;
        #pragma unroll
        for (int w = 0; w < 8; w++) { lsum += ws[w][0]; msum += ws[w][1]; ksum += ws[w][2]; }
        float supcon = -ksum * (1.0f / NR) + lsum;
        float mse = msum * (1.0f / NMSE);
        out[0] = supcon + 0.5f * mse;
    }
}

extern "C" void kernel_launch(void* const* d_in, const int* in_sizes, int n_in,
                              void* d_out, int out_size) {
    const float* Zs  = (const float*)d_in[0];
    const int*   pos = (const int*)d_in[1];
    const int*   neg = (const int*)d_in[2];
    const float* fd  = (const float*)d_in[3];
    const float* id  = (const float*)d_in[4];
    float* out = (float*)d_out;

    static int smem_set = 0;
    int denom_smem = (64*CSTR + 3*64*CSTR) * (int)sizeof(__nv_bfloat16) + 464*4;
    if (!smem_set) {
        cudaFuncSetAttribute(k_denom, cudaFuncAttributeMaxDynamicSharedMemorySize, denom_smem);
        smem_set = 1;
    }

    k_front <<<1513, 256>>>(Zs, pos, neg, fd, id);
    k_MA    <<<NMP, 256>>>();
    k_Mred  <<<276, 256>>>();
    k_denom <<<252, 256, denom_smem>>>();
    k_final <<<1, 256>>>(out);
}

// round 14
// speedup vs baseline: 9.7272x; 2.1169x over previous
#include <cuda_runtime.h>
#include <cuda_bf16.h>
#include <math.h>
#include <stdint.h>

#define NR    8000
#define NPOS  4000
#define NF    128
#define NVOX  32768
#define NMSE  (128*32*32*32)
#define NMP   126          // per-class split-K moment partials (63 pos + 63 neg)

// ---- scratch (static device globals; no allocations) ----
__device__ __nv_bfloat16  g_Pb[NR*NF];       // normalized pixels bf16
__device__ __nv_bfloat16  g_Mp[NMP*NF*NF];   // per-class moment partials (bf16, 4 MB)
__device__ __nv_bfloat16  g_Mb[2*NF*NF];     // [0]=M_pos, [1]=M_neg (bf16)
__device__ float          g_S[2*NF];         // class col sums (atomic, zeroed in k_front)
__device__ float          g_Sp[1000*NF];     // per-gather-block column-sum partials
__device__ float          g_mseP[512];       // per-block mse partials
__device__ float          g_smaskP[128];     // per-tile S_mask partials (126 used)
__device__ float          g_logP[128];       // per-tile log(denom) partials (126 used)

__device__ __forceinline__ unsigned smem_u32(const void* p) {
    return (unsigned)__cvta_generic_to_shared(p);
}

__device__ __forceinline__ void mma16816(float c[4], const unsigned a[4],
                                         unsigned b0, unsigned b1) {
    asm volatile(
        "mma.sync.aligned.m16n8k16.row.col.f32.bf16.bf16.f32 "
        "{%0,%1,%2,%3}, {%4,%5,%6,%7}, {%8,%9}, {%0,%1,%2,%3};"
        : "+f"(c[0]), "+f"(c[1]), "+f"(c[2]), "+f"(c[3])
        : "r"(a[0]), "r"(a[1]), "r"(a[2]), "r"(a[3]), "r"(b0), "r"(b1));
}
__device__ __forceinline__ void ldsm4(unsigned& x0, unsigned& x1,
                                      unsigned& x2, unsigned& x3, unsigned addr) {
    asm volatile("ldmatrix.sync.aligned.m8n8.x4.shared.b16 {%0,%1,%2,%3}, [%4];"
                 : "=r"(x0), "=r"(x1), "=r"(x2), "=r"(x3) : "r"(addr));
}

// ---------------- K1: fused front kernel ----------------
// [0,1000): gather + normalize + col-sum partial; [1000,1512): MSE; 1512: zero g_S
__global__ void k_front(const float* __restrict__ Zs,
                        const int* __restrict__ pos,
                        const int* __restrict__ neg,
                        const float* __restrict__ fd,
                        const float* __restrict__ id) {
    __shared__ float smP[8][NF];
    int b = blockIdx.x, t = threadIdx.x;
    if (b < 1000) {
        int wid = t >> 5, lane = t & 31;
        int r = b * 8 + wid;
        int v = (r < NPOS) ? pos[r] : neg[r - NPOS];
        float x[4];
        #pragma unroll
        for (int k = 0; k < 4; k++) x[k] = Zs[(size_t)(lane + 32*k)*NVOX + v];
        float s = x[0]*x[0] + x[1]*x[1] + x[2]*x[2] + x[3]*x[3];
        #pragma unroll
        for (int m = 16; m; m >>= 1) s += __shfl_xor_sync(0xffffffffu, s, m);
        float inv = 1.0f / fmaxf(sqrtf(s), 1e-12f);
        #pragma unroll
        for (int k = 0; k < 4; k++) {
            float p = x[k] * inv;
            g_Pb[r*NF + lane + 32*k] = __float2bfloat16(p);
            smP[wid][lane + 32*k] = p;
        }
        __syncthreads();
        if (t < NF) {
            float cs = 0.f;
            #pragma unroll
            for (int w = 0; w < 8; w++) cs += smP[w][t];
            g_Sp[b*NF + t] = cs;
        }
    } else if (b < 1512) {
        int mb = b - 1000;
        int n4 = NMSE / 4;
        float s = 0.f;
        for (int i = mb*256 + t; i < n4; i += 512*256) {
            float4 a = ((const float4*)fd)[i];
            float4 c = ((const float4*)id)[i];
            float d0 = a.x-c.x, d1 = a.y-c.y, d2 = a.z-c.z, d3 = a.w-c.w;
            s += d0*d0 + d1*d1 + d2*d2 + d3*d3;
        }
        #pragma unroll
        for (int m = 16; m; m >>= 1) s += __shfl_xor_sync(0xffffffffu, s, m);
        __shared__ float ws[8];
        if ((t & 31) == 0) ws[t >> 5] = s;
        __syncthreads();
        if (t == 0) {
            float tot = 0.f;
            #pragma unroll
            for (int w = 0; w < 8; w++) tot += ws[w];
            g_mseP[mb] = tot;
        }
    } else {
        if (t < 2*NF) g_S[t] = 0.f;
    }
}

// ---------------- K2a: per-class moment partials via bf16 HMMA ----------------
// grid 126: b<63 -> pos tile (rows b*64, valid<4000), b>=63 -> neg tile
__global__ void __launch_bounds__(256) k_MA() {
    __shared__ unsigned short spT[128][72];  // transposed tile: [feat][sample]
    int t = threadIdx.x, wid = t >> 5, lane = t & 31;
    int b = blockIdx.x;
    int r0   = (b < 63) ? b*64 : NPOS + (b - 63)*64;
    int rlim = (b < 63) ? NPOS : NR;

    // load 64x128 bf16 (zero-pad rows >= rlim), transpose into spT
    for (int i = t; i < 1024; i += 256) {
        int r = i >> 4, seg = i & 15;
        int jj = r0 + r;
        uint4 v = make_uint4(0u,0u,0u,0u);
        if (jj < rlim) v = ((const uint4*)&g_Pb[(size_t)jj*NF])[seg];
        unsigned w0 = v.x, w1 = v.y, w2 = v.z, w3 = v.w;
        int f = seg * 8;
        spT[f+0][r] = (unsigned short)(w0 & 0xffffu);
        spT[f+1][r] = (unsigned short)(w0 >> 16);
        spT[f+2][r] = (unsigned short)(w1 & 0xffffu);
        spT[f+3][r] = (unsigned short)(w1 >> 16);
        spT[f+4][r] = (unsigned short)(w2 & 0xffffu);
        spT[f+5][r] = (unsigned short)(w2 >> 16);
        spT[f+6][r] = (unsigned short)(w3 & 0xffffu);
        spT[f+7][r] = (unsigned short)(w3 >> 16);
    }
    __syncthreads();

    int i0 = wid * 16;
    int lm = lane >> 3, lr = lane & 7;
    unsigned base = smem_u32(&spT[0][0]);
    unsigned aAddr0 = base + (unsigned)(((i0 + (lm & 1)*8 + lr) * 72 + (lm >> 1)*8) << 1);
    unsigned bRowOff = (unsigned)((((lm >> 1)*8 + lr) * 72 + (lm & 1)*8) << 1);

    float c[16][4];
    #pragma unroll
    for (int nn = 0; nn < 16; nn++)
        #pragma unroll
        for (int q = 0; q < 4; q++) c[nn][q] = 0.f;

    #pragma unroll
    for (int kk = 0; kk < 4; kk++) {
        unsigned af[4];
        ldsm4(af[0], af[1], af[2], af[3], aAddr0 + kk*32);
        #pragma unroll
        for (int q = 0; q < 8; q++) {
            unsigned x0, x1, x2, x3;
            unsigned addr = base + (unsigned)((q*16*72) << 1) + bRowOff + kk*32;
            ldsm4(x0, x1, x2, x3, addr);
            mma16816(c[2*q],     af, x0, x1);
            mma16816(c[2*q + 1], af, x2, x3);
        }
    }

    __nv_bfloat16* dst = &g_Mp[(size_t)b * NF * NF];
    int g = lane >> 2, tt = lane & 3;
    #pragma unroll
    for (int nn = 0; nn < 16; nn++) {
        int col = nn*8 + 2*tt;
        __nv_bfloat162 v0 = __floats2bfloat162_rn(c[nn][0], c[nn][1]);
        __nv_bfloat162 v1 = __floats2bfloat162_rn(c[nn][2], c[nn][3]);
        *(unsigned*)&dst[(i0+g  )*NF + col] = *(unsigned*)&v0;
        *(unsigned*)&dst[(i0+g+8)*NF + col] = *(unsigned*)&v1;
    }
}

// ---------------- K2b: reduce moment partials + S partials ----------------
// grid 148: [0,128) -> M chunks (b&1 = class, 256-elem chunk); [128,148) -> g_S
__global__ void k_Mred() {
    int b = blockIdx.x, t = threadIdx.x;
    if (b < 128) {
        int cls = b & 1, chunk = b >> 1;
        int e = chunk * 256 + t;
        int p0 = cls * 63;
        float s = 0.f;
        #pragma unroll 9
        for (int p = p0; p < p0 + 63; p++)
            s += __bfloat162float(g_Mp[(size_t)p*NF*NF + e]);
        g_Mb[cls*NF*NF + e] = __float2bfloat16(s);
    } else if (t < NF) {
        int idx = b - 128;
        int cls = idx & 1, chunk = idx >> 1;
        int b0 = cls * 500 + chunk * 50;
        float s = 0.f;
        #pragma unroll 10
        for (int k = 0; k < 50; k++) s += g_Sp[(b0 + k)*NF + t];
        atomicAdd(&g_S[cls*NF + t], s);
    }
}

// ---------------- K3: quadratic-form kernel (replaces the big GEMM) ----------
// denom_i = 4000 + rinv*(p_i . s_opp) + 0.5*rinv^2*(p_i^T M_opp p_i)
// grid 126 class-pure 64-row tiles, 256 thr = 8 warps (warp_m 0..3, warp_n 0..1)
#define CSTR 136
__global__ void __launch_bounds__(256) k_qform() {
    extern __shared__ __nv_bfloat16 sm[];
    __nv_bfloat16* Pt = sm;                   // 64 x CSTR
    __nv_bfloat16* Mt = sm + 64*CSTR;         // 2 x 128 x CSTR (Mpos, Mneg)
    float* fb  = (float*)(sm + 64*CSTR + 256*CSTR);
    float* Ssm = fb;            // [2][128]
    float* esm = fb + 256;      // [4][128]: q=0 qpos, 1 qneg, 2 sdot_pos, 3 sdot_neg
    float* wred = fb + 768;     // [4]

    int t = threadIdx.x, wid = t >> 5, lane = t & 31;
    int g = lane >> 2, tt = lane & 3;
    int warp_m = wid & 3, warp_n = wid >> 2;
    int b = blockIdx.x;
    int cls  = (b < 63) ? 0 : 1;
    int r0   = (cls == 0) ? b*64 : NPOS + (b - 63)*64;
    int rlim = (cls == 0) ? NPOS : NR;

    // loads
    for (int i = t; i < 1024; i += 256) {
        int row = i >> 4, seg = i & 15;
        int jj = r0 + row;
        uint4 v = make_uint4(0u,0u,0u,0u);
        if (jj < rlim) v = ((const uint4*)&g_Pb[(size_t)jj*NF])[seg];
        *(uint4*)&Pt[row*CSTR + seg*8] = v;
    }
    {
        const uint4* srcM = (const uint4*)g_Mb;
        for (int i = t; i < 4096; i += 256) {
            int row = i >> 4, seg = i & 15;   // row 0..255 spans both classes
            *(uint4*)&Mt[row*CSTR + seg*8] = srcM[i];
        }
    }
    if (t < 2*NF) Ssm[t] = g_S[t];
    __syncthreads();

    // A fragments (rows of P)
    unsigned af[8][4];
    int ar = warp_m * 16 + g;
    #pragma unroll
    for (int kk = 0; kk < 8; kk++) {
        af[kk][0] = *(const unsigned*)&Pt[ ar    *CSTR + kk*16     + 2*tt];
        af[kk][1] = *(const unsigned*)&Pt[(ar+8)*CSTR + kk*16     + 2*tt];
        af[kk][2] = *(const unsigned*)&Pt[ ar    *CSTR + kk*16 + 8 + 2*tt];
        af[kk][3] = *(const unsigned*)&Pt[(ar+8)*CSTR + kk*16 + 8 + 2*tt];
    }

    int lm = lane >> 3, lr = lane & 7;
    unsigned mrow = (unsigned)((warp_n*64 + (lm>>1)*8 + lr)*CSTR + (lm&1)*8);

    // two GEMMs: Y_c = P * M_c ; epilogue q_c = <Y_c[r], P[r]>
    #pragma unroll
    for (int cc = 0; cc < 2; cc++) {
        unsigned mbase = smem_u32(Mt + cc*128*CSTR) + 2u*mrow;
        float c[8][4];
        #pragma unroll
        for (int nn = 0; nn < 8; nn++)
            #pragma unroll
            for (int q = 0; q < 4; q++) c[nn][q] = 0.f;
        #pragma unroll
        for (int kk = 0; kk < 8; kk++) {
            #pragma unroll
            for (int q = 0; q < 4; q++) {
                unsigned x0, x1, x2, x3;
                ldsm4(x0, x1, x2, x3, mbase + 2u*(unsigned)(q*16*CSTR + kk*16));
                mma16816(c[2*q],     af[kk], x0, x1);
                mma16816(c[2*q + 1], af[kk], x2, x3);
            }
        }
        float qA = 0.f, qB = 0.f;
        #pragma unroll
        for (int nn = 0; nn < 8; nn++) {
            int col = warp_n*64 + nn*8 + 2*tt;
            float2 pa = __bfloat1622float2(*(__nv_bfloat162*)&Pt[ ar    *CSTR + col]);
            float2 pb = __bfloat1622float2(*(__nv_bfloat162*)&Pt[(ar+8)*CSTR + col]);
            qA += c[nn][0]*pa.x + c[nn][1]*pa.y;
            qB += c[nn][2]*pb.x + c[nn][3]*pb.y;
        }
        #pragma unroll
        for (int m = 1; m <= 2; m <<= 1) {
            qA += __shfl_xor_sync(0xffffffffu, qA, m);
            qB += __shfl_xor_sync(0xffffffffu, qB, m);
        }
        if (tt == 0) {
            esm[cc*128 + warp_n*64 + ar]     = qA;
            esm[cc*128 + warp_n*64 + ar + 8] = qB;
        }
    }

    // s-dots: sdot_c = <s_c, P[r]> (no GEMM needed)
    {
        float sA0 = 0.f, sB0 = 0.f, sA1 = 0.f, sB1 = 0.f;
        #pragma unroll
        for (int nn = 0; nn < 8; nn++) {
            int col = warp_n*64 + nn*8 + 2*tt;
            float2 pa = __bfloat1622float2(*(__nv_bfloat162*)&Pt[ ar    *CSTR + col]);
            float2 pb = __bfloat1622float2(*(__nv_bfloat162*)&Pt[(ar+8)*CSTR + col]);
            float2 s0 = *(const float2*)&Ssm[col];
            float2 s1 = *(const float2*)&Ssm[NF + col];
            sA0 += s0.x*pa.x + s0.y*pa.y;  sB0 += s0.x*pb.x + s0.y*pb.y;
            sA1 += s1.x*pa.x + s1.y*pa.y;  sB1 += s1.x*pb.x + s1.y*pb.y;
        }
        #pragma unroll
        for (int m = 1; m <= 2; m <<= 1) {
            sA0 += __shfl_xor_sync(0xffffffffu, sA0, m);
            sB0 += __shfl_xor_sync(0xffffffffu, sB0, m);
            sA1 += __shfl_xor_sync(0xffffffffu, sA1, m);
            sB1 += __shfl_xor_sync(0xffffffffu, sB1, m);
        }
        if (tt == 0) {
            esm[2*128 + warp_n*64 + ar]     = sA0;
            esm[2*128 + warp_n*64 + ar + 8] = sB0;
            esm[3*128 + warp_n*64 + ar]     = sA1;
            esm[3*128 + warp_n*64 + ar + 8] = sB1;
        }
    }
    __syncthreads();

    // per-row combine (t<64), then block reduce
    if (t < 64) {
        float qp = esm[t]         + esm[64 + t];
        float qn = esm[128 + t]   + esm[128 + 64 + t];
        float s0 = esm[256 + t]   + esm[256 + 64 + t];
        float s1 = esm[384 + t]   + esm[384 + 64 + t];
        bool valid = (r0 + t) < rlim;
        float qf = qp + qn;
        float rinv = rsqrtf(qf);
        rinv = rinv * (1.5f - 0.5f * qf * rinv * rinv);
        float q_opp = (cls == 0) ? qn : qp;
        float s_opp = (cls == 0) ? s1 : s0;
        float s_same = (cls == 0) ? s0 : s1;
        float denom = 4000.f + rinv*s_opp + 0.5f*rinv*rinv*q_opp;
        float lg = valid ? logf(denom) : 0.f;
        float cv = valid ? (s_same - 1.0f) * rinv : 0.f;
        #pragma unroll
        for (int m = 16; m; m >>= 1) {
            lg += __shfl_xor_sync(0xffffffffu, lg, m);
            cv += __shfl_xor_sync(0xffffffffu, cv, m);
        }
        if (lane == 0) { wred[wid*2] = lg; wred[wid*2+1] = cv; }
    }
    __syncthreads();
    if (t == 0) {
        g_logP[b]   = wred[0] + wred[2];
        g_smaskP[b] = wred[1] + wred[3];
    }
}

// ---------------- K4: final combine ----------------
__global__ void k_final(float* out) {
    int t = threadIdx.x;
    float s = 0.f, sk = 0.f;
    if (t < 126) { s = g_logP[t]; sk = g_smaskP[t]; }
    float sm_ = 0.f;
    for (int i = t; i < 512; i += 256) sm_ += g_mseP[i];
    #pragma unroll
    for (int m = 16; m; m >>= 1) {
        s   += __shfl_xor_sync(0xffffffffu, s, m);
        sm_ += __shfl_xor_sync(0xffffffffu, sm_, m);
        sk  += __shfl_xor_sync(0xffffffffu, sk, m);
    }
    __shared__ float ws[8][3];
    if ((t & 31) == 0) { ws[t>>5][0] = s; ws[t>>5][1] = sm_; ws[t>>5][2] = sk; }
    __syncthreads();
    if (t == 0) {
        float lsum = 0.f, msum = 0.f, ksum = 0.f;
        #pragma unroll
        for (int w = 0; w < 8; w++) { lsum += ws[w][0]; msum += ws[w][1]; ksum += ws[w][2]; }
        float supcon = -ksum * (1.0f / NR) + lsum;
        float mse = msum * (1.0f / NMSE);
        out[0] = supcon + 0.5f * mse;
    }
}

extern "C" void kernel_launch(void* const* d_in, const int* in_sizes, int n_in,
                              void* d_out, int out_size) {
    const float* Zs  = (const float*)d_in[0];
    const int*   pos = (const int*)d_in[1];
    const int*   neg = (const int*)d_in[2];
    const float* fd  = (const float*)d_in[3];
    const float* id  = (const float*)d_in[4];
    float* out = (float*)d_out;

    static int smem_set = 0;
    int qform_smem = (64*CSTR + 256*CSTR) * (int)sizeof(__nv_bfloat16) + 772*4;
    if (!smem_set) {
        cudaFuncSetAttribute(k_qform, cudaFuncAttributeMaxDynamicSharedMemorySize, qform_smem);
        smem_set = 1;
    }

    k_front <<<1513, 256>>>(Zs, pos, neg, fd, id);
    k_MA    <<<NMP, 256>>>();
    k_Mred  <<<148, 256>>>();
    k_qform <<<126, 256, qform_smem>>>();
    k_final <<<1, 256>>>(out);
}

// round 17
// speedup vs baseline: 10.3087x; 1.0598x over previous
#include <cuda_runtime.h>
#include <cuda_bf16.h>
#include <math.h>
#include <stdint.h>

#define NR    8000
#define NPOS  4000
#define NF    128
#define NVOX  32768
#define NMSE  (128*32*32*32)
#define NMP   126          // per-class split-K moment partials (63 pos + 63 neg)

// ---- scratch (static device globals; no allocations) ----
__device__ __nv_bfloat16  g_Pb[NR*NF];       // normalized pixels bf16
__device__ __nv_bfloat16  g_Mp[NMP*NF*NF];   // per-class moment partials (bf16, 4 MB)
__device__ __nv_bfloat16  g_Mb[2*NF*NF];     // [0]=M_pos, [1]=M_neg (bf16)
__device__ float          g_S[2*NF];         // class col sums (atomic, zeroed in k_front)
__device__ float          g_Sp[1000*NF];     // per-gather-block column-sum partials
__device__ float          g_mseP[512];       // per-block mse partials
__device__ float          g_smaskP[128];     // per-tile S_mask partials (126 used)
__device__ float          g_logP[128];       // per-tile log(denom) partials (126 used)

__device__ __forceinline__ unsigned smem_u32(const void* p) {
    return (unsigned)__cvta_generic_to_shared(p);
}

__device__ __forceinline__ void mma16816(float c[4], const unsigned a[4],
                                         unsigned b0, unsigned b1) {
    asm volatile(
        "mma.sync.aligned.m16n8k16.row.col.f32.bf16.bf16.f32 "
        "{%0,%1,%2,%3}, {%4,%5,%6,%7}, {%8,%9}, {%0,%1,%2,%3};"
        : "+f"(c[0]), "+f"(c[1]), "+f"(c[2]), "+f"(c[3])
        : "r"(a[0]), "r"(a[1]), "r"(a[2]), "r"(a[3]), "r"(b0), "r"(b1));
}
__device__ __forceinline__ void ldsm4(unsigned& x0, unsigned& x1,
                                      unsigned& x2, unsigned& x3, unsigned addr) {
    asm volatile("ldmatrix.sync.aligned.m8n8.x4.shared.b16 {%0,%1,%2,%3}, [%4];"
                 : "=r"(x0), "=r"(x1), "=r"(x2), "=r"(x3) : "r"(addr));
}

// ---------------- K1: fused front kernel ----------------
// [0,1000): gather + normalize + col-sum partial; [1000,1512): MSE; 1512: zero g_S
__global__ void k_front(const float* __restrict__ Zs,
                        const int* __restrict__ pos,
                        const int* __restrict__ neg,
                        const float* __restrict__ fd,
                        const float* __restrict__ id) {
    __shared__ float smP[8][NF];
    int b = blockIdx.x, t = threadIdx.x;
    if (b < 1000) {
        int wid = t >> 5, lane = t & 31;
        int r = b * 8 + wid;
        int v = (r < NPOS) ? pos[r] : neg[r - NPOS];
        float x[4];
        #pragma unroll
        for (int k = 0; k < 4; k++) x[k] = Zs[(size_t)(lane + 32*k)*NVOX + v];
        float s = x[0]*x[0] + x[1]*x[1] + x[2]*x[2] + x[3]*x[3];
        #pragma unroll
        for (int m = 16; m; m >>= 1) s += __shfl_xor_sync(0xffffffffu, s, m);
        float inv = 1.0f / fmaxf(sqrtf(s), 1e-12f);
        #pragma unroll
        for (int k = 0; k < 4; k++) {
            float p = x[k] * inv;
            g_Pb[r*NF + lane + 32*k] = __float2bfloat16(p);
            smP[wid][lane + 32*k] = p;
        }
        __syncthreads();
        if (t < NF) {
            float cs = 0.f;
            #pragma unroll
            for (int w = 0; w < 8; w++) cs += smP[w][t];
            g_Sp[b*NF + t] = cs;
        }
    } else if (b < 1512) {
        int mb = b - 1000;
        int n4 = NMSE / 4;
        float s = 0.f;
        for (int i = mb*256 + t; i < n4; i += 512*256) {
            float4 a = ((const float4*)fd)[i];
            float4 c = ((const float4*)id)[i];
            float d0 = a.x-c.x, d1 = a.y-c.y, d2 = a.z-c.z, d3 = a.w-c.w;
            s += d0*d0 + d1*d1 + d2*d2 + d3*d3;
        }
        #pragma unroll
        for (int m = 16; m; m >>= 1) s += __shfl_xor_sync(0xffffffffu, s, m);
        __shared__ float ws[8];
        if ((t & 31) == 0) ws[t >> 5] = s;
        __syncthreads();
        if (t == 0) {
            float tot = 0.f;
            #pragma unroll
            for (int w = 0; w < 8; w++) tot += ws[w];
            g_mseP[mb] = tot;
        }
    } else {
        if (t < 2*NF) g_S[t] = 0.f;
    }
}

// ---------------- K2a: per-class moment partials via bf16 HMMA ----------------
// grid 126: b<63 -> pos tile (rows b*64, valid<4000), b>=63 -> neg tile
__global__ void __launch_bounds__(256) k_MA() {
    __shared__ unsigned short spT[128][72];  // transposed tile: [feat][sample]
    int t = threadIdx.x, wid = t >> 5, lane = t & 31;
    int b = blockIdx.x;
    int r0   = (b < 63) ? b*64 : NPOS + (b - 63)*64;
    int rlim = (b < 63) ? NPOS : NR;

    for (int i = t; i < 1024; i += 256) {
        int r = i >> 4, seg = i & 15;
        int jj = r0 + r;
        uint4 v = make_uint4(0u,0u,0u,0u);
        if (jj < rlim) v = ((const uint4*)&g_Pb[(size_t)jj*NF])[seg];
        unsigned w0 = v.x, w1 = v.y, w2 = v.z, w3 = v.w;
        int f = seg * 8;
        spT[f+0][r] = (unsigned short)(w0 & 0xffffu);
        spT[f+1][r] = (unsigned short)(w0 >> 16);
        spT[f+2][r] = (unsigned short)(w1 & 0xffffu);
        spT[f+3][r] = (unsigned short)(w1 >> 16);
        spT[f+4][r] = (unsigned short)(w2 & 0xffffu);
        spT[f+5][r] = (unsigned short)(w2 >> 16);
        spT[f+6][r] = (unsigned short)(w3 & 0xffffu);
        spT[f+7][r] = (unsigned short)(w3 >> 16);
    }
    __syncthreads();

    int i0 = wid * 16;
    int lm = lane >> 3, lr = lane & 7;
    unsigned base = smem_u32(&spT[0][0]);
    unsigned aAddr0 = base + (unsigned)(((i0 + (lm & 1)*8 + lr) * 72 + (lm >> 1)*8) << 1);
    unsigned bRowOff = (unsigned)((((lm >> 1)*8 + lr) * 72 + (lm & 1)*8) << 1);

    float c[16][4];
    #pragma unroll
    for (int nn = 0; nn < 16; nn++)
        #pragma unroll
        for (int q = 0; q < 4; q++) c[nn][q] = 0.f;

    #pragma unroll
    for (int kk = 0; kk < 4; kk++) {
        unsigned af[4];
        ldsm4(af[0], af[1], af[2], af[3], aAddr0 + kk*32);
        #pragma unroll
        for (int q = 0; q < 8; q++) {
            unsigned x0, x1, x2, x3;
            unsigned addr = base + (unsigned)((q*16*72) << 1) + bRowOff + kk*32;
            ldsm4(x0, x1, x2, x3, addr);
            mma16816(c[2*q],     af, x0, x1);
            mma16816(c[2*q + 1], af, x2, x3);
        }
    }

    __nv_bfloat16* dst = &g_Mp[(size_t)b * NF * NF];
    int g = lane >> 2, tt = lane & 3;
    #pragma unroll
    for (int nn = 0; nn < 16; nn++) {
        int col = nn*8 + 2*tt;
        __nv_bfloat162 v0 = __floats2bfloat162_rn(c[nn][0], c[nn][1]);
        __nv_bfloat162 v1 = __floats2bfloat162_rn(c[nn][2], c[nn][3]);
        *(unsigned*)&dst[(i0+g  )*NF + col] = *(unsigned*)&v0;
        *(unsigned*)&dst[(i0+g+8)*NF + col] = *(unsigned*)&v1;
    }
}

// ---------------- K2b: reduce moment partials + S partials ----------------
// grid 148: [0,128) -> M chunks (b&1 = class, 256-elem chunk); [128,148) -> g_S
__global__ void k_Mred() {
    int b = blockIdx.x, t = threadIdx.x;
    if (b < 128) {
        int cls = b & 1, chunk = b >> 1;
        int e = chunk * 256 + t;
        int p0 = cls * 63;
        float s = 0.f;
        #pragma unroll 9
        for (int p = p0; p < p0 + 63; p++)
            s += __bfloat162float(g_Mp[(size_t)p*NF*NF + e]);
        g_Mb[cls*NF*NF + e] = __float2bfloat16(s);
    } else if (t < NF) {
        int idx = b - 128;
        int cls = idx & 1, chunk = idx >> 1;
        int b0 = cls * 500 + chunk * 50;
        float s = 0.f;
        #pragma unroll 10
        for (int k = 0; k < 50; k++) s += g_Sp[(b0 + k)*NF + t];
        atomicAdd(&g_S[cls*NF + t], s);
    }
}

// ---------------- K3: quadratic-form kernel ----------------
// denom_i = 4000 + rinv*(p_i . s_opp) + 0.5*rinv^2*(p_i^T M_opp p_i)
// grid 126 class-pure 64-row tiles, 512 thr = 16 warps:
//   warp_m = wid&3 (16 rows), cc = (wid>>2)&1 (class GEMM), warp_n = wid>>3 (64 cols)
#define CSTR 136
__global__ void __launch_bounds__(512) k_qform() {
    extern __shared__ __nv_bfloat16 sm[];
    __nv_bfloat16* Pt = sm;                   // 64 x CSTR
    __nv_bfloat16* Mt = sm + 64*CSTR;         // 2 x 128 x CSTR (Mpos, Mneg)
    float* fb  = (float*)(sm + 64*CSTR + 256*CSTR);
    float* Ssm = fb;            // [2][128]
    float* esm = fb + 256;      // [4][128]: 0 qpos, 1 qneg, 2 sdot_pos, 3 sdot_neg
    float* wred = fb + 768;     // [4]

    int t = threadIdx.x, wid = t >> 5, lane = t & 31;
    int g = lane >> 2, tt = lane & 3;
    int warp_m = wid & 3, cc = (wid >> 2) & 1, warp_n = wid >> 3;
    int b = blockIdx.x;
    int cls  = (b < 63) ? 0 : 1;
    int r0   = (cls == 0) ? b*64 : NPOS + (b - 63)*64;
    int rlim = (cls == 0) ? NPOS : NR;

    // loads
    for (int i = t; i < 1024; i += 512) {
        int row = i >> 4, seg = i & 15;
        int jj = r0 + row;
        uint4 v = make_uint4(0u,0u,0u,0u);
        if (jj < rlim) v = ((const uint4*)&g_Pb[(size_t)jj*NF])[seg];
        *(uint4*)&Pt[row*CSTR + seg*8] = v;
    }
    {
        const uint4* srcM = (const uint4*)g_Mb;
        for (int i = t; i < 4096; i += 512) {
            int row = i >> 4, seg = i & 15;
            *(uint4*)&Mt[row*CSTR + seg*8] = srcM[i];
        }
    }
    if (t < 2*NF) Ssm[t] = g_S[t];
    __syncthreads();

    int lm = lane >> 3, lr = lane & 7;
    int i0 = warp_m * 16;
    int ar = i0 + g;

    // A fragments via ldmatrix (same mapping as k_MA, stride CSTR)
    unsigned aAddr = smem_u32(Pt)
                   + (unsigned)(((i0 + (lm & 1)*8 + lr)*CSTR + (lm >> 1)*8) << 1);
    unsigned af[8][4];
    #pragma unroll
    for (int kk = 0; kk < 8; kk++)
        ldsm4(af[kk][0], af[kk][1], af[kk][2], af[kk][3], aAddr + kk*32);

    // one class-GEMM per warp: Y_cc = P * M_cc (16 rows x 64 cols)
    unsigned mbase = smem_u32(Mt) + (unsigned)((cc*128*CSTR) << 1)
                   + (unsigned)(((warp_n*64 + (lm>>1)*8 + lr)*CSTR + (lm&1)*8) << 1);
    float c[8][4];
    #pragma unroll
    for (int nn = 0; nn < 8; nn++)
        #pragma unroll
        for (int q = 0; q < 4; q++) c[nn][q] = 0.f;
    #pragma unroll
    for (int kk = 0; kk < 8; kk++) {
        #pragma unroll
        for (int q = 0; q < 4; q++) {
            unsigned x0, x1, x2, x3;
            ldsm4(x0, x1, x2, x3, mbase + 2u*(unsigned)(q*16*CSTR + kk*16));
            mma16816(c[2*q],     af[kk], x0, x1);
            mma16816(c[2*q + 1], af[kk], x2, x3);
        }
    }

    // fused epilogue: q_cc = <Y_cc[r], P[r]>, sdot_cc = <s_cc, P[r]>
    {
        const float* Sv = Ssm + cc*NF;
        float qA = 0.f, qB = 0.f, sA = 0.f, sB = 0.f;
        #pragma unroll
        for (int nn = 0; nn < 8; nn++) {
            int col = warp_n*64 + nn*8 + 2*tt;
            float2 pa = __bfloat1622float2(*(__nv_bfloat162*)&Pt[ ar    *CSTR + col]);
            float2 pb = __bfloat1622float2(*(__nv_bfloat162*)&Pt[(ar+8)*CSTR + col]);
            qA += c[nn][0]*pa.x + c[nn][1]*pa.y;
            qB += c[nn][2]*pb.x + c[nn][3]*pb.y;
            float2 sv = *(const float2*)&Sv[col];
            sA += sv.x*pa.x + sv.y*pa.y;
            sB += sv.x*pb.x + sv.y*pb.y;
        }
        #pragma unroll
        for (int m = 1; m <= 2; m <<= 1) {
            qA += __shfl_xor_sync(0xffffffffu, qA, m);
            qB += __shfl_xor_sync(0xffffffffu, qB, m);
            sA += __shfl_xor_sync(0xffffffffu, sA, m);
            sB += __shfl_xor_sync(0xffffffffu, sB, m);
        }
        if (tt == 0) {
            esm[cc*128 + warp_n*64 + ar]         = qA;
            esm[cc*128 + warp_n*64 + ar + 8]     = qB;
            esm[(2+cc)*128 + warp_n*64 + ar]     = sA;
            esm[(2+cc)*128 + warp_n*64 + ar + 8] = sB;
        }
    }
    __syncthreads();

    // per-row combine (t<64), then block reduce
    if (t < 64) {
        float qp = esm[t]         + esm[64 + t];
        float qn = esm[128 + t]   + esm[128 + 64 + t];
        float s0 = esm[256 + t]   + esm[256 + 64 + t];
        float s1 = esm[384 + t]   + esm[384 + 64 + t];
        bool valid = (r0 + t) < rlim;
        float qf = qp + qn;
        float rinv = rsqrtf(qf);
        rinv = rinv * (1.5f - 0.5f * qf * rinv * rinv);
        float q_opp  = (cls == 0) ? qn : qp;
        float s_opp  = (cls == 0) ? s1 : s0;
        float s_same = (cls == 0) ? s0 : s1;
        float denom = 4000.f + rinv*s_opp + 0.5f*rinv*rinv*q_opp;
        float lg = valid ? logf(denom) : 0.f;
        float cv = valid ? (s_same - 1.0f) * rinv : 0.f;
        #pragma unroll
        for (int m = 16; m; m >>= 1) {
            lg += __shfl_xor_sync(0xffffffffu, lg, m);
            cv += __shfl_xor_sync(0xffffffffu, cv, m);
        }
        if (lane == 0) { wred[wid*2] = lg; wred[wid*2+1] = cv; }
    }
    __syncthreads();
    if (t == 0) {
        g_logP[b]   = wred[0] + wred[2];
        g_smaskP[b] = wred[1] + wred[3];
    }
}

// ---------------- K4: final combine ----------------
__global__ void k_final(float* out) {
    int t = threadIdx.x;
    float s = 0.f, sk = 0.f;
    if (t < 126) { s = g_logP[t]; sk = g_smaskP[t]; }
    float sm_ = 0.f;
    for (int i = t; i < 512; i += 256) sm_ += g_mseP[i];
    #pragma unroll
    for (int m = 16; m; m >>= 1) {
        s   += __shfl_xor_sync(0xffffffffu, s, m);
        sm_ += __shfl_xor_sync(0xffffffffu, sm_, m);
        sk  += __shfl_xor_sync(0xffffffffu, sk, m);
    }
    __shared__ float ws[8][3];
    if ((t & 31) == 0) { ws[t>>5][0] = s; ws[t>>5][1] = sm_; ws[t>>5][2] = sk; }
    __syncthreads();
    if (t == 0) {
        float lsum = 0.f, msum = 0.f, ksum = 0.f;
        #pragma unroll
        for (int w = 0; w < 8; w++) { lsum += ws[w][0]; msum += ws[w][1]; ksum += ws[w][2]; }
        float supcon = -ksum * (1.0f / NR) + lsum;
        float mse = msum * (1.0f / NMSE);
        out[0] = supcon + 0.5f * mse;
    }
}

extern "C" void kernel_launch(void* const* d_in, const int* in_sizes, int n_in,
                              void* d_out, int out_size) {
    const float* Zs  = (const float*)d_in[0];
    const int*   pos = (const int*)d_in[1];
    const int*   neg = (const int*)d_in[2];
    const float* fd  = (const float*)d_in[3];
    const float* id  = (const float*)d_in[4];
    float* out = (float*)d_out;

    static int smem_set = 0;
    int qform_smem = (64*CSTR + 256*CSTR) * (int)sizeof(__nv_bfloat16) + 772*4;
    if (!smem_set) {
        cudaFuncSetAttribute(k_qform, cudaFuncAttributeMaxDynamicSharedMemorySize, qform_smem);
        smem_set = 1;
    }

    k_front <<<1513, 256>>>(Zs, pos, neg, fd, id);
    k_MA    <<<NMP, 256>>>();
    k_Mred  <<<148, 256>>>();
    k_qform <<<126, 512, qform_smem>>>();
    k_final <<<1, 256>>>(out);
}